// round 3
// baseline (speedup 1.0000x reference)
#include <cuda_runtime.h>
#include <cstdint>
#include <cstddef>

// ---------------- problem constants ----------------
#define NTOK     32768        // 8 * 4096 tokens
#define DD       256          // model dim
#define QKVC     2560         // 8 heads * 256 (Q) + 256 (K) + 256 (V)
#define OC       2048         // 8 heads * 256 attention output

// ---------------- static scratch (allocation-free rule) ----------------
__device__ float g_a    [(size_t)NTOK * DD];     // LN1 output, blocked layout
__device__ float g_wqkv [(size_t)DD * QKVC];     // concat weights [256][2560]
__device__ float g_qkv  [(size_t)NTOK * QKVC];   // Q0..Q7 | K | V   per token
__device__ float g_attno[(size_t)NTOK * OC];     // attention outputs, col = h*256+d
__device__ float g_so   [OC];                    // so[h*256+d] = sum_v o[h,d,v]
__device__ float g_x2   [(size_t)NTOK * DD];     // x + attn residual (orig layout)
__device__ float g_ln2  [(size_t)NTOK * DD];     // LN2 output
__device__ float g_mlp1 [(size_t)NTOK * DD];     // MLP hidden

// ---------------- weight concat: W[d][j] ----------------
__global__ void prep_w_kernel(const float* __restrict__ q,
                              const float* __restrict__ k,
                              const float* __restrict__ v) {
    int idx = blockIdx.x * 256 + threadIdx.x;      // 256*2560 total
    int d = idx / QKVC, j = idx % QKVC;
    float val;
    if (j < 2048) { int h = j >> 8, kk = j & 255; val = q[((size_t)(h * 256 + d)) * 256 + kk]; }
    else if (j < 2304) val = k[(size_t)d * 256 + (j - 2048)];
    else               val = v[(size_t)d * 256 + (j - 2304)];
    g_wqkv[(size_t)d * QKVC + j] = val;
}

// ---------------- so[h,d] = sum_v o[h,d,v]  (einsum keeps d, sums h & v) ----------------
__global__ void prep_so_kernel(const float* __restrict__ o) {
    int row  = (blockIdx.x * blockDim.x + threadIdx.x) >> 5;   // 0..2047 = h*256+d
    int lane = threadIdx.x & 31;
    const float* rp = o + (size_t)row * 256;
    float4 a = ((const float4*)rp)[lane];
    float4 b = ((const float4*)rp)[lane + 32];
    float s = a.x + a.y + a.z + a.w + b.x + b.y + b.z + b.w;
#pragma unroll
    for (int off = 16; off > 0; off >>= 1) s += __shfl_xor_sync(0xffffffffu, s, off);
    if (lane == 0) g_so[row] = s;
}

// ---------------- LayerNorm (one warp per row), block-permute on write ----------------
__global__ void ln1_kernel(const float* __restrict__ in,
                           const float* __restrict__ gamma,
                           const float* __restrict__ beta,
                           float* __restrict__ out) {
    int gwarp = (blockIdx.x * blockDim.x + threadIdx.x) >> 5;  // row 0..32767
    int lane  = threadIdx.x & 31;
    const float* row = in + (size_t)gwarp * DD;
    float4 v0 = ((const float4*)row)[lane];
    float4 v1 = ((const float4*)row)[lane + 32];
    float s  = v0.x + v0.y + v0.z + v0.w + v1.x + v1.y + v1.z + v1.w;
    float sq = v0.x*v0.x + v0.y*v0.y + v0.z*v0.z + v0.w*v0.w
             + v1.x*v1.x + v1.y*v1.y + v1.z*v1.z + v1.w*v1.w;
#pragma unroll
    for (int o = 16; o > 0; o >>= 1) {
        s  += __shfl_xor_sync(0xffffffffu, s,  o);
        sq += __shfl_xor_sync(0xffffffffu, sq, o);
    }
    float mean = s * (1.0f / 256.0f);
    float var  = sq * (1.0f / 256.0f) - mean * mean;
    float rstd = rsqrtf(var + 1e-5f);

    // input row = (b, pos=h*64+w) -> blocked token (b, m, n)
    int b   = gwarp >> 12;
    int pos = gwarp & 4095;
    int h = pos >> 6, w = pos & 63;
    int m = ((h & 7) << 3) | (w & 7);
    int n = ((h >> 3) << 3) | (w >> 3);
    size_t orow = ((size_t)b << 12) | (unsigned)((m << 6) | n);

    float* op = out + orow * DD;
    float4 g0 = ((const float4*)gamma)[lane];
    float4 g1 = ((const float4*)gamma)[lane + 32];
    float4 b0 = ((const float4*)beta)[lane];
    float4 b1 = ((const float4*)beta)[lane + 32];
    float4 o0, o1;
    o0.x = (v0.x - mean) * rstd * g0.x + b0.x;
    o0.y = (v0.y - mean) * rstd * g0.y + b0.y;
    o0.z = (v0.z - mean) * rstd * g0.z + b0.z;
    o0.w = (v0.w - mean) * rstd * g0.w + b0.w;
    o1.x = (v1.x - mean) * rstd * g1.x + b1.x;
    o1.y = (v1.y - mean) * rstd * g1.y + b1.y;
    o1.z = (v1.z - mean) * rstd * g1.z + b1.z;
    o1.w = (v1.w - mean) * rstd * g1.w + b1.w;
    ((float4*)op)[lane]      = o0;
    ((float4*)op)[lane + 32] = o1;
}

// ---------------- generic SGEMM 128x64x16, 256 threads, 8x4 per-thread ----------------
// MODE 0: plain store
// MODE 2: + bias, ReLU
// MODE 3: + bias, + residual (same layout)
template <int MODE>
__global__ void sgemm_kernel(const float* __restrict__ A,
                             const float* __restrict__ Bm,
                             float* __restrict__ C,
                             const float* __restrict__ bias,
                             const float* __restrict__ res,
                             int M, int N, int K) {
    __shared__ __align__(16) float As[16][128];
    __shared__ __align__(16) float Bs[16][64];
    int tid = threadIdx.x;
    int tx = tid & 15, ty = tid >> 4;
    int rowBase = blockIdx.y * 128;
    int colBase = blockIdx.x * 64;

    float acc[8][4] = {};

    for (int k0 = 0; k0 < K; k0 += 16) {
#pragma unroll
        for (int it = 0; it < 2; it++) {
            int g = it * 256 + tid;
            int r = g >> 2, kc = (g & 3) << 2;
            float4 av = *(const float4*)(A + (size_t)(rowBase + r) * K + k0 + kc);
            As[kc + 0][r] = av.x; As[kc + 1][r] = av.y;
            As[kc + 2][r] = av.z; As[kc + 3][r] = av.w;
        }
        {
            int r = tid >> 4, c = (tid & 15) << 2;
            *(float4*)&Bs[r][c] = *(const float4*)(Bm + (size_t)(k0 + r) * N + colBase + c);
        }
        __syncthreads();
#pragma unroll
        for (int kk = 0; kk < 16; kk++) {
            float4 a0 = *(const float4*)&As[kk][ty * 8];
            float4 a1 = *(const float4*)&As[kk][ty * 8 + 4];
            float4 b4 = *(const float4*)&Bs[kk][tx * 4];
            float ra[8] = {a0.x, a0.y, a0.z, a0.w, a1.x, a1.y, a1.z, a1.w};
            float rb[4] = {b4.x, b4.y, b4.z, b4.w};
#pragma unroll
            for (int i = 0; i < 8; i++)
#pragma unroll
                for (int j = 0; j < 4; j++)
                    acc[i][j] += ra[i] * rb[j];
        }
        __syncthreads();
    }

#pragma unroll
    for (int i = 0; i < 8; i++) {
        int row = rowBase + ty * 8 + i;
        int col = colBase + tx * 4;
        float4 r4 = make_float4(acc[i][0], acc[i][1], acc[i][2], acc[i][3]);
        if (MODE == 2 || MODE == 3) {
            float4 bv = *(const float4*)(bias + col);
            r4.x += bv.x; r4.y += bv.y; r4.z += bv.z; r4.w += bv.w;
        }
        if (MODE == 2) {
            r4.x = fmaxf(r4.x, 0.f); r4.y = fmaxf(r4.y, 0.f);
            r4.z = fmaxf(r4.z, 0.f); r4.w = fmaxf(r4.w, 0.f);
        }
        if (MODE == 3) {
            float4 rv = *(const float4*)(res + (size_t)row * N + col);
            r4.x += rv.x; r4.y += rv.y; r4.z += rv.z; r4.w += rv.w;
        }
        *(float4*)(C + (size_t)row * N + col) = r4;
    }
}

// ---------------- fused attention ----------------
// One CTA per (b, head, fixed-index) unit: S = Q(64x256) K^T, softmax, O = P V.
// units 0..2047:   grid attention (heads 0-3), fixed = n, token stride 64
// units 2048..4095: block attention (heads 4-7), fixed = m, token stride 1
#define QPITCH 257
#define PPITCH 65
#define ATTN_SMEM_FLOATS (2 * 64 * QPITCH + 64 * PPITCH)

__device__ __forceinline__ void attn_load_tile(float* dst, size_t base, int stride,
                                               int colOff, int tid) {
#pragma unroll
    for (int i = 0; i < 16; i++) {
        int g = i * 256 + tid;
        int r = g >> 6;
        int c = (g & 63) << 2;
        float4 v = *(const float4*)(g_qkv + (base + (size_t)r * stride) * QKVC + colOff + c);
        float* d = dst + r * QPITCH + c;
        d[0] = v.x; d[1] = v.y; d[2] = v.z; d[3] = v.w;
    }
}

__global__ void attn_kernel() {
    extern __shared__ float sm[];
    float* Qs  = sm;
    float* KVs = sm + 64 * QPITCH;
    float* Ps  = sm + 2 * 64 * QPITCH;

    int tid = threadIdx.x;
    int warp = tid >> 5, lane = tid & 31;

    int u = blockIdx.x;
    bool gridmode = (u < 2048);
    int b, h, fix;
    if (gridmode) { b = u >> 8; h = (u >> 6) & 3; fix = u & 63; }
    else { int u2 = u - 2048; b = u2 >> 8; h = 4 + ((u2 >> 6) & 3); fix = u2 & 63; }
    size_t base; int stride;
    if (gridmode) { base = (size_t)b * 4096 + fix; stride = 64; }
    else          { base = ((size_t)b * 64 + fix) * 64; stride = 1; }

    attn_load_tile(Qs,  base, stride, h * 256, tid);
    attn_load_tile(KVs, base, stride, 2048,    tid);
    __syncthreads();

    // S: each warp owns 8 query rows; lane covers z = lane and z = lane+32
    float s0[8] = {}, s1[8] = {};
    const float* qb = Qs + (warp * 8) * QPITCH;
    const float* k0p = KVs + lane * QPITCH;
    const float* k1p = KVs + (lane + 32) * QPITCH;
#pragma unroll 4
    for (int k = 0; k < 256; k++) {
        float kv0 = k0p[k];
        float kv1 = k1p[k];
#pragma unroll
        for (int r = 0; r < 8; r++) {
            float qv = qb[r * QPITCH + k];
            s0[r] += qv * kv0;
            s1[r] += qv * kv1;
        }
    }

    // softmax over z (64) per query row
#pragma unroll
    for (int r = 0; r < 8; r++) {
        float mx = fmaxf(s0[r], s1[r]);
#pragma unroll
        for (int o = 16; o > 0; o >>= 1) mx = fmaxf(mx, __shfl_xor_sync(0xffffffffu, mx, o));
        float e0 = __expf(s0[r] - mx);
        float e1 = __expf(s1[r] - mx);
        float sum = e0 + e1;
#pragma unroll
        for (int o = 16; o > 0; o >>= 1) sum += __shfl_xor_sync(0xffffffffu, sum, o);
        float inv = 1.0f / sum;
        Ps[(warp * 8 + r) * PPITCH + lane]      = e0 * inv;
        Ps[(warp * 8 + r) * PPITCH + lane + 32] = e1 * inv;
    }
    __syncthreads();                    // all warps done with K
    attn_load_tile(KVs, base, stride, 2304, tid);   // V overwrites K
    __syncthreads();

    // O = P @ V : per thread 8 rows x 8 v-columns (v = lane + 32*i)
    float oa[8][8] = {};
    for (int z = 0; z < 64; z++) {
        float vv[8];
#pragma unroll
        for (int i = 0; i < 8; i++) vv[i] = KVs[z * QPITCH + lane + 32 * i];
#pragma unroll
        for (int r = 0; r < 8; r++) {
            float p = Ps[(warp * 8 + r) * PPITCH + z];
#pragma unroll
            for (int i = 0; i < 8; i++) oa[r][i] += p * vv[i];
        }
    }
#pragma unroll
    for (int r = 0; r < 8; r++) {
        size_t row = base + (size_t)(warp * 8 + r) * stride;
        float* op = g_attno + row * OC + h * 256 + lane;
#pragma unroll
        for (int i = 0; i < 8; i++) op[i * 32] = oa[r][i];
    }
}

// ---------- head-mix (Z[d] = sum_h O[h,d]*so[h,d]) + unpermute + residual + LN2 ----------
__global__ void zred_ln2_kernel(const float* __restrict__ x,
                                const float* __restrict__ gamma,
                                const float* __restrict__ beta,
                                float* __restrict__ x2,
                                float* __restrict__ ln2out) {
    int gw   = (blockIdx.x * blockDim.x + threadIdx.x) >> 5;   // blocked token 0..32767
    int lane = threadIdx.x & 31;

    // blocked (b,m,n) -> original row (b, h*64+w)
    int b = gw >> 12, m = (gw >> 6) & 63, n = gw & 63;
    int hh = ((n >> 3) << 3) | (m >> 3);
    int ww = ((n & 7) << 3) | (m & 7);
    size_t orow = ((size_t)b << 12) | (unsigned)((hh << 6) | ww);

    const float* arow = g_attno + (size_t)gw * OC;
    float4 acc0 = make_float4(0.f, 0.f, 0.f, 0.f);
    float4 acc1 = make_float4(0.f, 0.f, 0.f, 0.f);
#pragma unroll
    for (int h = 0; h < 8; h++) {
        float4 a0 = ((const float4*)(arow + h * 256))[lane];
        float4 a1 = ((const float4*)(arow + h * 256))[lane + 32];
        float4 s0 = ((const float4*)(g_so + h * 256))[lane];
        float4 s1 = ((const float4*)(g_so + h * 256))[lane + 32];
        acc0.x += a0.x * s0.x; acc0.y += a0.y * s0.y;
        acc0.z += a0.z * s0.z; acc0.w += a0.w * s0.w;
        acc1.x += a1.x * s1.x; acc1.y += a1.y * s1.y;
        acc1.z += a1.z * s1.z; acc1.w += a1.w * s1.w;
    }
    const float* xr = x + orow * DD;
    float4 x0 = ((const float4*)xr)[lane];
    float4 x1 = ((const float4*)xr)[lane + 32];
    float4 v0 = make_float4(x0.x + acc0.x, x0.y + acc0.y, x0.z + acc0.z, x0.w + acc0.w);
    float4 v1 = make_float4(x1.x + acc1.x, x1.y + acc1.y, x1.z + acc1.z, x1.w + acc1.w);

    ((float4*)(x2 + orow * DD))[lane]      = v0;
    ((float4*)(x2 + orow * DD))[lane + 32] = v1;

    // LN2 on the row we just built (all values live in this warp)
    float s  = v0.x + v0.y + v0.z + v0.w + v1.x + v1.y + v1.z + v1.w;
    float sq = v0.x*v0.x + v0.y*v0.y + v0.z*v0.z + v0.w*v0.w
             + v1.x*v1.x + v1.y*v1.y + v1.z*v1.z + v1.w*v1.w;
#pragma unroll
    for (int o = 16; o > 0; o >>= 1) {
        s  += __shfl_xor_sync(0xffffffffu, s,  o);
        sq += __shfl_xor_sync(0xffffffffu, sq, o);
    }
    float mean = s * (1.0f / 256.0f);
    float var  = sq * (1.0f / 256.0f) - mean * mean;
    float rstd = rsqrtf(var + 1e-5f);

    float4 g0 = ((const float4*)gamma)[lane];
    float4 g1 = ((const float4*)gamma)[lane + 32];
    float4 bb0 = ((const float4*)beta)[lane];
    float4 bb1 = ((const float4*)beta)[lane + 32];
    float4 o0, o1;
    o0.x = (v0.x - mean) * rstd * g0.x + bb0.x;
    o0.y = (v0.y - mean) * rstd * g0.y + bb0.y;
    o0.z = (v0.z - mean) * rstd * g0.z + bb0.z;
    o0.w = (v0.w - mean) * rstd * g0.w + bb0.w;
    o1.x = (v1.x - mean) * rstd * g1.x + bb1.x;
    o1.y = (v1.y - mean) * rstd * g1.y + bb1.y;
    o1.z = (v1.z - mean) * rstd * g1.z + bb1.z;
    o1.w = (v1.w - mean) * rstd * g1.w + bb1.w;
    ((float4*)(ln2out + orow * DD))[lane]      = o0;
    ((float4*)(ln2out + orow * DD))[lane + 32] = o1;
}

// ---------------- launch ----------------
extern "C" void kernel_launch(void* const* d_in, const int* in_sizes, int n_in,
                              void* d_out, int out_size) {
    const float* x    = (const float*)d_in[0];
    const float* ln1w = (const float*)d_in[1];
    const float* ln1b = (const float*)d_in[2];
    const float* qw   = (const float*)d_in[3];
    const float* kw   = (const float*)d_in[4];
    const float* vw   = (const float*)d_in[5];
    const float* ow   = (const float*)d_in[6];
    const float* ln2w = (const float*)d_in[7];
    const float* ln2b = (const float*)d_in[8];
    const float* w1   = (const float*)d_in[9];
    const float* b1   = (const float*)d_in[10];
    const float* w2   = (const float*)d_in[11];
    const float* b2   = (const float*)d_in[12];
    float* out = (float*)d_out;

    float *p_a, *p_wqkv, *p_qkv, *p_x2, *p_ln2, *p_mlp1;
    cudaGetSymbolAddress((void**)&p_a,     g_a);
    cudaGetSymbolAddress((void**)&p_wqkv,  g_wqkv);
    cudaGetSymbolAddress((void**)&p_qkv,   g_qkv);
    cudaGetSymbolAddress((void**)&p_x2,    g_x2);
    cudaGetSymbolAddress((void**)&p_ln2,   g_ln2);
    cudaGetSymbolAddress((void**)&p_mlp1,  g_mlp1);

    const int ATTN_SMEM_BYTES = ATTN_SMEM_FLOATS * 4;
    cudaFuncSetAttribute(attn_kernel, cudaFuncAttributeMaxDynamicSharedMemorySize,
                         ATTN_SMEM_BYTES);

    // 1. concat QKV weights + head-mix weights
    prep_w_kernel<<<QKVC, 256>>>(qw, kw, vw);
    prep_so_kernel<<<256, 256>>>(ow);
    // 2. LN1 + block permute
    ln1_kernel<<<NTOK / 8, 256>>>(x, ln1w, ln1b, p_a);
    // 3. QKV projection: [32768,256] @ [256,2560]
    sgemm_kernel<0><<<dim3(QKVC / 64, NTOK / 128), 256>>>(
        p_a, p_wqkv, p_qkv, nullptr, nullptr, NTOK, QKVC, DD);
    // 4. grid + block attention
    attn_kernel<<<4096, 256, ATTN_SMEM_BYTES>>>();
    // 5. head-mix + unpermute + residual + LN2 (fused)
    zred_ln2_kernel<<<NTOK / 8, 256>>>(x, ln2w, ln2b, p_x2, p_ln2);
    // 6. MLP fc1 + ReLU
    sgemm_kernel<2><<<dim3(DD / 64, NTOK / 128), 256>>>(
        p_ln2, w1, p_mlp1, b1, nullptr, NTOK, DD, DD);
    // 7. MLP fc2 + bias + residual -> output
    sgemm_kernel<3><<<dim3(DD / 64, NTOK / 128), 256>>>(
        p_mlp1, w2, out, b2, p_x2, NTOK, DD, DD);
}

// round 4
// speedup vs baseline: 1.1542x; 1.1542x over previous
#include <cuda_runtime.h>
#include <cstdint>
#include <cstddef>

// ---------------- problem constants ----------------
#define NTOK     32768        // 8 * 4096 tokens
#define DD       256          // model dim
#define QKVC     2560         // 8 heads * 256 (Q) + 256 (K) + 256 (V)
#define OC       2048         // 8 heads * 256 attention output

// ---------------- static scratch (allocation-free rule) ----------------
__device__ float g_a    [(size_t)NTOK * DD];
__device__ float g_wqkv [(size_t)DD * QKVC];
__device__ float g_qkv  [(size_t)NTOK * QKVC];
__device__ float g_attno[(size_t)NTOK * OC];
__device__ float g_so   [OC];
__device__ float g_x2   [(size_t)NTOK * DD];
__device__ float g_ln2  [(size_t)NTOK * DD];
__device__ float g_mlp1 [(size_t)NTOK * DD];

// ---------------- weight concat: W[d][j] ----------------
__global__ void prep_w_kernel(const float* __restrict__ q,
                              const float* __restrict__ k,
                              const float* __restrict__ v) {
    int idx = blockIdx.x * 256 + threadIdx.x;
    int d = idx / QKVC, j = idx % QKVC;
    float val;
    if (j < 2048) { int h = j >> 8, kk = j & 255; val = q[((size_t)(h * 256 + d)) * 256 + kk]; }
    else if (j < 2304) val = k[(size_t)d * 256 + (j - 2048)];
    else               val = v[(size_t)d * 256 + (j - 2304)];
    g_wqkv[(size_t)d * QKVC + j] = val;
}

// ---------------- so[h,d] = sum_v o[h,d,v] ----------------
__global__ void prep_so_kernel(const float* __restrict__ o) {
    int row  = (blockIdx.x * blockDim.x + threadIdx.x) >> 5;
    int lane = threadIdx.x & 31;
    const float* rp = o + (size_t)row * 256;
    float4 a = ((const float4*)rp)[lane];
    float4 b = ((const float4*)rp)[lane + 32];
    float s = a.x + a.y + a.z + a.w + b.x + b.y + b.z + b.w;
#pragma unroll
    for (int off = 16; off > 0; off >>= 1) s += __shfl_xor_sync(0xffffffffu, s, off);
    if (lane == 0) g_so[row] = s;
}

// ---------------- LN1 + block permute (one warp per row) ----------------
__global__ void ln1_kernel(const float* __restrict__ in,
                           const float* __restrict__ gamma,
                           const float* __restrict__ beta,
                           float* __restrict__ out) {
    int gwarp = (blockIdx.x * blockDim.x + threadIdx.x) >> 5;
    int lane  = threadIdx.x & 31;
    const float* row = in + (size_t)gwarp * DD;
    float4 v0 = ((const float4*)row)[lane];
    float4 v1 = ((const float4*)row)[lane + 32];
    float s  = v0.x + v0.y + v0.z + v0.w + v1.x + v1.y + v1.z + v1.w;
    float sq = v0.x*v0.x + v0.y*v0.y + v0.z*v0.z + v0.w*v0.w
             + v1.x*v1.x + v1.y*v1.y + v1.z*v1.z + v1.w*v1.w;
#pragma unroll
    for (int o = 16; o > 0; o >>= 1) {
        s  += __shfl_xor_sync(0xffffffffu, s,  o);
        sq += __shfl_xor_sync(0xffffffffu, sq, o);
    }
    float mean = s * (1.0f / 256.0f);
    float var  = sq * (1.0f / 256.0f) - mean * mean;
    float rstd = rsqrtf(var + 1e-5f);

    int b   = gwarp >> 12;
    int pos = gwarp & 4095;
    int h = pos >> 6, w = pos & 63;
    int m = ((h & 7) << 3) | (w & 7);
    int n = ((h >> 3) << 3) | (w >> 3);
    size_t orow = ((size_t)b << 12) | (unsigned)((m << 6) | n);

    float* op = out + orow * DD;
    float4 g0 = ((const float4*)gamma)[lane];
    float4 g1 = ((const float4*)gamma)[lane + 32];
    float4 b0 = ((const float4*)beta)[lane];
    float4 b1 = ((const float4*)beta)[lane + 32];
    float4 o0, o1;
    o0.x = (v0.x - mean) * rstd * g0.x + b0.x;
    o0.y = (v0.y - mean) * rstd * g0.y + b0.y;
    o0.z = (v0.z - mean) * rstd * g0.z + b0.z;
    o0.w = (v0.w - mean) * rstd * g0.w + b0.w;
    o1.x = (v1.x - mean) * rstd * g1.x + b1.x;
    o1.y = (v1.y - mean) * rstd * g1.y + b1.y;
    o1.z = (v1.z - mean) * rstd * g1.z + b1.z;
    o1.w = (v1.w - mean) * rstd * g1.w + b1.w;
    ((float4*)op)[lane]      = o0;
    ((float4*)op)[lane + 32] = o1;
}

// ================= tensor-core GEMM, 3xTF32 =================
// 128x128 CTA tile, 8 warps (2 x 4), each warp 64x32, mma m16n8k8,
// K-chunk 32, cp.async double buffer.
// MODE 0: plain store   MODE 2: +bias, ReLU   MODE 3: +bias, +residual

#define AP 36     // A smem pitch (floats): 36 mod 32 = 4 -> frag banks 4g+tig
#define BP 132    // B smem pitch (floats): 132 mod 32 = 4
#define ABUF (128 * AP)
#define BBUF (32 * BP)
#define GEMM_SMEM_BYTES ((2 * ABUF + 2 * BBUF) * 4)

__device__ __forceinline__ void cpasync16(uint32_t s, const void* g) {
    asm volatile("cp.async.cg.shared.global [%0], [%1], 16;\n" :: "r"(s), "l"(g));
}
__device__ __forceinline__ void split_tf32(float x, uint32_t& hi, uint32_t& lo) {
    uint32_t h;
    asm("cvt.rna.tf32.f32 %0, %1;\n" : "=r"(h) : "f"(x));
    float l = x - __uint_as_float(h);
    uint32_t lo_;
    asm("cvt.rna.tf32.f32 %0, %1;\n" : "=r"(lo_) : "f"(l));
    hi = h; lo = lo_;
}
__device__ __forceinline__ void mma8(float* c, const uint32_t* a, const uint32_t* b) {
    asm volatile(
        "mma.sync.aligned.m16n8k8.row.col.f32.tf32.tf32.f32 "
        "{%0,%1,%2,%3},{%4,%5,%6,%7},{%8,%9},{%0,%1,%2,%3};\n"
        : "+f"(c[0]), "+f"(c[1]), "+f"(c[2]), "+f"(c[3])
        : "r"(a[0]), "r"(a[1]), "r"(a[2]), "r"(a[3]), "r"(b[0]), "r"(b[1]));
}

template <int MODE>
__global__ __launch_bounds__(256, 2)
void mma_gemm_kernel(const float* __restrict__ A,
                     const float* __restrict__ Bm,
                     float* __restrict__ C,
                     const float* __restrict__ bias,
                     const float* __restrict__ res,
                     int M, int N, int K) {
    extern __shared__ float smem[];
    float* AsBase = smem;                 // 2 * ABUF
    float* BsBase = smem + 2 * ABUF;      // 2 * BBUF

    int tid = threadIdx.x;
    int lane = tid & 31, warp = tid >> 5;
    int wm = warp & 1, wn = warp >> 1;
    int g = lane >> 2, tig = lane & 3;
    int rowBase = blockIdx.y * 128;
    int colBase = blockIdx.x * 128;

    uint32_t aSm = (uint32_t)__cvta_generic_to_shared(AsBase);
    uint32_t bSm = (uint32_t)__cvta_generic_to_shared(BsBase);

    float acc[4][4][4] = {};

    int nch = K >> 5;

    // ---- async load of one K-chunk into buffer buf ----
    auto issue_loads = [&](int c, int buf) {
        uint32_t aB = aSm + (uint32_t)buf * (ABUF * 4);
        uint32_t bB = bSm + (uint32_t)buf * (BBUF * 4);
#pragma unroll
        for (int i = 0; i < 4; i++) {
            int f = tid + i * 256;          // 1024 float4 = 128 rows x 8
            int r = f >> 3, kq = f & 7;
            cpasync16(aB + (uint32_t)(r * AP + kq * 4) * 4,
                      A + (size_t)(rowBase + r) * K + c * 32 + kq * 4);
        }
#pragma unroll
        for (int i = 0; i < 4; i++) {
            int f = tid + i * 256;          // 1024 float4 = 32 k x 32
            int kr = f >> 5, nq = f & 31;
            cpasync16(bB + (uint32_t)(kr * BP + nq * 4) * 4,
                      Bm + (size_t)(c * 32 + kr) * N + colBase + nq * 4);
        }
        asm volatile("cp.async.commit_group;\n");
    };

    issue_loads(0, 0);

    for (int c = 0; c < nch; c++) {
        if (c + 1 < nch) {
            issue_loads(c + 1, (c + 1) & 1);
            asm volatile("cp.async.wait_group 1;\n");
        } else {
            asm volatile("cp.async.wait_group 0;\n");
        }
        __syncthreads();

        const float* Ab = AsBase + (c & 1) * ABUF;
        const float* Bb = BsBase + (c & 1) * BBUF;

#pragma unroll
        for (int ks = 0; ks < 4; ks++) {
            int kb = ks * 8;
            uint32_t ahi[4][4], alo[4][4];
#pragma unroll
            for (int mi = 0; mi < 4; mi++) {
                const float* ap = Ab + (wm * 64 + mi * 16 + g) * AP + kb + tig;
                float a0 = ap[0];
                float a1 = ap[8 * AP];
                float a2 = ap[4];
                float a3 = ap[8 * AP + 4];
                split_tf32(a0, ahi[mi][0], alo[mi][0]);
                split_tf32(a1, ahi[mi][1], alo[mi][1]);
                split_tf32(a2, ahi[mi][2], alo[mi][2]);
                split_tf32(a3, ahi[mi][3], alo[mi][3]);
            }
#pragma unroll
            for (int ni = 0; ni < 4; ni++) {
                const float* bp = Bb + (kb + tig) * BP + wn * 32 + ni * 8 + g;
                float b0 = bp[0];
                float b1 = bp[4 * BP];
                uint32_t bhi[2], blo[2];
                split_tf32(b0, bhi[0], blo[0]);
                split_tf32(b1, bhi[1], blo[1]);
#pragma unroll
                for (int mi = 0; mi < 4; mi++) {
                    mma8(acc[mi][ni], ahi[mi], bhi);
                    mma8(acc[mi][ni], ahi[mi], blo);
                    mma8(acc[mi][ni], alo[mi], bhi);
                }
            }
        }
        __syncthreads();
    }

    // ---- epilogue ----
#pragma unroll
    for (int mi = 0; mi < 4; mi++) {
        int r0 = rowBase + wm * 64 + mi * 16 + g;
        int r1 = r0 + 8;
#pragma unroll
        for (int ni = 0; ni < 4; ni++) {
            int col = colBase + wn * 32 + ni * 8 + tig * 2;
            float2 v0 = make_float2(acc[mi][ni][0], acc[mi][ni][1]);
            float2 v1 = make_float2(acc[mi][ni][2], acc[mi][ni][3]);
            if (MODE == 2 || MODE == 3) {
                float2 bv = *(const float2*)(bias + col);
                v0.x += bv.x; v0.y += bv.y;
                v1.x += bv.x; v1.y += bv.y;
            }
            if (MODE == 2) {
                v0.x = fmaxf(v0.x, 0.f); v0.y = fmaxf(v0.y, 0.f);
                v1.x = fmaxf(v1.x, 0.f); v1.y = fmaxf(v1.y, 0.f);
            }
            if (MODE == 3) {
                float2 e0 = *(const float2*)(res + (size_t)r0 * N + col);
                float2 e1 = *(const float2*)(res + (size_t)r1 * N + col);
                v0.x += e0.x; v0.y += e0.y;
                v1.x += e1.x; v1.y += e1.y;
            }
            *(float2*)(C + (size_t)r0 * N + col) = v0;
            *(float2*)(C + (size_t)r1 * N + col) = v1;
        }
    }
}

// ---------------- fused attention (unchanged from R3) ----------------
#define QPITCH 257
#define PPITCH 65
#define ATTN_SMEM_FLOATS (2 * 64 * QPITCH + 64 * PPITCH)

__device__ __forceinline__ void attn_load_tile(float* dst, size_t base, int stride,
                                               int colOff, int tid) {
#pragma unroll
    for (int i = 0; i < 16; i++) {
        int g = i * 256 + tid;
        int r = g >> 6;
        int c = (g & 63) << 2;
        float4 v = *(const float4*)(g_qkv + (base + (size_t)r * stride) * QKVC + colOff + c);
        float* d = dst + r * QPITCH + c;
        d[0] = v.x; d[1] = v.y; d[2] = v.z; d[3] = v.w;
    }
}

__global__ void attn_kernel() {
    extern __shared__ float sm[];
    float* Qs  = sm;
    float* KVs = sm + 64 * QPITCH;
    float* Ps  = sm + 2 * 64 * QPITCH;

    int tid = threadIdx.x;
    int warp = tid >> 5, lane = tid & 31;

    int u = blockIdx.x;
    bool gridmode = (u < 2048);
    int b, h, fix;
    if (gridmode) { b = u >> 8; h = (u >> 6) & 3; fix = u & 63; }
    else { int u2 = u - 2048; b = u2 >> 8; h = 4 + ((u2 >> 6) & 3); fix = u2 & 63; }
    size_t base; int stride;
    if (gridmode) { base = (size_t)b * 4096 + fix; stride = 64; }
    else          { base = ((size_t)b * 64 + fix) * 64; stride = 1; }

    attn_load_tile(Qs,  base, stride, h * 256, tid);
    attn_load_tile(KVs, base, stride, 2048,    tid);
    __syncthreads();

    float s0[8] = {}, s1[8] = {};
    const float* qb = Qs + (warp * 8) * QPITCH;
    const float* k0p = KVs + lane * QPITCH;
    const float* k1p = KVs + (lane + 32) * QPITCH;
#pragma unroll 4
    for (int k = 0; k < 256; k++) {
        float kv0 = k0p[k];
        float kv1 = k1p[k];
#pragma unroll
        for (int r = 0; r < 8; r++) {
            float qv = qb[r * QPITCH + k];
            s0[r] += qv * kv0;
            s1[r] += qv * kv1;
        }
    }

#pragma unroll
    for (int r = 0; r < 8; r++) {
        float mx = fmaxf(s0[r], s1[r]);
#pragma unroll
        for (int o = 16; o > 0; o >>= 1) mx = fmaxf(mx, __shfl_xor_sync(0xffffffffu, mx, o));
        float e0 = __expf(s0[r] - mx);
        float e1 = __expf(s1[r] - mx);
        float sum = e0 + e1;
#pragma unroll
        for (int o = 16; o > 0; o >>= 1) sum += __shfl_xor_sync(0xffffffffu, sum, o);
        float inv = 1.0f / sum;
        Ps[(warp * 8 + r) * PPITCH + lane]      = e0 * inv;
        Ps[(warp * 8 + r) * PPITCH + lane + 32] = e1 * inv;
    }
    __syncthreads();
    attn_load_tile(KVs, base, stride, 2304, tid);
    __syncthreads();

    float oa[8][8] = {};
    for (int z = 0; z < 64; z++) {
        float vv[8];
#pragma unroll
        for (int i = 0; i < 8; i++) vv[i] = KVs[z * QPITCH + lane + 32 * i];
#pragma unroll
        for (int r = 0; r < 8; r++) {
            float p = Ps[(warp * 8 + r) * PPITCH + z];
#pragma unroll
            for (int i = 0; i < 8; i++) oa[r][i] += p * vv[i];
        }
    }
#pragma unroll
    for (int r = 0; r < 8; r++) {
        size_t row = base + (size_t)(warp * 8 + r) * stride;
        float* op = g_attno + row * OC + h * 256 + lane;
#pragma unroll
        for (int i = 0; i < 8; i++) op[i * 32] = oa[r][i];
    }
}

// ---------- head-mix + unpermute + residual + LN2 (fused) ----------
__global__ void zred_ln2_kernel(const float* __restrict__ x,
                                const float* __restrict__ gamma,
                                const float* __restrict__ beta,
                                float* __restrict__ x2,
                                float* __restrict__ ln2out) {
    int gw   = (blockIdx.x * blockDim.x + threadIdx.x) >> 5;
    int lane = threadIdx.x & 31;

    int b = gw >> 12, m = (gw >> 6) & 63, n = gw & 63;
    int hh = ((n >> 3) << 3) | (m >> 3);
    int ww = ((n & 7) << 3) | (m & 7);
    size_t orow = ((size_t)b << 12) | (unsigned)((hh << 6) | ww);

    const float* arow = g_attno + (size_t)gw * OC;
    float4 acc0 = make_float4(0.f, 0.f, 0.f, 0.f);
    float4 acc1 = make_float4(0.f, 0.f, 0.f, 0.f);
#pragma unroll
    for (int h = 0; h < 8; h++) {
        float4 a0 = ((const float4*)(arow + h * 256))[lane];
        float4 a1 = ((const float4*)(arow + h * 256))[lane + 32];
        float4 s0 = ((const float4*)(g_so + h * 256))[lane];
        float4 s1 = ((const float4*)(g_so + h * 256))[lane + 32];
        acc0.x += a0.x * s0.x; acc0.y += a0.y * s0.y;
        acc0.z += a0.z * s0.z; acc0.w += a0.w * s0.w;
        acc1.x += a1.x * s1.x; acc1.y += a1.y * s1.y;
        acc1.z += a1.z * s1.z; acc1.w += a1.w * s1.w;
    }
    const float* xr = x + orow * DD;
    float4 x0 = ((const float4*)xr)[lane];
    float4 x1 = ((const float4*)xr)[lane + 32];
    float4 v0 = make_float4(x0.x + acc0.x, x0.y + acc0.y, x0.z + acc0.z, x0.w + acc0.w);
    float4 v1 = make_float4(x1.x + acc1.x, x1.y + acc1.y, x1.z + acc1.z, x1.w + acc1.w);

    ((float4*)(x2 + orow * DD))[lane]      = v0;
    ((float4*)(x2 + orow * DD))[lane + 32] = v1;

    float s  = v0.x + v0.y + v0.z + v0.w + v1.x + v1.y + v1.z + v1.w;
    float sq = v0.x*v0.x + v0.y*v0.y + v0.z*v0.z + v0.w*v0.w
             + v1.x*v1.x + v1.y*v1.y + v1.z*v1.z + v1.w*v1.w;
#pragma unroll
    for (int o = 16; o > 0; o >>= 1) {
        s  += __shfl_xor_sync(0xffffffffu, s,  o);
        sq += __shfl_xor_sync(0xffffffffu, sq, o);
    }
    float mean = s * (1.0f / 256.0f);
    float var  = sq * (1.0f / 256.0f) - mean * mean;
    float rstd = rsqrtf(var + 1e-5f);

    float4 g0 = ((const float4*)gamma)[lane];
    float4 g1 = ((const float4*)gamma)[lane + 32];
    float4 bb0 = ((const float4*)beta)[lane];
    float4 bb1 = ((const float4*)beta)[lane + 32];
    float4 o0, o1;
    o0.x = (v0.x - mean) * rstd * g0.x + bb0.x;
    o0.y = (v0.y - mean) * rstd * g0.y + bb0.y;
    o0.z = (v0.z - mean) * rstd * g0.z + bb0.z;
    o0.w = (v0.w - mean) * rstd * g0.w + bb0.w;
    o1.x = (v1.x - mean) * rstd * g1.x + bb1.x;
    o1.y = (v1.y - mean) * rstd * g1.y + bb1.y;
    o1.z = (v1.z - mean) * rstd * g1.z + bb1.z;
    o1.w = (v1.w - mean) * rstd * g1.w + bb1.w;
    ((float4*)(ln2out + orow * DD))[lane]      = o0;
    ((float4*)(ln2out + orow * DD))[lane + 32] = o1;
}

// ---------------- launch ----------------
extern "C" void kernel_launch(void* const* d_in, const int* in_sizes, int n_in,
                              void* d_out, int out_size) {
    const float* x    = (const float*)d_in[0];
    const float* ln1w = (const float*)d_in[1];
    const float* ln1b = (const float*)d_in[2];
    const float* qw   = (const float*)d_in[3];
    const float* kw   = (const float*)d_in[4];
    const float* vw   = (const float*)d_in[5];
    const float* ow   = (const float*)d_in[6];
    const float* ln2w = (const float*)d_in[7];
    const float* ln2b = (const float*)d_in[8];
    const float* w1   = (const float*)d_in[9];
    const float* b1   = (const float*)d_in[10];
    const float* w2   = (const float*)d_in[11];
    const float* b2   = (const float*)d_in[12];
    float* out = (float*)d_out;

    float *p_a, *p_wqkv, *p_qkv, *p_x2, *p_ln2, *p_mlp1;
    cudaGetSymbolAddress((void**)&p_a,     g_a);
    cudaGetSymbolAddress((void**)&p_wqkv,  g_wqkv);
    cudaGetSymbolAddress((void**)&p_qkv,   g_qkv);
    cudaGetSymbolAddress((void**)&p_x2,    g_x2);
    cudaGetSymbolAddress((void**)&p_ln2,   g_ln2);
    cudaGetSymbolAddress((void**)&p_mlp1,  g_mlp1);

    const int ATTN_SMEM_BYTES = ATTN_SMEM_FLOATS * 4;
    cudaFuncSetAttribute(attn_kernel, cudaFuncAttributeMaxDynamicSharedMemorySize,
                         ATTN_SMEM_BYTES);
    cudaFuncSetAttribute(mma_gemm_kernel<0>, cudaFuncAttributeMaxDynamicSharedMemorySize,
                         GEMM_SMEM_BYTES);
    cudaFuncSetAttribute(mma_gemm_kernel<2>, cudaFuncAttributeMaxDynamicSharedMemorySize,
                         GEMM_SMEM_BYTES);
    cudaFuncSetAttribute(mma_gemm_kernel<3>, cudaFuncAttributeMaxDynamicSharedMemorySize,
                         GEMM_SMEM_BYTES);

    // 1. weight prep
    prep_w_kernel<<<QKVC, 256>>>(qw, kw, vw);
    prep_so_kernel<<<256, 256>>>(ow);
    // 2. LN1 + block permute
    ln1_kernel<<<NTOK / 8, 256>>>(x, ln1w, ln1b, p_a);
    // 3. QKV projection: [32768,256] @ [256,2560] (3xTF32 tensor cores)
    mma_gemm_kernel<0><<<dim3(QKVC / 128, NTOK / 128), 256, GEMM_SMEM_BYTES>>>(
        p_a, p_wqkv, p_qkv, nullptr, nullptr, NTOK, QKVC, DD);
    // 4. grid + block attention
    attn_kernel<<<4096, 256, ATTN_SMEM_BYTES>>>();
    // 5. head-mix + unpermute + residual + LN2 (fused)
    zred_ln2_kernel<<<NTOK / 8, 256>>>(x, ln2w, ln2b, p_x2, p_ln2);
    // 6. MLP fc1 + ReLU
    mma_gemm_kernel<2><<<dim3(DD / 128, NTOK / 128), 256, GEMM_SMEM_BYTES>>>(
        p_ln2, w1, p_mlp1, b1, nullptr, NTOK, DD, DD);
    // 7. MLP fc2 + bias + residual -> output
    mma_gemm_kernel<3><<<dim3(DD / 128, NTOK / 128), 256, GEMM_SMEM_BYTES>>>(
        p_mlp1, w2, out, b2, p_x2, NTOK, DD, DD);
}

// round 6
// speedup vs baseline: 1.5234x; 1.3199x over previous
#include <cuda_runtime.h>
#include <cuda_bf16.h>
#include <cstdint>
#include <cstddef>

// ---------------- problem constants ----------------
#define NTOK     32768
#define DD       256
#define QKVC     2560
#define OC       2048

// ---------------- static scratch ----------------
__device__ __nv_bfloat16 g_asp  [(size_t)NTOK * 512];   // LN1 out, blocked, [row][hi256|lo256]
__device__ __nv_bfloat16 g_wsp  [(size_t)QKVC * 512];   // qkv weights [j][hi|lo] over d
__device__ __nv_bfloat16 g_w1sp [(size_t)DD * 512];     // w1^T split
__device__ __nv_bfloat16 g_w2sp [(size_t)DD * 512];     // w2^T split
__device__ __nv_bfloat16 g_ln2sp[(size_t)NTOK * 512];   // LN2 out split
__device__ __nv_bfloat16 g_m1sp [(size_t)NTOK * 512];   // MLP hidden split
__device__ float g_qkv  [(size_t)NTOK * QKVC];
__device__ float g_attno[(size_t)NTOK * OC];
__device__ float g_so   [OC];
__device__ float g_x2   [(size_t)NTOK * DD];

// ---------------- helpers ----------------
__device__ __forceinline__ void bsplit(float v, __nv_bfloat16& h, __nv_bfloat16& l) {
    h = __float2bfloat16_rn(v);
    l = __float2bfloat16_rn(v - __bfloat162float(h));
}
__device__ __forceinline__ void cpasync16(uint32_t s, const void* g) {
    asm volatile("cp.async.cg.shared.global [%0], [%1], 16;\n" :: "r"(s), "l"(g));
}
__device__ __forceinline__ void mma16816(float* c, const uint32_t* a, const uint32_t* b) {
    asm volatile(
        "mma.sync.aligned.m16n8k16.row.col.f32.bf16.bf16.f32 "
        "{%0,%1,%2,%3},{%4,%5,%6,%7},{%8,%9},{%0,%1,%2,%3};\n"
        : "+f"(c[0]), "+f"(c[1]), "+f"(c[2]), "+f"(c[3])
        : "r"(a[0]), "r"(a[1]), "r"(a[2]), "r"(a[3]), "r"(b[0]), "r"(b[1]));
}

// ---------------- weight prep: qkv transposed split  B[j][d] ----------------
__global__ void prep_wqkv_kernel(const float* __restrict__ q,
                                 const float* __restrict__ k,
                                 const float* __restrict__ v) {
    int idx = blockIdx.x * 256 + threadIdx.x;   // 2560*256
    int d = idx & 255, j = idx >> 8;
    float val;
    if (j < 2048) { int h = j >> 8, kk = j & 255; val = q[((size_t)(h * 256 + d)) * 256 + kk]; }
    else if (j < 2304) val = k[(size_t)d * 256 + (j - 2048)];
    else               val = v[(size_t)d * 256 + (j - 2304)];
    __nv_bfloat16 h16, l16; bsplit(val, h16, l16);
    g_wsp[(size_t)j * 512 + d]       = h16;
    g_wsp[(size_t)j * 512 + 256 + d] = l16;
}

// transpose-split: dst[j][d] = src[d][j], src [256][256]
__global__ void prep_wt_kernel(const float* __restrict__ src, __nv_bfloat16* __restrict__ dst) {
    int idx = blockIdx.x * 256 + threadIdx.x;
    int d = idx & 255, j = idx >> 8;
    float val = src[(size_t)d * 256 + j];
    __nv_bfloat16 h16, l16; bsplit(val, h16, l16);
    dst[(size_t)j * 512 + d]       = h16;
    dst[(size_t)j * 512 + 256 + d] = l16;
}

// ---------------- so[h,d] = sum_v o[h,d,v] ----------------
__global__ void prep_so_kernel(const float* __restrict__ o) {
    int row  = (blockIdx.x * blockDim.x + threadIdx.x) >> 5;
    int lane = threadIdx.x & 31;
    const float* rp = o + (size_t)row * 256;
    float4 a = ((const float4*)rp)[lane];
    float4 b = ((const float4*)rp)[lane + 32];
    float s = a.x + a.y + a.z + a.w + b.x + b.y + b.z + b.w;
#pragma unroll
    for (int off = 16; off > 0; off >>= 1) s += __shfl_xor_sync(0xffffffffu, s, off);
    if (lane == 0) g_so[row] = s;
}

// ---------------- LN1 + block permute -> split bf16 ----------------
__device__ __forceinline__ void store_split8(__nv_bfloat16* rowp, int col,
                                             float4 v0, float4 v1) {
    __nv_bfloat16 h[8], l[8];
    bsplit(v0.x, h[0], l[0]); bsplit(v0.y, h[1], l[1]);
    bsplit(v0.z, h[2], l[2]); bsplit(v0.w, h[3], l[3]);
    bsplit(v1.x, h[4], l[4]); bsplit(v1.y, h[5], l[5]);
    bsplit(v1.z, h[6], l[6]); bsplit(v1.w, h[7], l[7]);
#pragma unroll
    for (int i = 0; i < 4; i++) {
        rowp[col + i]             = h[i];
        rowp[col + 128 + i]       = h[4 + i];
        rowp[256 + col + i]       = l[i];
        rowp[256 + col + 128 + i] = l[4 + i];
    }
}

__global__ void ln1_kernel(const float* __restrict__ in,
                           const float* __restrict__ gamma,
                           const float* __restrict__ beta) {
    int gwarp = (blockIdx.x * blockDim.x + threadIdx.x) >> 5;
    int lane  = threadIdx.x & 31;
    const float* row = in + (size_t)gwarp * DD;
    float4 v0 = ((const float4*)row)[lane];
    float4 v1 = ((const float4*)row)[lane + 32];
    float s  = v0.x + v0.y + v0.z + v0.w + v1.x + v1.y + v1.z + v1.w;
    float sq = v0.x*v0.x + v0.y*v0.y + v0.z*v0.z + v0.w*v0.w
             + v1.x*v1.x + v1.y*v1.y + v1.z*v1.z + v1.w*v1.w;
#pragma unroll
    for (int o = 16; o > 0; o >>= 1) {
        s  += __shfl_xor_sync(0xffffffffu, s,  o);
        sq += __shfl_xor_sync(0xffffffffu, sq, o);
    }
    float mean = s * (1.0f / 256.0f);
    float var  = sq * (1.0f / 256.0f) - mean * mean;
    float rstd = rsqrtf(var + 1e-5f);

    int b = gwarp >> 12, pos = gwarp & 4095;
    int h = pos >> 6, w = pos & 63;
    int m = ((h & 7) << 3) | (w & 7);
    int n = ((h >> 3) << 3) | (w >> 3);
    size_t orow = ((size_t)b << 12) | (unsigned)((m << 6) | n);

    float4 g0 = ((const float4*)gamma)[lane];
    float4 g1 = ((const float4*)gamma)[lane + 32];
    float4 b0 = ((const float4*)beta)[lane];
    float4 b1 = ((const float4*)beta)[lane + 32];
    float4 o0, o1;
    o0.x = (v0.x - mean) * rstd * g0.x + b0.x;
    o0.y = (v0.y - mean) * rstd * g0.y + b0.y;
    o0.z = (v0.z - mean) * rstd * g0.z + b0.z;
    o0.w = (v0.w - mean) * rstd * g0.w + b0.w;
    o1.x = (v1.x - mean) * rstd * g1.x + b1.x;
    o1.y = (v1.y - mean) * rstd * g1.y + b1.y;
    o1.z = (v1.z - mean) * rstd * g1.z + b1.z;
    o1.w = (v1.w - mean) * rstd * g1.w + b1.w;
    store_split8(g_asp + orow * 512, lane * 4, o0, o1);
}

// ================= bf16 mma.sync GEMM, 3-term split =================
// C[M,N] = A(M,256) @ W(256,N). A split [row][hi|lo], B split [j][hi|lo].
// CTA tile 128x128, 8 warps (2x4), warp 64x32, K-chunk 32 (2 k16 steps),
// double-buffered cp.async. Pitch P=40 bf16 -> conflict-free fragment LDS.
// MODE 0: fp32 store   MODE 2: +bias, relu, split bf16 store   MODE 3: +bias +res fp32
#define GP 40
#define MATB (128 * GP * 2)            // one matrix piece: 10240 B
#define STAGEB (4 * MATB)              // Ah, Al, Bh, Bl: 40960 B
#define GSMEM (2 * STAGEB)             // 81920 B

template <int MODE>
__global__ __launch_bounds__(256, 2)
void bfmma_gemm_kernel(const __nv_bfloat16* __restrict__ Asp,
                       const __nv_bfloat16* __restrict__ Bsp,
                       float* __restrict__ C,
                       __nv_bfloat16* __restrict__ Csp,
                       const float* __restrict__ bias,
                       const float* __restrict__ res,
                       int ldC) {
    extern __shared__ __nv_bfloat16 smem[];
    uint32_t sb = (uint32_t)__cvta_generic_to_shared(smem);

    int tid = threadIdx.x;
    int lane = tid & 31, warp = tid >> 5;
    int wm = warp & 1, wn = warp >> 1;
    int g = lane >> 2, tig = lane & 3;
    int rowBase = blockIdx.y * 128;
    int colBase = blockIdx.x * 128;

    float acc[4][4][4] = {};

    auto load_chunk = [&](int c, int st) {
        const __nv_bfloat16* Ag = Asp + (size_t)rowBase * 512 + c * 32;
        const __nv_bfloat16* Bg = Bsp + (size_t)colBase * 512 + c * 32;
        uint32_t base = sb + (uint32_t)st * STAGEB;
#pragma unroll
        for (int i = 0; i < 2; i++) {
            int f = tid + i * 256;         // 512 transfers per piece
            int r = f >> 2, q = f & 3;
            uint32_t so = (uint32_t)(r * GP + q * 8) * 2;
            const __nv_bfloat16* ga = Ag + (size_t)r * 512 + q * 8;
            const __nv_bfloat16* gb = Bg + (size_t)r * 512 + q * 8;
            cpasync16(base + so,            ga);          // A hi
            cpasync16(base + MATB + so,     ga + 256);    // A lo
            cpasync16(base + 2 * MATB + so, gb);          // B hi
            cpasync16(base + 3 * MATB + so, gb + 256);    // B lo
        }
        asm volatile("cp.async.commit_group;\n");
    };

    load_chunk(0, 0);

    const int NCH = 8;                    // K = 256 / 32
    for (int c = 0; c < NCH; c++) {
        if (c + 1 < NCH) {
            load_chunk(c + 1, (c + 1) & 1);
            asm volatile("cp.async.wait_group 1;\n");
        } else {
            asm volatile("cp.async.wait_group 0;\n");
        }
        __syncthreads();

        const __nv_bfloat16* Ah = smem + (c & 1) * (STAGEB / 2);
        const __nv_bfloat16* Al = Ah + MATB / 2;
        const __nv_bfloat16* Bh = Ah + MATB;         // 2*MATB/2
        const __nv_bfloat16* Bl = Ah + 3 * (MATB / 2);

#pragma unroll
        for (int ks = 0; ks < 2; ks++) {
            int kb = ks * 16;
            uint32_t ahi[4][4], alo[4][4];
#pragma unroll
            for (int mi = 0; mi < 4; mi++) {
                int row = wm * 64 + mi * 16 + g;
                const __nv_bfloat16* ph = Ah + row * GP + kb + 2 * tig;
                const __nv_bfloat16* pl = Al + row * GP + kb + 2 * tig;
                ahi[mi][0] = *(const uint32_t*)(ph);
                ahi[mi][1] = *(const uint32_t*)(ph + 8 * GP);
                ahi[mi][2] = *(const uint32_t*)(ph + 8);
                ahi[mi][3] = *(const uint32_t*)(ph + 8 * GP + 8);
                alo[mi][0] = *(const uint32_t*)(pl);
                alo[mi][1] = *(const uint32_t*)(pl + 8 * GP);
                alo[mi][2] = *(const uint32_t*)(pl + 8);
                alo[mi][3] = *(const uint32_t*)(pl + 8 * GP + 8);
            }
#pragma unroll
            for (int ni = 0; ni < 4; ni++) {
                int n = wn * 32 + ni * 8 + g;
                const __nv_bfloat16* ph = Bh + n * GP + kb + 2 * tig;
                const __nv_bfloat16* pl = Bl + n * GP + kb + 2 * tig;
                uint32_t bh[2], bl[2];
                bh[0] = *(const uint32_t*)(ph);
                bh[1] = *(const uint32_t*)(ph + 8);
                bl[0] = *(const uint32_t*)(pl);
                bl[1] = *(const uint32_t*)(pl + 8);
#pragma unroll
                for (int mi = 0; mi < 4; mi++) {
                    mma16816(acc[mi][ni], ahi[mi], bh);
                    mma16816(acc[mi][ni], alo[mi], bh);
                    mma16816(acc[mi][ni], ahi[mi], bl);
                }
            }
        }
        __syncthreads();
    }

    // ---- epilogue ----
#pragma unroll
    for (int mi = 0; mi < 4; mi++) {
        int r0 = rowBase + wm * 64 + mi * 16 + g;
        int r1 = r0 + 8;
#pragma unroll
        for (int ni = 0; ni < 4; ni++) {
            int col = colBase + wn * 32 + ni * 8 + tig * 2;
            float2 v0 = make_float2(acc[mi][ni][0], acc[mi][ni][1]);
            float2 v1 = make_float2(acc[mi][ni][2], acc[mi][ni][3]);
            if (MODE == 2 || MODE == 3) {
                float2 bv = *(const float2*)(bias + col);
                v0.x += bv.x; v0.y += bv.y;
                v1.x += bv.x; v1.y += bv.y;
            }
            if (MODE == 2) {
                v0.x = fmaxf(v0.x, 0.f); v0.y = fmaxf(v0.y, 0.f);
                v1.x = fmaxf(v1.x, 0.f); v1.y = fmaxf(v1.y, 0.f);
                __nv_bfloat16 h0, l0, h1, l1;
                __nv_bfloat162* hp0 = (__nv_bfloat162*)(Csp + (size_t)r0 * 512 + col);
                __nv_bfloat162* lp0 = (__nv_bfloat162*)(Csp + (size_t)r0 * 512 + 256 + col);
                bsplit(v0.x, h0, l0); bsplit(v0.y, h1, l1);
                *hp0 = __nv_bfloat162(h0, h1);
                *lp0 = __nv_bfloat162(l0, l1);
                __nv_bfloat162* hp1 = (__nv_bfloat162*)(Csp + (size_t)r1 * 512 + col);
                __nv_bfloat162* lp1 = (__nv_bfloat162*)(Csp + (size_t)r1 * 512 + 256 + col);
                bsplit(v1.x, h0, l0); bsplit(v1.y, h1, l1);
                *hp1 = __nv_bfloat162(h0, h1);
                *lp1 = __nv_bfloat162(l0, l1);
            } else {
                if (MODE == 3) {
                    float2 e0 = *(const float2*)(res + (size_t)r0 * ldC + col);
                    float2 e1 = *(const float2*)(res + (size_t)r1 * ldC + col);
                    v0.x += e0.x; v0.y += e0.y;
                    v1.x += e1.x; v1.y += e1.y;
                }
                *(float2*)(C + (size_t)r0 * ldC + col) = v0;
                *(float2*)(C + (size_t)r1 * ldC + col) = v1;
            }
        }
    }
}

// ---------------- fused attention (fp32, unchanged) ----------------
#define QPITCH 257
#define PPITCH 65
#define ATTN_SMEM_FLOATS (2 * 64 * QPITCH + 64 * PPITCH)

__device__ __forceinline__ void attn_load_tile(float* dst, size_t base, int stride,
                                               int colOff, int tid) {
#pragma unroll
    for (int i = 0; i < 16; i++) {
        int g = i * 256 + tid;
        int r = g >> 6;
        int c = (g & 63) << 2;
        float4 v = *(const float4*)(g_qkv + (base + (size_t)r * stride) * QKVC + colOff + c);
        float* d = dst + r * QPITCH + c;
        d[0] = v.x; d[1] = v.y; d[2] = v.z; d[3] = v.w;
    }
}

__global__ void attn_kernel() {
    extern __shared__ float sm[];
    float* Qs  = sm;
    float* KVs = sm + 64 * QPITCH;
    float* Ps  = sm + 2 * 64 * QPITCH;

    int tid = threadIdx.x;
    int warp = tid >> 5, lane = tid & 31;

    int u = blockIdx.x;
    bool gridmode = (u < 2048);
    int b, h, fix;
    if (gridmode) { b = u >> 8; h = (u >> 6) & 3; fix = u & 63; }
    else { int u2 = u - 2048; b = u2 >> 8; h = 4 + ((u2 >> 6) & 3); fix = u2 & 63; }
    size_t base; int stride;
    if (gridmode) { base = (size_t)b * 4096 + fix; stride = 64; }
    else          { base = ((size_t)b * 64 + fix) * 64; stride = 1; }

    attn_load_tile(Qs,  base, stride, h * 256, tid);
    attn_load_tile(KVs, base, stride, 2048,    tid);
    __syncthreads();

    float s0[8] = {}, s1[8] = {};
    const float* qb = Qs + (warp * 8) * QPITCH;
    const float* k0p = KVs + lane * QPITCH;
    const float* k1p = KVs + (lane + 32) * QPITCH;
#pragma unroll 4
    for (int k = 0; k < 256; k++) {
        float kv0 = k0p[k];
        float kv1 = k1p[k];
#pragma unroll
        for (int r = 0; r < 8; r++) {
            float qv = qb[r * QPITCH + k];
            s0[r] += qv * kv0;
            s1[r] += qv * kv1;
        }
    }

#pragma unroll
    for (int r = 0; r < 8; r++) {
        float mx = fmaxf(s0[r], s1[r]);
#pragma unroll
        for (int o = 16; o > 0; o >>= 1) mx = fmaxf(mx, __shfl_xor_sync(0xffffffffu, mx, o));
        float e0 = __expf(s0[r] - mx);
        float e1 = __expf(s1[r] - mx);
        float sum = e0 + e1;
#pragma unroll
        for (int o = 16; o > 0; o >>= 1) sum += __shfl_xor_sync(0xffffffffu, sum, o);
        float inv = 1.0f / sum;
        Ps[(warp * 8 + r) * PPITCH + lane]      = e0 * inv;
        Ps[(warp * 8 + r) * PPITCH + lane + 32] = e1 * inv;
    }
    __syncthreads();
    attn_load_tile(KVs, base, stride, 2304, tid);
    __syncthreads();

    float oa[8][8] = {};
    for (int z = 0; z < 64; z++) {
        float vv[8];
#pragma unroll
        for (int i = 0; i < 8; i++) vv[i] = KVs[z * QPITCH + lane + 32 * i];
#pragma unroll
        for (int r = 0; r < 8; r++) {
            float p = Ps[(warp * 8 + r) * PPITCH + z];
#pragma unroll
            for (int i = 0; i < 8; i++) oa[r][i] += p * vv[i];
        }
    }
#pragma unroll
    for (int r = 0; r < 8; r++) {
        size_t row = base + (size_t)(warp * 8 + r) * stride;
        float* op = g_attno + row * OC + h * 256 + lane;
#pragma unroll
        for (int i = 0; i < 8; i++) op[i * 32] = oa[r][i];
    }
}

// ---------- head-mix + unpermute + residual + LN2 -> split bf16 ----------
__global__ void zred_ln2_kernel(const float* __restrict__ x,
                                const float* __restrict__ gamma,
                                const float* __restrict__ beta,
                                float* __restrict__ x2) {
    int gw   = (blockIdx.x * blockDim.x + threadIdx.x) >> 5;
    int lane = threadIdx.x & 31;

    int b = gw >> 12, m = (gw >> 6) & 63, n = gw & 63;
    int hh = ((n >> 3) << 3) | (m >> 3);
    int ww = ((n & 7) << 3) | (m & 7);
    size_t orow = ((size_t)b << 12) | (unsigned)((hh << 6) | ww);

    const float* arow = g_attno + (size_t)gw * OC;
    float4 acc0 = make_float4(0.f, 0.f, 0.f, 0.f);
    float4 acc1 = make_float4(0.f, 0.f, 0.f, 0.f);
#pragma unroll
    for (int h = 0; h < 8; h++) {
        float4 a0 = ((const float4*)(arow + h * 256))[lane];
        float4 a1 = ((const float4*)(arow + h * 256))[lane + 32];
        float4 s0 = ((const float4*)(g_so + h * 256))[lane];
        float4 s1 = ((const float4*)(g_so + h * 256))[lane + 32];
        acc0.x += a0.x * s0.x; acc0.y += a0.y * s0.y;
        acc0.z += a0.z * s0.z; acc0.w += a0.w * s0.w;
        acc1.x += a1.x * s1.x; acc1.y += a1.y * s1.y;
        acc1.z += a1.z * s1.z; acc1.w += a1.w * s1.w;
    }
    const float* xr = x + orow * DD;
    float4 x0 = ((const float4*)xr)[lane];
    float4 x1 = ((const float4*)xr)[lane + 32];
    float4 v0 = make_float4(x0.x + acc0.x, x0.y + acc0.y, x0.z + acc0.z, x0.w + acc0.w);
    float4 v1 = make_float4(x1.x + acc1.x, x1.y + acc1.y, x1.z + acc1.z, x1.w + acc1.w);

    ((float4*)(x2 + orow * DD))[lane]      = v0;
    ((float4*)(x2 + orow * DD))[lane + 32] = v1;

    float s  = v0.x + v0.y + v0.z + v0.w + v1.x + v1.y + v1.z + v1.w;
    float sq = v0.x*v0.x + v0.y*v0.y + v0.z*v0.z + v0.w*v0.w
             + v1.x*v1.x + v1.y*v1.y + v1.z*v1.z + v1.w*v1.w;
#pragma unroll
    for (int o = 16; o > 0; o >>= 1) {
        s  += __shfl_xor_sync(0xffffffffu, s,  o);
        sq += __shfl_xor_sync(0xffffffffu, sq, o);
    }
    float mean = s * (1.0f / 256.0f);
    float var  = sq * (1.0f / 256.0f) - mean * mean;
    float rstd = rsqrtf(var + 1e-5f);

    float4 g0 = ((const float4*)gamma)[lane];
    float4 g1 = ((const float4*)gamma)[lane + 32];
    float4 bb0 = ((const float4*)beta)[lane];
    float4 bb1 = ((const float4*)beta)[lane + 32];
    float4 o0, o1;
    o0.x = (v0.x - mean) * rstd * g0.x + bb0.x;
    o0.y = (v0.y - mean) * rstd * g0.y + bb0.y;
    o0.z = (v0.z - mean) * rstd * g0.z + bb0.z;
    o0.w = (v0.w - mean) * rstd * g0.w + bb0.w;
    o1.x = (v1.x - mean) * rstd * g1.x + bb1.x;
    o1.y = (v1.y - mean) * rstd * g1.y + bb1.y;
    o1.z = (v1.z - mean) * rstd * g1.z + bb1.z;
    o1.w = (v1.w - mean) * rstd * g1.w + bb1.w;
    store_split8(g_ln2sp + orow * 512, lane * 4, o0, o1);
}

// ---------------- launch ----------------
extern "C" void kernel_launch(void* const* d_in, const int* in_sizes, int n_in,
                              void* d_out, int out_size) {
    const float* x    = (const float*)d_in[0];
    const float* ln1w = (const float*)d_in[1];
    const float* ln1b = (const float*)d_in[2];
    const float* qw   = (const float*)d_in[3];
    const float* kw   = (const float*)d_in[4];
    const float* vw   = (const float*)d_in[5];
    const float* ow   = (const float*)d_in[6];
    const float* ln2w = (const float*)d_in[7];
    const float* ln2b = (const float*)d_in[8];
    const float* w1   = (const float*)d_in[9];
    const float* b1   = (const float*)d_in[10];
    const float* w2   = (const float*)d_in[11];
    const float* b2   = (const float*)d_in[12];
    float* out = (float*)d_out;

    __nv_bfloat16 *p_asp, *p_wsp, *p_w1sp, *p_w2sp, *p_ln2sp, *p_m1sp;
    float *p_qkv, *p_x2;
    cudaGetSymbolAddress((void**)&p_asp,   g_asp);
    cudaGetSymbolAddress((void**)&p_wsp,   g_wsp);
    cudaGetSymbolAddress((void**)&p_w1sp,  g_w1sp);
    cudaGetSymbolAddress((void**)&p_w2sp,  g_w2sp);
    cudaGetSymbolAddress((void**)&p_ln2sp, g_ln2sp);
    cudaGetSymbolAddress((void**)&p_m1sp,  g_m1sp);
    cudaGetSymbolAddress((void**)&p_qkv,   g_qkv);
    cudaGetSymbolAddress((void**)&p_x2,    g_x2);

    const int ATTN_SMEM_BYTES = ATTN_SMEM_FLOATS * 4;
    cudaFuncSetAttribute(attn_kernel, cudaFuncAttributeMaxDynamicSharedMemorySize,
                         ATTN_SMEM_BYTES);
    cudaFuncSetAttribute(bfmma_gemm_kernel<0>, cudaFuncAttributeMaxDynamicSharedMemorySize, GSMEM);
    cudaFuncSetAttribute(bfmma_gemm_kernel<2>, cudaFuncAttributeMaxDynamicSharedMemorySize, GSMEM);
    cudaFuncSetAttribute(bfmma_gemm_kernel<3>, cudaFuncAttributeMaxDynamicSharedMemorySize, GSMEM);

    // 1. weight prep (split bf16)
    prep_wqkv_kernel<<<QKVC, 256>>>(qw, kw, vw);
    prep_wt_kernel<<<256, 256>>>(w1, p_w1sp);
    prep_wt_kernel<<<256, 256>>>(w2, p_w2sp);
    prep_so_kernel<<<256, 256>>>(ow);
    // 2. LN1 + block permute -> split
    ln1_kernel<<<NTOK / 8, 256>>>(x, ln1w, ln1b);
    // 3. QKV projection (bf16 mma, 3-term split)
    bfmma_gemm_kernel<0><<<dim3(QKVC / 128, NTOK / 128), 256, GSMEM>>>(
        p_asp, p_wsp, p_qkv, nullptr, nullptr, nullptr, QKVC);
    // 4. attention
    attn_kernel<<<4096, 256, ATTN_SMEM_BYTES>>>();
    // 5. head-mix + unpermute + residual + LN2 -> split
    zred_ln2_kernel<<<NTOK / 8, 256>>>(x, ln2w, ln2b, p_x2);
    // 6. MLP fc1 + ReLU -> split
    bfmma_gemm_kernel<2><<<dim3(DD / 128, NTOK / 128), 256, GSMEM>>>(
        p_ln2sp, p_w1sp, nullptr, p_m1sp, b1, nullptr, DD);
    // 7. MLP fc2 + bias + residual -> out
    bfmma_gemm_kernel<3><<<dim3(DD / 128, NTOK / 128), 256, GSMEM>>>(
        p_m1sp, p_w2sp, out, nullptr, b2, p_x2, DD);
}

// round 7
// speedup vs baseline: 2.2106x; 1.4511x over previous
#include <cuda_runtime.h>
#include <cuda_bf16.h>
#include <cstdint>
#include <cstddef>

// ---------------- problem constants ----------------
#define NTOK     32768
#define DD       256
#define QKVC     2560
#define OC       2048

// ---------------- static scratch ----------------
__device__ __nv_bfloat16 g_asp  [(size_t)NTOK * 512];    // LN1 out, blocked, [row][hi256|lo256]
__device__ __nv_bfloat16 g_wsp  [(size_t)QKVC * 512];    // qkv weights [j][hi|lo] over d
__device__ __nv_bfloat16 g_w1sp [(size_t)DD * 512];
__device__ __nv_bfloat16 g_w2sp [(size_t)DD * 512];
__device__ __nv_bfloat16 g_ln2sp[(size_t)NTOK * 512];
__device__ __nv_bfloat16 g_m1sp [(size_t)NTOK * 512];
__device__ __nv_bfloat16 g_qkvsp[(size_t)NTOK * 5120];   // QKV out split: [tok][hi2560|lo2560]
__device__ float g_attno[(size_t)NTOK * OC];
__device__ float g_so   [OC];
__device__ float g_x2   [(size_t)NTOK * DD];

// ---------------- helpers ----------------
__device__ __forceinline__ void bsplit(float v, __nv_bfloat16& h, __nv_bfloat16& l) {
    h = __float2bfloat16_rn(v);
    l = __float2bfloat16_rn(v - __bfloat162float(h));
}
__device__ __forceinline__ void cpasync16(uint32_t s, const void* g) {
    asm volatile("cp.async.cg.shared.global [%0], [%1], 16;\n" :: "r"(s), "l"(g));
}
__device__ __forceinline__ void mma16816(float* c, const uint32_t* a, const uint32_t* b) {
    asm volatile(
        "mma.sync.aligned.m16n8k16.row.col.f32.bf16.bf16.f32 "
        "{%0,%1,%2,%3},{%4,%5,%6,%7},{%8,%9},{%0,%1,%2,%3};\n"
        : "+f"(c[0]), "+f"(c[1]), "+f"(c[2]), "+f"(c[3])
        : "r"(a[0]), "r"(a[1]), "r"(a[2]), "r"(a[3]), "r"(b[0]), "r"(b[1]));
}
__device__ __forceinline__ uint32_t pack2(const __nv_bfloat16* p0, const __nv_bfloat16* p1) {
    uint32_t a = *(const uint16_t*)p0;
    uint32_t b = *(const uint16_t*)p1;
    return a | (b << 16);
}

// ---------------- weight prep ----------------
__global__ void prep_wqkv_kernel(const float* __restrict__ q,
                                 const float* __restrict__ k,
                                 const float* __restrict__ v) {
    int idx = blockIdx.x * 256 + threadIdx.x;
    int d = idx & 255, j = idx >> 8;
    float val;
    if (j < 2048) { int h = j >> 8, kk = j & 255; val = q[((size_t)(h * 256 + d)) * 256 + kk]; }
    else if (j < 2304) val = k[(size_t)d * 256 + (j - 2048)];
    else               val = v[(size_t)d * 256 + (j - 2304)];
    __nv_bfloat16 h16, l16; bsplit(val, h16, l16);
    g_wsp[(size_t)j * 512 + d]       = h16;
    g_wsp[(size_t)j * 512 + 256 + d] = l16;
}

__global__ void prep_wt_kernel(const float* __restrict__ src, __nv_bfloat16* __restrict__ dst) {
    int idx = blockIdx.x * 256 + threadIdx.x;
    int d = idx & 255, j = idx >> 8;
    float val = src[(size_t)d * 256 + j];
    __nv_bfloat16 h16, l16; bsplit(val, h16, l16);
    dst[(size_t)j * 512 + d]       = h16;
    dst[(size_t)j * 512 + 256 + d] = l16;
}

__global__ void prep_so_kernel(const float* __restrict__ o) {
    int row  = (blockIdx.x * blockDim.x + threadIdx.x) >> 5;
    int lane = threadIdx.x & 31;
    const float* rp = o + (size_t)row * 256;
    float4 a = ((const float4*)rp)[lane];
    float4 b = ((const float4*)rp)[lane + 32];
    float s = a.x + a.y + a.z + a.w + b.x + b.y + b.z + b.w;
#pragma unroll
    for (int off = 16; off > 0; off >>= 1) s += __shfl_xor_sync(0xffffffffu, s, off);
    if (lane == 0) g_so[row] = s;
}

// ---------------- LN1 + block permute -> split bf16 ----------------
__device__ __forceinline__ void store_split8(__nv_bfloat16* rowp, int col,
                                             float4 v0, float4 v1) {
    __nv_bfloat16 h[8], l[8];
    bsplit(v0.x, h[0], l[0]); bsplit(v0.y, h[1], l[1]);
    bsplit(v0.z, h[2], l[2]); bsplit(v0.w, h[3], l[3]);
    bsplit(v1.x, h[4], l[4]); bsplit(v1.y, h[5], l[5]);
    bsplit(v1.z, h[6], l[6]); bsplit(v1.w, h[7], l[7]);
#pragma unroll
    for (int i = 0; i < 4; i++) {
        rowp[col + i]             = h[i];
        rowp[col + 128 + i]       = h[4 + i];
        rowp[256 + col + i]       = l[i];
        rowp[256 + col + 128 + i] = l[4 + i];
    }
}

__global__ void ln1_kernel(const float* __restrict__ in,
                           const float* __restrict__ gamma,
                           const float* __restrict__ beta) {
    int gwarp = (blockIdx.x * blockDim.x + threadIdx.x) >> 5;
    int lane  = threadIdx.x & 31;
    const float* row = in + (size_t)gwarp * DD;
    float4 v0 = ((const float4*)row)[lane];
    float4 v1 = ((const float4*)row)[lane + 32];
    float s  = v0.x + v0.y + v0.z + v0.w + v1.x + v1.y + v1.z + v1.w;
    float sq = v0.x*v0.x + v0.y*v0.y + v0.z*v0.z + v0.w*v0.w
             + v1.x*v1.x + v1.y*v1.y + v1.z*v1.z + v1.w*v1.w;
#pragma unroll
    for (int o = 16; o > 0; o >>= 1) {
        s  += __shfl_xor_sync(0xffffffffu, s,  o);
        sq += __shfl_xor_sync(0xffffffffu, sq, o);
    }
    float mean = s * (1.0f / 256.0f);
    float var  = sq * (1.0f / 256.0f) - mean * mean;
    float rstd = rsqrtf(var + 1e-5f);

    int b = gwarp >> 12, pos = gwarp & 4095;
    int h = pos >> 6, w = pos & 63;
    int m = ((h & 7) << 3) | (w & 7);
    int n = ((h >> 3) << 3) | (w >> 3);
    size_t orow = ((size_t)b << 12) | (unsigned)((m << 6) | n);

    float4 g0 = ((const float4*)gamma)[lane];
    float4 g1 = ((const float4*)gamma)[lane + 32];
    float4 b0 = ((const float4*)beta)[lane];
    float4 b1 = ((const float4*)beta)[lane + 32];
    float4 o0, o1;
    o0.x = (v0.x - mean) * rstd * g0.x + b0.x;
    o0.y = (v0.y - mean) * rstd * g0.y + b0.y;
    o0.z = (v0.z - mean) * rstd * g0.z + b0.z;
    o0.w = (v0.w - mean) * rstd * g0.w + b0.w;
    o1.x = (v1.x - mean) * rstd * g1.x + b1.x;
    o1.y = (v1.y - mean) * rstd * g1.y + b1.y;
    o1.z = (v1.z - mean) * rstd * g1.z + b1.z;
    o1.w = (v1.w - mean) * rstd * g1.w + b1.w;
    store_split8(g_asp + orow * 512, lane * 4, o0, o1);
}

// ================= bf16 mma GEMM, 3-term split (R6-proven) =================
// MODE 0: split bf16 store to g_qkvsp   MODE 2: +bias, relu, split store
// MODE 3: +bias, +residual, fp32 store
#define GP 40
#define MATB (128 * GP * 2)
#define STAGEB (4 * MATB)
#define GSMEM (2 * STAGEB)

template <int MODE>
__global__ __launch_bounds__(256, 2)
void bfmma_gemm_kernel(const __nv_bfloat16* __restrict__ Asp,
                       const __nv_bfloat16* __restrict__ Bsp,
                       float* __restrict__ C,
                       __nv_bfloat16* __restrict__ Csp,
                       const float* __restrict__ bias,
                       const float* __restrict__ res,
                       int ldC) {
    extern __shared__ __nv_bfloat16 smem[];
    uint32_t sb = (uint32_t)__cvta_generic_to_shared(smem);

    int tid = threadIdx.x;
    int lane = tid & 31, warp = tid >> 5;
    int wm = warp & 1, wn = warp >> 1;
    int g = lane >> 2, tig = lane & 3;
    int rowBase = blockIdx.y * 128;
    int colBase = blockIdx.x * 128;

    float acc[4][4][4] = {};

    auto load_chunk = [&](int c, int st) {
        const __nv_bfloat16* Ag = Asp + (size_t)rowBase * 512 + c * 32;
        const __nv_bfloat16* Bg = Bsp + (size_t)colBase * 512 + c * 32;
        uint32_t base = sb + (uint32_t)st * STAGEB;
#pragma unroll
        for (int i = 0; i < 2; i++) {
            int f = tid + i * 256;
            int r = f >> 2, q = f & 3;
            uint32_t so = (uint32_t)(r * GP + q * 8) * 2;
            const __nv_bfloat16* ga = Ag + (size_t)r * 512 + q * 8;
            const __nv_bfloat16* gb = Bg + (size_t)r * 512 + q * 8;
            cpasync16(base + so,            ga);
            cpasync16(base + MATB + so,     ga + 256);
            cpasync16(base + 2 * MATB + so, gb);
            cpasync16(base + 3 * MATB + so, gb + 256);
        }
        asm volatile("cp.async.commit_group;\n");
    };

    load_chunk(0, 0);

    const int NCH = 8;
    for (int c = 0; c < NCH; c++) {
        if (c + 1 < NCH) {
            load_chunk(c + 1, (c + 1) & 1);
            asm volatile("cp.async.wait_group 1;\n");
        } else {
            asm volatile("cp.async.wait_group 0;\n");
        }
        __syncthreads();

        const __nv_bfloat16* Ah = smem + (c & 1) * (STAGEB / 2);
        const __nv_bfloat16* Al = Ah + MATB / 2;
        const __nv_bfloat16* Bh = Ah + MATB;
        const __nv_bfloat16* Bl = Ah + 3 * (MATB / 2);

#pragma unroll
        for (int ks = 0; ks < 2; ks++) {
            int kb = ks * 16;
            uint32_t ahi[4][4], alo[4][4];
#pragma unroll
            for (int mi = 0; mi < 4; mi++) {
                int row = wm * 64 + mi * 16 + g;
                const __nv_bfloat16* ph = Ah + row * GP + kb + 2 * tig;
                const __nv_bfloat16* pl = Al + row * GP + kb + 2 * tig;
                ahi[mi][0] = *(const uint32_t*)(ph);
                ahi[mi][1] = *(const uint32_t*)(ph + 8 * GP);
                ahi[mi][2] = *(const uint32_t*)(ph + 8);
                ahi[mi][3] = *(const uint32_t*)(ph + 8 * GP + 8);
                alo[mi][0] = *(const uint32_t*)(pl);
                alo[mi][1] = *(const uint32_t*)(pl + 8 * GP);
                alo[mi][2] = *(const uint32_t*)(pl + 8);
                alo[mi][3] = *(const uint32_t*)(pl + 8 * GP + 8);
            }
#pragma unroll
            for (int ni = 0; ni < 4; ni++) {
                int n = wn * 32 + ni * 8 + g;
                const __nv_bfloat16* ph = Bh + n * GP + kb + 2 * tig;
                const __nv_bfloat16* pl = Bl + n * GP + kb + 2 * tig;
                uint32_t bh[2], bl[2];
                bh[0] = *(const uint32_t*)(ph);
                bh[1] = *(const uint32_t*)(ph + 8);
                bl[0] = *(const uint32_t*)(pl);
                bl[1] = *(const uint32_t*)(pl + 8);
#pragma unroll
                for (int mi = 0; mi < 4; mi++) {
                    mma16816(acc[mi][ni], ahi[mi], bh);
                    mma16816(acc[mi][ni], alo[mi], bh);
                    mma16816(acc[mi][ni], ahi[mi], bl);
                }
            }
        }
        __syncthreads();
    }

#pragma unroll
    for (int mi = 0; mi < 4; mi++) {
        int r0 = rowBase + wm * 64 + mi * 16 + g;
        int r1 = r0 + 8;
#pragma unroll
        for (int ni = 0; ni < 4; ni++) {
            int col = colBase + wn * 32 + ni * 8 + tig * 2;
            float2 v0 = make_float2(acc[mi][ni][0], acc[mi][ni][1]);
            float2 v1 = make_float2(acc[mi][ni][2], acc[mi][ni][3]);
            if (MODE == 2 || MODE == 3) {
                float2 bv = *(const float2*)(bias + col);
                v0.x += bv.x; v0.y += bv.y;
                v1.x += bv.x; v1.y += bv.y;
            }
            if (MODE == 0) {
                __nv_bfloat16 h0, l0, h1, l1;
                bsplit(v0.x, h0, l0); bsplit(v0.y, h1, l1);
                *(__nv_bfloat162*)(Csp + (size_t)r0 * 5120 + col)        = __nv_bfloat162(h0, h1);
                *(__nv_bfloat162*)(Csp + (size_t)r0 * 5120 + 2560 + col) = __nv_bfloat162(l0, l1);
                bsplit(v1.x, h0, l0); bsplit(v1.y, h1, l1);
                *(__nv_bfloat162*)(Csp + (size_t)r1 * 5120 + col)        = __nv_bfloat162(h0, h1);
                *(__nv_bfloat162*)(Csp + (size_t)r1 * 5120 + 2560 + col) = __nv_bfloat162(l0, l1);
            } else if (MODE == 2) {
                v0.x = fmaxf(v0.x, 0.f); v0.y = fmaxf(v0.y, 0.f);
                v1.x = fmaxf(v1.x, 0.f); v1.y = fmaxf(v1.y, 0.f);
                __nv_bfloat16 h0, l0, h1, l1;
                bsplit(v0.x, h0, l0); bsplit(v0.y, h1, l1);
                *(__nv_bfloat162*)(Csp + (size_t)r0 * 512 + col)       = __nv_bfloat162(h0, h1);
                *(__nv_bfloat162*)(Csp + (size_t)r0 * 512 + 256 + col) = __nv_bfloat162(l0, l1);
                bsplit(v1.x, h0, l0); bsplit(v1.y, h1, l1);
                *(__nv_bfloat162*)(Csp + (size_t)r1 * 512 + col)       = __nv_bfloat162(h0, h1);
                *(__nv_bfloat162*)(Csp + (size_t)r1 * 512 + 256 + col) = __nv_bfloat162(l0, l1);
            } else {
                float2 e0 = *(const float2*)(res + (size_t)r0 * ldC + col);
                float2 e1 = *(const float2*)(res + (size_t)r1 * ldC + col);
                v0.x += e0.x; v0.y += e0.y;
                v1.x += e1.x; v1.y += e1.y;
                *(float2*)(C + (size_t)r0 * ldC + col) = v0;
                *(float2*)(C + (size_t)r1 * ldC + col) = v1;
            }
        }
    }
}

// ================= tensor-core attention =================
// One CTA per (b, fix) x mode: loads K,V once, loops 4 heads.
// S = Q K^T (3-term split mma), in-register softmax, O = P V (3-term split mma).
#define TP 264                      // Q/K/V smem pitch (bf16)
#define PP 72                       // P smem pitch
#define TILE_E (64 * TP)
#define ATTN_SMEM_B ((6 * TILE_E + 2 * 64 * PP) * 2 + 256 * 4)

__global__ __launch_bounds__(256)
void attn_mma_kernel() {
    extern __shared__ __nv_bfloat16 asm_[];
    __nv_bfloat16* Qh = asm_;
    __nv_bfloat16* Ql = Qh + TILE_E;
    __nv_bfloat16* Kh = Ql + TILE_E;
    __nv_bfloat16* Kl = Kh + TILE_E;
    __nv_bfloat16* Vh = Kl + TILE_E;
    __nv_bfloat16* Vl = Vh + TILE_E;
    __nv_bfloat16* Ph = Vl + TILE_E;
    __nv_bfloat16* Pl = Ph + 64 * PP;
    float* stmax = (float*)(Pl + 64 * PP);   // [64][2]
    float* stsum = stmax + 128;              // [64][2]
    uint32_t sbase = (uint32_t)__cvta_generic_to_shared(asm_);

    int tid = threadIdx.x;
    int lane = tid & 31, warp = tid >> 5;
    int g = lane >> 2, tig = lane & 3;

    int u = blockIdx.x;                     // 1024
    bool gridmode = (u < 512);
    int b, fix;
    if (gridmode) { b = u >> 6; fix = u & 63; }
    else          { int u2 = u - 512; b = u2 >> 6; fix = u2 & 63; }
    size_t base; int stride;
    if (gridmode) { base = (size_t)b * 4096 + fix; stride = 64; }
    else          { base = (size_t)b * 4096 + (size_t)fix * 64; stride = 1; }
    int head0 = gridmode ? 0 : 4;

    // piece loader: 64 rows x 256 cols, hi+lo planes
    auto load_piece = [&](const __nv_bfloat16* dh, const __nv_bfloat16* dl, int colOff) {
        uint32_t sh = sbase + (uint32_t)((const char*)dh - (const char*)asm_);
        uint32_t sl = sbase + (uint32_t)((const char*)dl - (const char*)asm_);
#pragma unroll
        for (int i = 0; i < 8; i++) {
            int f = i * 256 + tid;
            int r = f >> 5, q = f & 31;
            size_t token = base + (size_t)r * stride;
            const __nv_bfloat16* ga = g_qkvsp + token * 5120 + colOff + q * 8;
            uint32_t so = (uint32_t)(r * TP + q * 8) * 2;
            cpasync16(sh + so, ga);
            cpasync16(sl + so, ga + 2560);
        }
    };

    load_piece(Kh, Kl, 2048);
    load_piece(Vh, Vl, 2304);
    load_piece(Qh, Ql, head0 * 256);
    asm volatile("cp.async.commit_group;\n");
    asm volatile("cp.async.wait_group 0;\n");
    __syncthreads();

    int warpm = warp >> 1, warpn = warp & 1;    // S: 4 x 2 ; O: same split
    int row0 = warpm * 16 + g, row1 = row0 + 8;

    for (int hl = 0; hl < 4; hl++) {
        int head = head0 + hl;

        // ---------- S = Q K^T ----------
        float c[4][4] = {};
#pragma unroll 4
        for (int ks = 0; ks < 16; ks++) {
            int kb = ks * 16;
            uint32_t ahi[4], alo[4];
            const __nv_bfloat16* qh = Qh + row0 * TP + kb + 2 * tig;
            const __nv_bfloat16* ql = Ql + row0 * TP + kb + 2 * tig;
            ahi[0] = *(const uint32_t*)(qh);
            ahi[1] = *(const uint32_t*)(qh + 8 * TP);
            ahi[2] = *(const uint32_t*)(qh + 8);
            ahi[3] = *(const uint32_t*)(qh + 8 * TP + 8);
            alo[0] = *(const uint32_t*)(ql);
            alo[1] = *(const uint32_t*)(ql + 8 * TP);
            alo[2] = *(const uint32_t*)(ql + 8);
            alo[3] = *(const uint32_t*)(ql + 8 * TP + 8);
#pragma unroll
            for (int ni = 0; ni < 4; ni++) {
                int n = warpn * 32 + ni * 8 + g;
                const __nv_bfloat16* kh = Kh + n * TP + kb + 2 * tig;
                const __nv_bfloat16* kl = Kl + n * TP + kb + 2 * tig;
                uint32_t bh[2], bl[2];
                bh[0] = *(const uint32_t*)(kh);
                bh[1] = *(const uint32_t*)(kh + 8);
                bl[0] = *(const uint32_t*)(kl);
                bl[1] = *(const uint32_t*)(kl + 8);
                mma16816(c[ni], ahi, bh);
                mma16816(c[ni], alo, bh);
                mma16816(c[ni], ahi, bl);
            }
        }

        // ---------- softmax (in-register, cross-warp via stats) ----------
        float m0 = -1e30f, m1 = -1e30f;
#pragma unroll
        for (int ni = 0; ni < 4; ni++) {
            m0 = fmaxf(m0, fmaxf(c[ni][0], c[ni][1]));
            m1 = fmaxf(m1, fmaxf(c[ni][2], c[ni][3]));
        }
        m0 = fmaxf(m0, __shfl_xor_sync(0xffffffffu, m0, 1));
        m0 = fmaxf(m0, __shfl_xor_sync(0xffffffffu, m0, 2));
        m1 = fmaxf(m1, __shfl_xor_sync(0xffffffffu, m1, 1));
        m1 = fmaxf(m1, __shfl_xor_sync(0xffffffffu, m1, 2));
        if (tig == 0) {
            stmax[row0 * 2 + warpn] = m0;
            stmax[row1 * 2 + warpn] = m1;
        }
        __syncthreads();
        m0 = fmaxf(stmax[row0 * 2], stmax[row0 * 2 + 1]);
        m1 = fmaxf(stmax[row1 * 2], stmax[row1 * 2 + 1]);
        float s0 = 0.f, s1 = 0.f;
#pragma unroll
        for (int ni = 0; ni < 4; ni++) {
            c[ni][0] = __expf(c[ni][0] - m0);
            c[ni][1] = __expf(c[ni][1] - m0);
            c[ni][2] = __expf(c[ni][2] - m1);
            c[ni][3] = __expf(c[ni][3] - m1);
            s0 += c[ni][0] + c[ni][1];
            s1 += c[ni][2] + c[ni][3];
        }
        s0 += __shfl_xor_sync(0xffffffffu, s0, 1);
        s0 += __shfl_xor_sync(0xffffffffu, s0, 2);
        s1 += __shfl_xor_sync(0xffffffffu, s1, 1);
        s1 += __shfl_xor_sync(0xffffffffu, s1, 2);
        if (tig == 0) {
            stsum[row0 * 2 + warpn] = s0;
            stsum[row1 * 2 + warpn] = s1;
        }
        __syncthreads();
        float inv0 = 1.0f / (stsum[row0 * 2] + stsum[row0 * 2 + 1]);
        float inv1 = 1.0f / (stsum[row1 * 2] + stsum[row1 * 2 + 1]);
#pragma unroll
        for (int ni = 0; ni < 4; ni++) {
            int cn = warpn * 32 + ni * 8 + 2 * tig;
            __nv_bfloat16 h0, l0, h1, l1;
            bsplit(c[ni][0] * inv0, h0, l0); bsplit(c[ni][1] * inv0, h1, l1);
            *(__nv_bfloat162*)(Ph + row0 * PP + cn) = __nv_bfloat162(h0, h1);
            *(__nv_bfloat162*)(Pl + row0 * PP + cn) = __nv_bfloat162(l0, l1);
            bsplit(c[ni][2] * inv1, h0, l0); bsplit(c[ni][3] * inv1, h1, l1);
            *(__nv_bfloat162*)(Ph + row1 * PP + cn) = __nv_bfloat162(h0, h1);
            *(__nv_bfloat162*)(Pl + row1 * PP + cn) = __nv_bfloat162(l0, l1);
        }
        __syncthreads();   // P visible; Q buffer free

        if (hl < 3) {      // prefetch next head's Q during O-phase
            load_piece(Qh, Ql, (head + 1) * 256);
            asm volatile("cp.async.commit_group;\n");
        }

        // ---------- O = P V ----------
        float o[16][4] = {};
#pragma unroll
        for (int ks = 0; ks < 4; ks++) {
            int kb = ks * 16;
            uint32_t ph[4], pl[4];
            const __nv_bfloat16* pph = Ph + row0 * PP + kb + 2 * tig;
            const __nv_bfloat16* ppl = Pl + row0 * PP + kb + 2 * tig;
            ph[0] = *(const uint32_t*)(pph);
            ph[1] = *(const uint32_t*)(pph + 8 * PP);
            ph[2] = *(const uint32_t*)(pph + 8);
            ph[3] = *(const uint32_t*)(pph + 8 * PP + 8);
            pl[0] = *(const uint32_t*)(ppl);
            pl[1] = *(const uint32_t*)(ppl + 8 * PP);
            pl[2] = *(const uint32_t*)(ppl + 8);
            pl[3] = *(const uint32_t*)(ppl + 8 * PP + 8);
            int z0 = kb + 2 * tig;
#pragma unroll
            for (int ni = 0; ni < 16; ni++) {
                int v = warpn * 128 + ni * 8 + g;
                uint32_t bh[2], bl[2];
                bh[0] = pack2(Vh + z0 * TP + v,       Vh + (z0 + 1) * TP + v);
                bh[1] = pack2(Vh + (z0 + 8) * TP + v, Vh + (z0 + 9) * TP + v);
                bl[0] = pack2(Vl + z0 * TP + v,       Vl + (z0 + 1) * TP + v);
                bl[1] = pack2(Vl + (z0 + 8) * TP + v, Vl + (z0 + 9) * TP + v);
                mma16816(o[ni], ph, bh);
                mma16816(o[ni], pl, bh);
                mma16816(o[ni], ph, bl);
            }
        }

        // store O (fp32)
        size_t tok0 = base + (size_t)row0 * stride;
        size_t tok1 = base + (size_t)row1 * stride;
#pragma unroll
        for (int ni = 0; ni < 16; ni++) {
            int col = head * 256 + warpn * 128 + ni * 8 + 2 * tig;
            *(float2*)(g_attno + tok0 * OC + col) = make_float2(o[ni][0], o[ni][1]);
            *(float2*)(g_attno + tok1 * OC + col) = make_float2(o[ni][2], o[ni][3]);
        }

        if (hl < 3) asm volatile("cp.async.wait_group 0;\n");
        __syncthreads();
    }
}

// ---------- head-mix + unpermute + residual + LN2 -> split bf16 ----------
__global__ void zred_ln2_kernel(const float* __restrict__ x,
                                const float* __restrict__ gamma,
                                const float* __restrict__ beta,
                                float* __restrict__ x2) {
    int gw   = (blockIdx.x * blockDim.x + threadIdx.x) >> 5;
    int lane = threadIdx.x & 31;

    int b = gw >> 12, m = (gw >> 6) & 63, n = gw & 63;
    int hh = ((n >> 3) << 3) | (m >> 3);
    int ww = ((n & 7) << 3) | (m & 7);
    size_t orow = ((size_t)b << 12) | (unsigned)((hh << 6) | ww);

    const float* arow = g_attno + (size_t)gw * OC;
    float4 acc0 = make_float4(0.f, 0.f, 0.f, 0.f);
    float4 acc1 = make_float4(0.f, 0.f, 0.f, 0.f);
#pragma unroll
    for (int h = 0; h < 8; h++) {
        float4 a0 = ((const float4*)(arow + h * 256))[lane];
        float4 a1 = ((const float4*)(arow + h * 256))[lane + 32];
        float4 s0 = ((const float4*)(g_so + h * 256))[lane];
        float4 s1 = ((const float4*)(g_so + h * 256))[lane + 32];
        acc0.x += a0.x * s0.x; acc0.y += a0.y * s0.y;
        acc0.z += a0.z * s0.z; acc0.w += a0.w * s0.w;
        acc1.x += a1.x * s1.x; acc1.y += a1.y * s1.y;
        acc1.z += a1.z * s1.z; acc1.w += a1.w * s1.w;
    }
    const float* xr = x + orow * DD;
    float4 x0 = ((const float4*)xr)[lane];
    float4 x1 = ((const float4*)xr)[lane + 32];
    float4 v0 = make_float4(x0.x + acc0.x, x0.y + acc0.y, x0.z + acc0.z, x0.w + acc0.w);
    float4 v1 = make_float4(x1.x + acc1.x, x1.y + acc1.y, x1.z + acc1.z, x1.w + acc1.w);

    ((float4*)(x2 + orow * DD))[lane]      = v0;
    ((float4*)(x2 + orow * DD))[lane + 32] = v1;

    float s  = v0.x + v0.y + v0.z + v0.w + v1.x + v1.y + v1.z + v1.w;
    float sq = v0.x*v0.x + v0.y*v0.y + v0.z*v0.z + v0.w*v0.w
             + v1.x*v1.x + v1.y*v1.y + v1.z*v1.z + v1.w*v1.w;
#pragma unroll
    for (int o = 16; o > 0; o >>= 1) {
        s  += __shfl_xor_sync(0xffffffffu, s,  o);
        sq += __shfl_xor_sync(0xffffffffu, sq, o);
    }
    float mean = s * (1.0f / 256.0f);
    float var  = sq * (1.0f / 256.0f) - mean * mean;
    float rstd = rsqrtf(var + 1e-5f);

    float4 g0 = ((const float4*)gamma)[lane];
    float4 g1 = ((const float4*)gamma)[lane + 32];
    float4 bb0 = ((const float4*)beta)[lane];
    float4 bb1 = ((const float4*)beta)[lane + 32];
    float4 o0, o1;
    o0.x = (v0.x - mean) * rstd * g0.x + bb0.x;
    o0.y = (v0.y - mean) * rstd * g0.y + bb0.y;
    o0.z = (v0.z - mean) * rstd * g0.z + bb0.z;
    o0.w = (v0.w - mean) * rstd * g0.w + bb0.w;
    o1.x = (v1.x - mean) * rstd * g1.x + bb1.x;
    o1.y = (v1.y - mean) * rstd * g1.y + bb1.y;
    o1.z = (v1.z - mean) * rstd * g1.z + bb1.z;
    o1.w = (v1.w - mean) * rstd * g1.w + bb1.w;
    store_split8(g_ln2sp + orow * 512, lane * 4, o0, o1);
}

// ---------------- launch ----------------
extern "C" void kernel_launch(void* const* d_in, const int* in_sizes, int n_in,
                              void* d_out, int out_size) {
    const float* x    = (const float*)d_in[0];
    const float* ln1w = (const float*)d_in[1];
    const float* ln1b = (const float*)d_in[2];
    const float* qw   = (const float*)d_in[3];
    const float* kw   = (const float*)d_in[4];
    const float* vw   = (const float*)d_in[5];
    const float* ow   = (const float*)d_in[6];
    const float* ln2w = (const float*)d_in[7];
    const float* ln2b = (const float*)d_in[8];
    const float* w1   = (const float*)d_in[9];
    const float* b1   = (const float*)d_in[10];
    const float* w2   = (const float*)d_in[11];
    const float* b2   = (const float*)d_in[12];
    float* out = (float*)d_out;

    __nv_bfloat16 *p_asp, *p_wsp, *p_w1sp, *p_w2sp, *p_ln2sp, *p_m1sp, *p_qkvsp;
    float *p_x2;
    cudaGetSymbolAddress((void**)&p_asp,   g_asp);
    cudaGetSymbolAddress((void**)&p_wsp,   g_wsp);
    cudaGetSymbolAddress((void**)&p_w1sp,  g_w1sp);
    cudaGetSymbolAddress((void**)&p_w2sp,  g_w2sp);
    cudaGetSymbolAddress((void**)&p_ln2sp, g_ln2sp);
    cudaGetSymbolAddress((void**)&p_m1sp,  g_m1sp);
    cudaGetSymbolAddress((void**)&p_qkvsp, g_qkvsp);
    cudaGetSymbolAddress((void**)&p_x2,    g_x2);

    cudaFuncSetAttribute(attn_mma_kernel, cudaFuncAttributeMaxDynamicSharedMemorySize,
                         ATTN_SMEM_B);
    cudaFuncSetAttribute(bfmma_gemm_kernel<0>, cudaFuncAttributeMaxDynamicSharedMemorySize, GSMEM);
    cudaFuncSetAttribute(bfmma_gemm_kernel<2>, cudaFuncAttributeMaxDynamicSharedMemorySize, GSMEM);
    cudaFuncSetAttribute(bfmma_gemm_kernel<3>, cudaFuncAttributeMaxDynamicSharedMemorySize, GSMEM);

    // 1. weight prep
    prep_wqkv_kernel<<<QKVC, 256>>>(qw, kw, vw);
    prep_wt_kernel<<<256, 256>>>(w1, p_w1sp);
    prep_wt_kernel<<<256, 256>>>(w2, p_w2sp);
    prep_so_kernel<<<256, 256>>>(ow);
    // 2. LN1 + block permute -> split
    ln1_kernel<<<NTOK / 8, 256>>>(x, ln1w, ln1b);
    // 3. QKV projection -> split bf16
    bfmma_gemm_kernel<0><<<dim3(QKVC / 128, NTOK / 128), 256, GSMEM>>>(
        p_asp, p_wsp, nullptr, p_qkvsp, nullptr, nullptr, QKVC);
    // 4. tensor-core attention (K/V shared across 4 heads per CTA)
    attn_mma_kernel<<<1024, 256, ATTN_SMEM_B>>>();
    // 5. head-mix + unpermute + residual + LN2 -> split
    zred_ln2_kernel<<<NTOK / 8, 256>>>(x, ln2w, ln2b, p_x2);
    // 6. MLP fc1 + ReLU -> split
    bfmma_gemm_kernel<2><<<dim3(DD / 128, NTOK / 128), 256, GSMEM>>>(
        p_ln2sp, p_w1sp, nullptr, p_m1sp, b1, nullptr, DD);
    // 7. MLP fc2 + bias + residual -> out
    bfmma_gemm_kernel<3><<<dim3(DD / 128, NTOK / 128), 256, GSMEM>>>(
        p_m1sp, p_w2sp, out, nullptr, b2, p_x2, DD);
}

// round 8
// speedup vs baseline: 2.3309x; 1.0544x over previous
#include <cuda_runtime.h>
#include <cuda_bf16.h>
#include <cstdint>
#include <cstddef>

// ---------------- problem constants ----------------
#define NTOK     32768
#define DD       256
#define QKVC     2560

// ---------------- static scratch ----------------
__device__ __nv_bfloat16 g_asp  [(size_t)NTOK * 512];    // LN1 out, blocked, [row][hi256|lo256]
__device__ __nv_bfloat16 g_wsp  [(size_t)QKVC * 512];    // qkv weights [j][hi|lo] over d
__device__ __nv_bfloat16 g_w1sp [(size_t)DD * 512];
__device__ __nv_bfloat16 g_w2sp [(size_t)DD * 512];
__device__ __nv_bfloat16 g_ln2sp[(size_t)NTOK * 512];
__device__ __nv_bfloat16 g_m1sp [(size_t)NTOK * 512];
__device__ __nv_bfloat16 g_qkvsp[(size_t)NTOK * 5120];   // QKV out split: [tok][hi2560|lo2560]
__device__ float g_z1  [(size_t)NTOK * DD];              // grid-mode partial Z (so-weighted)
__device__ float g_z2  [(size_t)NTOK * DD];              // block-mode partial Z
__device__ float g_so  [2048];
__device__ float g_x2  [(size_t)NTOK * DD];

// ---------------- helpers ----------------
__device__ __forceinline__ void bsplit(float v, __nv_bfloat16& h, __nv_bfloat16& l) {
    h = __float2bfloat16_rn(v);
    l = __float2bfloat16_rn(v - __bfloat162float(h));
}
__device__ __forceinline__ void cpasync16(uint32_t s, const void* g) {
    asm volatile("cp.async.cg.shared.global [%0], [%1], 16;\n" :: "r"(s), "l"(g));
}
__device__ __forceinline__ void mma16816(float* c, const uint32_t* a, const uint32_t* b) {
    asm volatile(
        "mma.sync.aligned.m16n8k16.row.col.f32.bf16.bf16.f32 "
        "{%0,%1,%2,%3},{%4,%5,%6,%7},{%8,%9},{%0,%1,%2,%3};\n"
        : "+f"(c[0]), "+f"(c[1]), "+f"(c[2]), "+f"(c[3])
        : "r"(a[0]), "r"(a[1]), "r"(a[2]), "r"(a[3]), "r"(b[0]), "r"(b[1]));
}
__device__ __forceinline__ void ldsm_x4(uint32_t* r, uint32_t a) {
    asm volatile("ldmatrix.sync.aligned.m8n8.x4.shared.b16 {%0,%1,%2,%3}, [%4];"
        : "=r"(r[0]), "=r"(r[1]), "=r"(r[2]), "=r"(r[3]) : "r"(a));
}
__device__ __forceinline__ void ldsm_x2(uint32_t* r, uint32_t a) {
    asm volatile("ldmatrix.sync.aligned.m8n8.x2.shared.b16 {%0,%1}, [%2];"
        : "=r"(r[0]), "=r"(r[1]) : "r"(a));
}
__device__ __forceinline__ void ldsm_x2t(uint32_t* r, uint32_t a) {
    asm volatile("ldmatrix.sync.aligned.m8n8.x2.trans.shared.b16 {%0,%1}, [%2];"
        : "=r"(r[0]), "=r"(r[1]) : "r"(a));
}

// ---------------- weight prep ----------------
__global__ void prep_wqkv_kernel(const float* __restrict__ q,
                                 const float* __restrict__ k,
                                 const float* __restrict__ v) {
    int idx = blockIdx.x * 256 + threadIdx.x;
    int d = idx & 255, j = idx >> 8;
    float val;
    if (j < 2048) { int h = j >> 8, kk = j & 255; val = q[((size_t)(h * 256 + d)) * 256 + kk]; }
    else if (j < 2304) val = k[(size_t)d * 256 + (j - 2048)];
    else               val = v[(size_t)d * 256 + (j - 2304)];
    __nv_bfloat16 h16, l16; bsplit(val, h16, l16);
    g_wsp[(size_t)j * 512 + d]       = h16;
    g_wsp[(size_t)j * 512 + 256 + d] = l16;
}

__global__ void prep_wt_kernel(const float* __restrict__ src, __nv_bfloat16* __restrict__ dst) {
    int idx = blockIdx.x * 256 + threadIdx.x;
    int d = idx & 255, j = idx >> 8;
    float val = src[(size_t)d * 256 + j];
    __nv_bfloat16 h16, l16; bsplit(val, h16, l16);
    dst[(size_t)j * 512 + d]       = h16;
    dst[(size_t)j * 512 + 256 + d] = l16;
}

__global__ void prep_so_kernel(const float* __restrict__ o) {
    int row  = (blockIdx.x * blockDim.x + threadIdx.x) >> 5;
    int lane = threadIdx.x & 31;
    const float* rp = o + (size_t)row * 256;
    float4 a = ((const float4*)rp)[lane];
    float4 b = ((const float4*)rp)[lane + 32];
    float s = a.x + a.y + a.z + a.w + b.x + b.y + b.z + b.w;
#pragma unroll
    for (int off = 16; off > 0; off >>= 1) s += __shfl_xor_sync(0xffffffffu, s, off);
    if (lane == 0) g_so[row] = s;
}

// ---------------- LN1 + block permute -> split bf16 ----------------
__device__ __forceinline__ void store_split8(__nv_bfloat16* rowp, int col,
                                             float4 v0, float4 v1) {
    __nv_bfloat16 h[8], l[8];
    bsplit(v0.x, h[0], l[0]); bsplit(v0.y, h[1], l[1]);
    bsplit(v0.z, h[2], l[2]); bsplit(v0.w, h[3], l[3]);
    bsplit(v1.x, h[4], l[4]); bsplit(v1.y, h[5], l[5]);
    bsplit(v1.z, h[6], l[6]); bsplit(v1.w, h[7], l[7]);
#pragma unroll
    for (int i = 0; i < 4; i++) {
        rowp[col + i]             = h[i];
        rowp[col + 128 + i]       = h[4 + i];
        rowp[256 + col + i]       = l[i];
        rowp[256 + col + 128 + i] = l[4 + i];
    }
}

__global__ void ln1_kernel(const float* __restrict__ in,
                           const float* __restrict__ gamma,
                           const float* __restrict__ beta) {
    int gwarp = (blockIdx.x * blockDim.x + threadIdx.x) >> 5;
    int lane  = threadIdx.x & 31;
    const float* row = in + (size_t)gwarp * DD;
    float4 v0 = ((const float4*)row)[lane];
    float4 v1 = ((const float4*)row)[lane + 32];
    float s  = v0.x + v0.y + v0.z + v0.w + v1.x + v1.y + v1.z + v1.w;
    float sq = v0.x*v0.x + v0.y*v0.y + v0.z*v0.z + v0.w*v0.w
             + v1.x*v1.x + v1.y*v1.y + v1.z*v1.z + v1.w*v1.w;
#pragma unroll
    for (int o = 16; o > 0; o >>= 1) {
        s  += __shfl_xor_sync(0xffffffffu, s,  o);
        sq += __shfl_xor_sync(0xffffffffu, sq, o);
    }
    float mean = s * (1.0f / 256.0f);
    float var  = sq * (1.0f / 256.0f) - mean * mean;
    float rstd = rsqrtf(var + 1e-5f);

    int b = gwarp >> 12, pos = gwarp & 4095;
    int h = pos >> 6, w = pos & 63;
    int m = ((h & 7) << 3) | (w & 7);
    int n = ((h >> 3) << 3) | (w >> 3);
    size_t orow = ((size_t)b << 12) | (unsigned)((m << 6) | n);

    float4 g0 = ((const float4*)gamma)[lane];
    float4 g1 = ((const float4*)gamma)[lane + 32];
    float4 b0 = ((const float4*)beta)[lane];
    float4 b1 = ((const float4*)beta)[lane + 32];
    float4 o0, o1;
    o0.x = (v0.x - mean) * rstd * g0.x + b0.x;
    o0.y = (v0.y - mean) * rstd * g0.y + b0.y;
    o0.z = (v0.z - mean) * rstd * g0.z + b0.z;
    o0.w = (v0.w - mean) * rstd * g0.w + b0.w;
    o1.x = (v1.x - mean) * rstd * g1.x + b1.x;
    o1.y = (v1.y - mean) * rstd * g1.y + b1.y;
    o1.z = (v1.z - mean) * rstd * g1.z + b1.z;
    o1.w = (v1.w - mean) * rstd * g1.w + b1.w;
    store_split8(g_asp + orow * 512, lane * 4, o0, o1);
}

// ================= bf16 mma GEMM, 3-term split, ldmatrix =================
#define GP 40
#define MATB (128 * GP * 2)            // 10240 B
#define STAGEB (4 * MATB)
#define GSMEM (2 * STAGEB)

template <int MODE>
__global__ __launch_bounds__(256, 2)
void bfmma_gemm_kernel(const __nv_bfloat16* __restrict__ Asp,
                       const __nv_bfloat16* __restrict__ Bsp,
                       float* __restrict__ C,
                       __nv_bfloat16* __restrict__ Csp,
                       const float* __restrict__ bias,
                       const float* __restrict__ res,
                       int ldC) {
    extern __shared__ __nv_bfloat16 smem[];
    uint32_t sb = (uint32_t)__cvta_generic_to_shared(smem);

    int tid = threadIdx.x;
    int lane = tid & 31, warp = tid >> 5;
    int wm = warp & 1, wn = warp >> 1;
    int g = lane >> 2, tig = lane & 3;
    int lrow8 = lane & 7;
    int l8 = (lane >> 3) & 1;
    int l16 = (lane >> 4) & 1;
    int rowBase = blockIdx.y * 128;
    int colBase = blockIdx.x * 128;

    uint32_t aoff = (uint32_t)(((wm * 64 + lrow8 + 8 * l8) * GP + 8 * l16) * 2);
    uint32_t boff = (uint32_t)(((wn * 32 + lrow8) * GP + 8 * l8) * 2);

    float acc[4][4][4] = {};

    auto load_chunk = [&](int c, int st) {
        const __nv_bfloat16* Ag = Asp + (size_t)rowBase * 512 + c * 32;
        const __nv_bfloat16* Bg = Bsp + (size_t)colBase * 512 + c * 32;
        uint32_t base = sb + (uint32_t)st * STAGEB;
#pragma unroll
        for (int i = 0; i < 2; i++) {
            int f = tid + i * 256;
            int r = f >> 2, q = f & 3;
            uint32_t so = (uint32_t)(r * GP + q * 8) * 2;
            const __nv_bfloat16* ga = Ag + (size_t)r * 512 + q * 8;
            const __nv_bfloat16* gb = Bg + (size_t)r * 512 + q * 8;
            cpasync16(base + so,            ga);
            cpasync16(base + MATB + so,     ga + 256);
            cpasync16(base + 2 * MATB + so, gb);
            cpasync16(base + 3 * MATB + so, gb + 256);
        }
        asm volatile("cp.async.commit_group;\n");
    };

    load_chunk(0, 0);

    const int NCH = 8;
    for (int c = 0; c < NCH; c++) {
        if (c + 1 < NCH) {
            load_chunk(c + 1, (c + 1) & 1);
            asm volatile("cp.async.wait_group 1;\n");
        } else {
            asm volatile("cp.async.wait_group 0;\n");
        }
        __syncthreads();

        uint32_t stb = sb + (uint32_t)(c & 1) * STAGEB;

#pragma unroll
        for (int ks = 0; ks < 2; ks++) {
            uint32_t kb2 = ks * 32;
            uint32_t ahi[4][4], alo[4][4];
#pragma unroll
            for (int mi = 0; mi < 4; mi++) {
                uint32_t a = stb + aoff + mi * (16 * GP * 2) + kb2;
                ldsm_x4(ahi[mi], a);
                ldsm_x4(alo[mi], a + MATB);
            }
#pragma unroll
            for (int ni = 0; ni < 4; ni++) {
                uint32_t ba = stb + 2 * MATB + boff + ni * (8 * GP * 2) + kb2;
                uint32_t bh[2], bl[2];
                ldsm_x2(bh, ba);
                ldsm_x2(bl, ba + MATB);
#pragma unroll
                for (int mi = 0; mi < 4; mi++) {
                    mma16816(acc[mi][ni], ahi[mi], bh);
                    mma16816(acc[mi][ni], alo[mi], bh);
                    mma16816(acc[mi][ni], ahi[mi], bl);
                }
            }
        }
        __syncthreads();
    }

#pragma unroll
    for (int mi = 0; mi < 4; mi++) {
        int r0 = rowBase + wm * 64 + mi * 16 + g;
        int r1 = r0 + 8;
#pragma unroll
        for (int ni = 0; ni < 4; ni++) {
            int col = colBase + wn * 32 + ni * 8 + tig * 2;
            float2 v0 = make_float2(acc[mi][ni][0], acc[mi][ni][1]);
            float2 v1 = make_float2(acc[mi][ni][2], acc[mi][ni][3]);
            if (MODE == 2 || MODE == 3) {
                float2 bv = *(const float2*)(bias + col);
                v0.x += bv.x; v0.y += bv.y;
                v1.x += bv.x; v1.y += bv.y;
            }
            if (MODE == 0) {
                __nv_bfloat16 h0, l0, h1, l1;
                bsplit(v0.x, h0, l0); bsplit(v0.y, h1, l1);
                *(__nv_bfloat162*)(Csp + (size_t)r0 * 5120 + col)        = __nv_bfloat162(h0, h1);
                *(__nv_bfloat162*)(Csp + (size_t)r0 * 5120 + 2560 + col) = __nv_bfloat162(l0, l1);
                bsplit(v1.x, h0, l0); bsplit(v1.y, h1, l1);
                *(__nv_bfloat162*)(Csp + (size_t)r1 * 5120 + col)        = __nv_bfloat162(h0, h1);
                *(__nv_bfloat162*)(Csp + (size_t)r1 * 5120 + 2560 + col) = __nv_bfloat162(l0, l1);
            } else if (MODE == 2) {
                v0.x = fmaxf(v0.x, 0.f); v0.y = fmaxf(v0.y, 0.f);
                v1.x = fmaxf(v1.x, 0.f); v1.y = fmaxf(v1.y, 0.f);
                __nv_bfloat16 h0, l0, h1, l1;
                bsplit(v0.x, h0, l0); bsplit(v0.y, h1, l1);
                *(__nv_bfloat162*)(Csp + (size_t)r0 * 512 + col)       = __nv_bfloat162(h0, h1);
                *(__nv_bfloat162*)(Csp + (size_t)r0 * 512 + 256 + col) = __nv_bfloat162(l0, l1);
                bsplit(v1.x, h0, l0); bsplit(v1.y, h1, l1);
                *(__nv_bfloat162*)(Csp + (size_t)r1 * 512 + col)       = __nv_bfloat162(h0, h1);
                *(__nv_bfloat162*)(Csp + (size_t)r1 * 512 + 256 + col) = __nv_bfloat162(l0, l1);
            } else {
                float2 e0 = *(const float2*)(res + (size_t)r0 * ldC + col);
                float2 e1 = *(const float2*)(res + (size_t)r1 * ldC + col);
                v0.x += e0.x; v0.y += e0.y;
                v1.x += e1.x; v1.y += e1.y;
                *(float2*)(C + (size_t)r0 * ldC + col) = v0;
                *(float2*)(C + (size_t)r1 * ldC + col) = v1;
            }
        }
    }
}

// ================= tensor-core attention + fused head-mix =================
// One CTA per (b, fix) x mode; K,V loaded once, 4 heads looped.
// Emits so-weighted partial Z (64x256 fp32) instead of raw O (4x64x256).
#define TP 264
#define PP 72
#define TILE_E (64 * TP)
#define TEB (TILE_E * 2)           // bytes per plane: 33792
#define PPB (64 * PP * 2)          // 9216
#define ATTN_SMEM_B (6 * TEB + 2 * PPB + 1024)

__global__ __launch_bounds__(256)
void attn_mma_kernel() {
    extern __shared__ __nv_bfloat16 asm_[];
    __nv_bfloat16* Ph = asm_ + 6 * TILE_E;
    __nv_bfloat16* Pl = Ph + 64 * PP;
    float* stmax = (float*)(Pl + 64 * PP);
    float* stsum = stmax + 128;
    uint32_t sbase = (uint32_t)__cvta_generic_to_shared(asm_);

    int tid = threadIdx.x;
    int lane = tid & 31, warp = tid >> 5;
    int g = lane >> 2, tig = lane & 3;
    int lrow8 = lane & 7;
    int l8 = (lane >> 3) & 1;
    int l16 = (lane >> 4) & 1;

    int u = blockIdx.x;
    bool gridmode = (u < 512);
    int b, fix;
    if (gridmode) { b = u >> 6; fix = u & 63; }
    else          { int u2 = u - 512; b = u2 >> 6; fix = u2 & 63; }
    size_t base; int stride;
    if (gridmode) { base = (size_t)b * 4096 + fix; stride = 64; }
    else          { base = (size_t)b * 4096 + (size_t)fix * 64; stride = 1; }
    int head0 = gridmode ? 0 : 4;

    // plane bases (bytes): Q=0, Qlo=TEB, K=2TEB, Klo=3TEB, V=4TEB, Vlo=5TEB
    auto load_piece = [&](int planeIdx, int colOff) {
        uint32_t sh = sbase + (uint32_t)planeIdx * TEB;
#pragma unroll
        for (int i = 0; i < 8; i++) {
            int f = i * 256 + tid;
            int r = f >> 5, q = f & 31;
            size_t token = base + (size_t)r * stride;
            const __nv_bfloat16* ga = g_qkvsp + token * 5120 + colOff + q * 8;
            uint32_t so = (uint32_t)(r * TP + q * 8) * 2;
            cpasync16(sh + so, ga);
            cpasync16(sh + TEB + so, ga + 2560);
        }
    };

    load_piece(2, 2048);        // K hi/lo
    load_piece(4, 2304);        // V hi/lo
    load_piece(0, head0 * 256); // Q hi/lo
    asm volatile("cp.async.commit_group;\n");
    asm volatile("cp.async.wait_group 0;\n");
    __syncthreads();

    int warpm = warp >> 1, warpn = warp & 1;
    int row0 = warpm * 16 + g, row1 = row0 + 8;

    uint32_t qoff = (uint32_t)(((warpm * 16 + lrow8 + 8 * l8) * TP + 8 * l16) * 2);
    uint32_t koff = (uint32_t)(((warpn * 32 + lrow8) * TP + 8 * l8) * 2);
    uint32_t poff = (uint32_t)(((warpm * 16 + lrow8 + 8 * l8) * PP + 8 * l16) * 2);
    uint32_t voff = (uint32_t)(((lrow8 + 8 * l8) * TP) * 2);
    uint32_t PB = sbase + 6 * TEB;
    uint32_t KB = sbase + 2 * TEB;
    uint32_t VB = sbase + 4 * TEB;

    float zacc[16][4] = {};

    for (int hl = 0; hl < 4; hl++) {
        int head = head0 + hl;

        // ---------- S = Q K^T ----------
        float c[4][4] = {};
#pragma unroll 4
        for (int ks = 0; ks < 16; ks++) {
            uint32_t kb2 = ks * 32;
            uint32_t ahi[4], alo[4];
            ldsm_x4(ahi, sbase + qoff + kb2);
            ldsm_x4(alo, sbase + TEB + qoff + kb2);
#pragma unroll
            for (int ni = 0; ni < 4; ni++) {
                uint32_t ba = KB + koff + ni * (8 * TP * 2) + kb2;
                uint32_t bh[2], bl[2];
                ldsm_x2(bh, ba);
                ldsm_x2(bl, ba + TEB);
                mma16816(c[ni], ahi, bh);
                mma16816(c[ni], alo, bh);
                mma16816(c[ni], ahi, bl);
            }
        }

        // ---------- softmax ----------
        float m0 = -1e30f, m1 = -1e30f;
#pragma unroll
        for (int ni = 0; ni < 4; ni++) {
            m0 = fmaxf(m0, fmaxf(c[ni][0], c[ni][1]));
            m1 = fmaxf(m1, fmaxf(c[ni][2], c[ni][3]));
        }
        m0 = fmaxf(m0, __shfl_xor_sync(0xffffffffu, m0, 1));
        m0 = fmaxf(m0, __shfl_xor_sync(0xffffffffu, m0, 2));
        m1 = fmaxf(m1, __shfl_xor_sync(0xffffffffu, m1, 1));
        m1 = fmaxf(m1, __shfl_xor_sync(0xffffffffu, m1, 2));
        if (tig == 0) {
            stmax[row0 * 2 + warpn] = m0;
            stmax[row1 * 2 + warpn] = m1;
        }
        __syncthreads();
        m0 = fmaxf(stmax[row0 * 2], stmax[row0 * 2 + 1]);
        m1 = fmaxf(stmax[row1 * 2], stmax[row1 * 2 + 1]);
        float s0 = 0.f, s1 = 0.f;
#pragma unroll
        for (int ni = 0; ni < 4; ni++) {
            c[ni][0] = __expf(c[ni][0] - m0);
            c[ni][1] = __expf(c[ni][1] - m0);
            c[ni][2] = __expf(c[ni][2] - m1);
            c[ni][3] = __expf(c[ni][3] - m1);
            s0 += c[ni][0] + c[ni][1];
            s1 += c[ni][2] + c[ni][3];
        }
        s0 += __shfl_xor_sync(0xffffffffu, s0, 1);
        s0 += __shfl_xor_sync(0xffffffffu, s0, 2);
        s1 += __shfl_xor_sync(0xffffffffu, s1, 1);
        s1 += __shfl_xor_sync(0xffffffffu, s1, 2);
        if (tig == 0) {
            stsum[row0 * 2 + warpn] = s0;
            stsum[row1 * 2 + warpn] = s1;
        }
        __syncthreads();
        float inv0 = 1.0f / (stsum[row0 * 2] + stsum[row0 * 2 + 1]);
        float inv1 = 1.0f / (stsum[row1 * 2] + stsum[row1 * 2 + 1]);
#pragma unroll
        for (int ni = 0; ni < 4; ni++) {
            int cn = warpn * 32 + ni * 8 + 2 * tig;
            __nv_bfloat16 h0, l0, h1, l1;
            bsplit(c[ni][0] * inv0, h0, l0); bsplit(c[ni][1] * inv0, h1, l1);
            *(__nv_bfloat162*)(Ph + row0 * PP + cn) = __nv_bfloat162(h0, h1);
            *(__nv_bfloat162*)(Pl + row0 * PP + cn) = __nv_bfloat162(l0, l1);
            bsplit(c[ni][2] * inv1, h0, l0); bsplit(c[ni][3] * inv1, h1, l1);
            *(__nv_bfloat162*)(Ph + row1 * PP + cn) = __nv_bfloat162(h0, h1);
            *(__nv_bfloat162*)(Pl + row1 * PP + cn) = __nv_bfloat162(l0, l1);
        }
        __syncthreads();

        if (hl < 3) {
            load_piece(0, (head + 1) * 256);
            asm volatile("cp.async.commit_group;\n");
        }

        // ---------- O = P V, so-scaled into zacc ----------
        const float* sop = g_so + head * 256;
#pragma unroll
        for (int ks = 0; ks < 4; ks++) {
            uint32_t kb2 = ks * 32;
            uint32_t ph[4], pl[4];
            ldsm_x4(ph, PB + poff + kb2);
            ldsm_x4(pl, PB + PPB + poff + kb2);
            uint32_t vrow = VB + voff + (uint32_t)ks * (16 * TP * 2);
#pragma unroll
            for (int ni = 0; ni < 16; ni++) {
                uint32_t va = vrow + (uint32_t)((warpn * 128 + ni * 8) * 2);
                uint32_t bh[2], bl[2];
                ldsm_x2t(bh, va);
                ldsm_x2t(bl, va + TEB);
                float ot[4] = {};
                mma16816(ot, ph, bh);
                mma16816(ot, pl, bh);
                mma16816(ot, ph, bl);
                float2 sv = *(const float2*)(sop + warpn * 128 + ni * 8 + 2 * tig);
                zacc[ni][0] += ot[0] * sv.x; zacc[ni][1] += ot[1] * sv.y;
                zacc[ni][2] += ot[2] * sv.x; zacc[ni][3] += ot[3] * sv.y;
            }
        }

        if (hl < 3) asm volatile("cp.async.wait_group 0;\n");
        __syncthreads();
    }

    // write so-weighted partial Z once
    float* gz = gridmode ? g_z1 : g_z2;
    size_t tok0 = base + (size_t)row0 * stride;
    size_t tok1 = base + (size_t)row1 * stride;
#pragma unroll
    for (int ni = 0; ni < 16; ni++) {
        int col = warpn * 128 + ni * 8 + 2 * tig;
        *(float2*)(gz + tok0 * DD + col) = make_float2(zacc[ni][0], zacc[ni][1]);
        *(float2*)(gz + tok1 * DD + col) = make_float2(zacc[ni][2], zacc[ni][3]);
    }
}

// ---------- z1+z2 + unpermute + residual + LN2 -> split bf16 ----------
__global__ void zred_ln2_kernel(const float* __restrict__ x,
                                const float* __restrict__ gamma,
                                const float* __restrict__ beta,
                                float* __restrict__ x2) {
    int gw   = (blockIdx.x * blockDim.x + threadIdx.x) >> 5;
    int lane = threadIdx.x & 31;

    int b = gw >> 12, m = (gw >> 6) & 63, n = gw & 63;
    int hh = ((n >> 3) << 3) | (m >> 3);
    int ww = ((n & 7) << 3) | (m & 7);
    size_t orow = ((size_t)b << 12) | (unsigned)((hh << 6) | ww);

    const float* z1 = g_z1 + (size_t)gw * DD;
    const float* z2 = g_z2 + (size_t)gw * DD;
    float4 a0 = ((const float4*)z1)[lane];
    float4 a1 = ((const float4*)z1)[lane + 32];
    float4 b0v = ((const float4*)z2)[lane];
    float4 b1v = ((const float4*)z2)[lane + 32];
    const float* xr = x + orow * DD;
    float4 x0 = ((const float4*)xr)[lane];
    float4 x1 = ((const float4*)xr)[lane + 32];
    float4 v0 = make_float4(x0.x + a0.x + b0v.x, x0.y + a0.y + b0v.y,
                            x0.z + a0.z + b0v.z, x0.w + a0.w + b0v.w);
    float4 v1 = make_float4(x1.x + a1.x + b1v.x, x1.y + a1.y + b1v.y,
                            x1.z + a1.z + b1v.z, x1.w + a1.w + b1v.w);

    ((float4*)(x2 + orow * DD))[lane]      = v0;
    ((float4*)(x2 + orow * DD))[lane + 32] = v1;

    float s  = v0.x + v0.y + v0.z + v0.w + v1.x + v1.y + v1.z + v1.w;
    float sq = v0.x*v0.x + v0.y*v0.y + v0.z*v0.z + v0.w*v0.w
             + v1.x*v1.x + v1.y*v1.y + v1.z*v1.z + v1.w*v1.w;
#pragma unroll
    for (int o = 16; o > 0; o >>= 1) {
        s  += __shfl_xor_sync(0xffffffffu, s,  o);
        sq += __shfl_xor_sync(0xffffffffu, sq, o);
    }
    float mean = s * (1.0f / 256.0f);
    float var  = sq * (1.0f / 256.0f) - mean * mean;
    float rstd = rsqrtf(var + 1e-5f);

    float4 g0 = ((const float4*)gamma)[lane];
    float4 g1 = ((const float4*)gamma)[lane + 32];
    float4 bb0 = ((const float4*)beta)[lane];
    float4 bb1 = ((const float4*)beta)[lane + 32];
    float4 o0, o1;
    o0.x = (v0.x - mean) * rstd * g0.x + bb0.x;
    o0.y = (v0.y - mean) * rstd * g0.y + bb0.y;
    o0.z = (v0.z - mean) * rstd * g0.z + bb0.z;
    o0.w = (v0.w - mean) * rstd * g0.w + bb0.w;
    o1.x = (v1.x - mean) * rstd * g1.x + bb1.x;
    o1.y = (v1.y - mean) * rstd * g1.y + bb1.y;
    o1.z = (v1.z - mean) * rstd * g1.z + bb1.z;
    o1.w = (v1.w - mean) * rstd * g1.w + bb1.w;
    store_split8(g_ln2sp + orow * 512, lane * 4, o0, o1);
}

// ---------------- launch ----------------
extern "C" void kernel_launch(void* const* d_in, const int* in_sizes, int n_in,
                              void* d_out, int out_size) {
    const float* x    = (const float*)d_in[0];
    const float* ln1w = (const float*)d_in[1];
    const float* ln1b = (const float*)d_in[2];
    const float* qw   = (const float*)d_in[3];
    const float* kw   = (const float*)d_in[4];
    const float* vw   = (const float*)d_in[5];
    const float* ow   = (const float*)d_in[6];
    const float* ln2w = (const float*)d_in[7];
    const float* ln2b = (const float*)d_in[8];
    const float* w1   = (const float*)d_in[9];
    const float* b1   = (const float*)d_in[10];
    const float* w2   = (const float*)d_in[11];
    const float* b2   = (const float*)d_in[12];
    float* out = (float*)d_out;

    __nv_bfloat16 *p_asp, *p_wsp, *p_w1sp, *p_w2sp, *p_ln2sp, *p_m1sp, *p_qkvsp;
    float *p_x2;
    cudaGetSymbolAddress((void**)&p_asp,   g_asp);
    cudaGetSymbolAddress((void**)&p_wsp,   g_wsp);
    cudaGetSymbolAddress((void**)&p_w1sp,  g_w1sp);
    cudaGetSymbolAddress((void**)&p_w2sp,  g_w2sp);
    cudaGetSymbolAddress((void**)&p_ln2sp, g_ln2sp);
    cudaGetSymbolAddress((void**)&p_m1sp,  g_m1sp);
    cudaGetSymbolAddress((void**)&p_qkvsp, g_qkvsp);
    cudaGetSymbolAddress((void**)&p_x2,    g_x2);

    cudaFuncSetAttribute(attn_mma_kernel, cudaFuncAttributeMaxDynamicSharedMemorySize,
                         ATTN_SMEM_B);
    cudaFuncSetAttribute(bfmma_gemm_kernel<0>, cudaFuncAttributeMaxDynamicSharedMemorySize, GSMEM);
    cudaFuncSetAttribute(bfmma_gemm_kernel<2>, cudaFuncAttributeMaxDynamicSharedMemorySize, GSMEM);
    cudaFuncSetAttribute(bfmma_gemm_kernel<3>, cudaFuncAttributeMaxDynamicSharedMemorySize, GSMEM);

    // 1. weight prep
    prep_wqkv_kernel<<<QKVC, 256>>>(qw, kw, vw);
    prep_wt_kernel<<<256, 256>>>(w1, p_w1sp);
    prep_wt_kernel<<<256, 256>>>(w2, p_w2sp);
    prep_so_kernel<<<256, 256>>>(ow);
    // 2. LN1 + block permute -> split
    ln1_kernel<<<NTOK / 8, 256>>>(x, ln1w, ln1b);
    // 3. QKV projection -> split bf16
    bfmma_gemm_kernel<0><<<dim3(QKVC / 128, NTOK / 128), 256, GSMEM>>>(
        p_asp, p_wsp, nullptr, p_qkvsp, nullptr, nullptr, QKVC);
    // 4. tensor-core attention + fused head-mix
    attn_mma_kernel<<<1024, 256, ATTN_SMEM_B>>>();
    // 5. z1+z2 + unpermute + residual + LN2 -> split
    zred_ln2_kernel<<<NTOK / 8, 256>>>(x, ln2w, ln2b, p_x2);
    // 6. MLP fc1 + ReLU -> split
    bfmma_gemm_kernel<2><<<dim3(DD / 128, NTOK / 128), 256, GSMEM>>>(
        p_ln2sp, p_w1sp, nullptr, p_m1sp, b1, nullptr, DD);
    // 7. MLP fc2 + bias + residual -> out
    bfmma_gemm_kernel<3><<<dim3(DD / 128, NTOK / 128), 256, GSMEM>>>(
        p_m1sp, p_w2sp, out, nullptr, b2, p_x2, DD);
}

// round 9
// speedup vs baseline: 2.3542x; 1.0100x over previous
#include <cuda_runtime.h>
#include <cuda_bf16.h>
#include <cstdint>
#include <cstddef>

typedef __nv_bfloat16 bf16;

// ---------------- problem constants ----------------
#define NTOK     32768
#define DD       256
#define QKVC     2560

// ---------------- static scratch ----------------
__device__ bf16 g_asp  [(size_t)NTOK * 512];
__device__ bf16 g_wsp  [(size_t)QKVC * 512];
__device__ bf16 g_w1sp [(size_t)DD * 512];
__device__ bf16 g_w2sp [(size_t)DD * 512];
__device__ bf16 g_ln2sp[(size_t)NTOK * 512];
__device__ bf16 g_qkvsp[(size_t)NTOK * 5120];
__device__ float g_z1  [(size_t)NTOK * DD];
__device__ float g_z2  [(size_t)NTOK * DD];
__device__ float g_so  [2048];
__device__ float g_x2  [(size_t)NTOK * DD];

// ---------------- helpers ----------------
__device__ __forceinline__ void bsplit(float v, bf16& h, bf16& l) {
    h = __float2bfloat16_rn(v);
    l = __float2bfloat16_rn(v - __bfloat162float(h));
}
__device__ __forceinline__ void cpasync16(uint32_t s, const void* g) {
    asm volatile("cp.async.cg.shared.global [%0], [%1], 16;\n" :: "r"(s), "l"(g));
}
__device__ __forceinline__ void mma16816(float* c, const uint32_t* a, const uint32_t* b) {
    asm volatile(
        "mma.sync.aligned.m16n8k16.row.col.f32.bf16.bf16.f32 "
        "{%0,%1,%2,%3},{%4,%5,%6,%7},{%8,%9},{%0,%1,%2,%3};\n"
        : "+f"(c[0]), "+f"(c[1]), "+f"(c[2]), "+f"(c[3])
        : "r"(a[0]), "r"(a[1]), "r"(a[2]), "r"(a[3]), "r"(b[0]), "r"(b[1]));
}
__device__ __forceinline__ void ldsm_x4(uint32_t* r, uint32_t a) {
    asm volatile("ldmatrix.sync.aligned.m8n8.x4.shared.b16 {%0,%1,%2,%3}, [%4];"
        : "=r"(r[0]), "=r"(r[1]), "=r"(r[2]), "=r"(r[3]) : "r"(a));
}
__device__ __forceinline__ void ldsm_x2(uint32_t* r, uint32_t a) {
    asm volatile("ldmatrix.sync.aligned.m8n8.x2.shared.b16 {%0,%1}, [%2];"
        : "=r"(r[0]), "=r"(r[1]) : "r"(a));
}
__device__ __forceinline__ void ldsm_x2t(uint32_t* r, uint32_t a) {
    asm volatile("ldmatrix.sync.aligned.m8n8.x2.trans.shared.b16 {%0,%1}, [%2];"
        : "=r"(r[0]), "=r"(r[1]) : "r"(a));
}

// ---------------- weight prep ----------------
__global__ void prep_wqkv_kernel(const float* __restrict__ q,
                                 const float* __restrict__ k,
                                 const float* __restrict__ v) {
    int idx = blockIdx.x * 256 + threadIdx.x;
    int d = idx & 255, j = idx >> 8;
    float val;
    if (j < 2048) { int h = j >> 8, kk = j & 255; val = q[((size_t)(h * 256 + d)) * 256 + kk]; }
    else if (j < 2304) val = k[(size_t)d * 256 + (j - 2048)];
    else               val = v[(size_t)d * 256 + (j - 2304)];
    bf16 h16, l16; bsplit(val, h16, l16);
    g_wsp[(size_t)j * 512 + d]       = h16;
    g_wsp[(size_t)j * 512 + 256 + d] = l16;
}

__global__ void prep_wt_kernel(const float* __restrict__ src, bf16* __restrict__ dst) {
    int idx = blockIdx.x * 256 + threadIdx.x;
    int d = idx & 255, j = idx >> 8;
    float val = src[(size_t)d * 256 + j];
    bf16 h16, l16; bsplit(val, h16, l16);
    dst[(size_t)j * 512 + d]       = h16;
    dst[(size_t)j * 512 + 256 + d] = l16;
}

__global__ void prep_so_kernel(const float* __restrict__ o) {
    int row  = (blockIdx.x * blockDim.x + threadIdx.x) >> 5;
    int lane = threadIdx.x & 31;
    const float* rp = o + (size_t)row * 256;
    float4 a = ((const float4*)rp)[lane];
    float4 b = ((const float4*)rp)[lane + 32];
    float s = a.x + a.y + a.z + a.w + b.x + b.y + b.z + b.w;
#pragma unroll
    for (int off = 16; off > 0; off >>= 1) s += __shfl_xor_sync(0xffffffffu, s, off);
    if (lane == 0) g_so[row] = s;
}

// ---------------- LN1 + block permute -> split bf16 ----------------
__device__ __forceinline__ void store_split8(bf16* rowp, int col, float4 v0, float4 v1) {
    bf16 h[8], l[8];
    bsplit(v0.x, h[0], l[0]); bsplit(v0.y, h[1], l[1]);
    bsplit(v0.z, h[2], l[2]); bsplit(v0.w, h[3], l[3]);
    bsplit(v1.x, h[4], l[4]); bsplit(v1.y, h[5], l[5]);
    bsplit(v1.z, h[6], l[6]); bsplit(v1.w, h[7], l[7]);
#pragma unroll
    for (int i = 0; i < 4; i++) {
        rowp[col + i]             = h[i];
        rowp[col + 128 + i]       = h[4 + i];
        rowp[256 + col + i]       = l[i];
        rowp[256 + col + 128 + i] = l[4 + i];
    }
}

__global__ void ln1_kernel(const float* __restrict__ in,
                           const float* __restrict__ gamma,
                           const float* __restrict__ beta) {
    int gwarp = (blockIdx.x * blockDim.x + threadIdx.x) >> 5;
    int lane  = threadIdx.x & 31;
    const float* row = in + (size_t)gwarp * DD;
    float4 v0 = ((const float4*)row)[lane];
    float4 v1 = ((const float4*)row)[lane + 32];
    float s  = v0.x + v0.y + v0.z + v0.w + v1.x + v1.y + v1.z + v1.w;
    float sq = v0.x*v0.x + v0.y*v0.y + v0.z*v0.z + v0.w*v0.w
             + v1.x*v1.x + v1.y*v1.y + v1.z*v1.z + v1.w*v1.w;
#pragma unroll
    for (int o = 16; o > 0; o >>= 1) {
        s  += __shfl_xor_sync(0xffffffffu, s,  o);
        sq += __shfl_xor_sync(0xffffffffu, sq, o);
    }
    float mean = s * (1.0f / 256.0f);
    float var  = sq * (1.0f / 256.0f) - mean * mean;
    float rstd = rsqrtf(var + 1e-5f);

    int b = gwarp >> 12, pos = gwarp & 4095;
    int h = pos >> 6, w = pos & 63;
    int m = ((h & 7) << 3) | (w & 7);
    int n = ((h >> 3) << 3) | (w >> 3);
    size_t orow = ((size_t)b << 12) | (unsigned)((m << 6) | n);

    float4 g0 = ((const float4*)gamma)[lane];
    float4 g1 = ((const float4*)gamma)[lane + 32];
    float4 b0 = ((const float4*)beta)[lane];
    float4 b1 = ((const float4*)beta)[lane + 32];
    float4 o0, o1;
    o0.x = (v0.x - mean) * rstd * g0.x + b0.x;
    o0.y = (v0.y - mean) * rstd * g0.y + b0.y;
    o0.z = (v0.z - mean) * rstd * g0.z + b0.z;
    o0.w = (v0.w - mean) * rstd * g0.w + b0.w;
    o1.x = (v1.x - mean) * rstd * g1.x + b1.x;
    o1.y = (v1.y - mean) * rstd * g1.y + b1.y;
    o1.z = (v1.z - mean) * rstd * g1.z + b1.z;
    o1.w = (v1.w - mean) * rstd * g1.w + b1.w;
    store_split8(g_asp + orow * 512, lane * 4, o0, o1);
}

// ================= wide bf16 GEMM: 128x256 tile, 3-term split =================
#define WGP 40
#define A_PL (128 * WGP * 2)            // 10240 B
#define B_PL (256 * WGP * 2)            // 20480 B
#define WSTAGE (2 * A_PL + 2 * B_PL)    // 61440 B
#define WGSMEM (2 * WSTAGE)             // 122880 B

__global__ __launch_bounds__(256, 1)
void qkv_gemm_kernel(const bf16* __restrict__ Asp,
                     const bf16* __restrict__ Bsp,
                     bf16* __restrict__ Csp) {
    extern __shared__ bf16 smem[];
    uint32_t sb = (uint32_t)__cvta_generic_to_shared(smem);

    int tid = threadIdx.x;
    int lane = tid & 31, warp = tid >> 5;
    int wm = warp & 1, wn = warp >> 1;          // 2 x 4 warps, 64x64 each
    int g = lane >> 2, tig = lane & 3;
    int lrow8 = lane & 7, l8 = (lane >> 3) & 1, l16 = (lane >> 4) & 1;
    int rowBase = blockIdx.y * 128;
    int colBase = blockIdx.x * 256;

    uint32_t aoff = (uint32_t)(((wm * 64 + lrow8 + 8 * l8) * WGP + 8 * l16) * 2);
    uint32_t boff = (uint32_t)(((wn * 64 + lrow8) * WGP + 8 * l8) * 2);

    float acc[4][8][4] = {};

    auto load_chunk = [&](int c, int st) {
        const bf16* Ag = Asp + (size_t)rowBase * 512 + c * 32;
        const bf16* Bg = Bsp + (size_t)colBase * 512 + c * 32;
        uint32_t base = sb + (uint32_t)st * WSTAGE;
#pragma unroll
        for (int i = 0; i < 2; i++) {
            int f = tid + i * 256;
            int r = f >> 2, q = f & 3;
            uint32_t so = (uint32_t)(r * WGP + q * 8) * 2;
            const bf16* ga = Ag + (size_t)r * 512 + q * 8;
            cpasync16(base + so,        ga);
            cpasync16(base + A_PL + so, ga + 256);
        }
#pragma unroll
        for (int i = 0; i < 4; i++) {
            int f = tid + i * 256;
            int r = f >> 2, q = f & 3;
            uint32_t so = (uint32_t)(r * WGP + q * 8) * 2;
            const bf16* gb = Bg + (size_t)r * 512 + q * 8;
            cpasync16(base + 2 * A_PL + so,        gb);
            cpasync16(base + 2 * A_PL + B_PL + so, gb + 256);
        }
        asm volatile("cp.async.commit_group;\n");
    };

    load_chunk(0, 0);
    const int NCH = 8;
    for (int c = 0; c < NCH; c++) {
        if (c + 1 < NCH) {
            load_chunk(c + 1, (c + 1) & 1);
            asm volatile("cp.async.wait_group 1;\n");
        } else {
            asm volatile("cp.async.wait_group 0;\n");
        }
        __syncthreads();

        uint32_t stb = sb + (uint32_t)(c & 1) * WSTAGE;
#pragma unroll
        for (int ks = 0; ks < 2; ks++) {
            uint32_t kb2 = ks * 32;
            uint32_t ahi[4][4], alo[4][4];
#pragma unroll
            for (int mi = 0; mi < 4; mi++) {
                uint32_t a = stb + aoff + mi * (16 * WGP * 2) + kb2;
                ldsm_x4(ahi[mi], a);
                ldsm_x4(alo[mi], a + A_PL);
            }
#pragma unroll
            for (int ni = 0; ni < 8; ni++) {
                uint32_t ba = stb + 2 * A_PL + boff + ni * (8 * WGP * 2) + kb2;
                uint32_t bh[2], bl[2];
                ldsm_x2(bh, ba);
                ldsm_x2(bl, ba + B_PL);
#pragma unroll
                for (int mi = 0; mi < 4; mi++) {
                    mma16816(acc[mi][ni], ahi[mi], bh);
                    mma16816(acc[mi][ni], alo[mi], bh);
                    mma16816(acc[mi][ni], ahi[mi], bl);
                }
            }
        }
        __syncthreads();
    }

#pragma unroll
    for (int mi = 0; mi < 4; mi++) {
        int r0 = rowBase + wm * 64 + mi * 16 + g;
        int r1 = r0 + 8;
#pragma unroll
        for (int ni = 0; ni < 8; ni++) {
            int col = colBase + wn * 64 + ni * 8 + tig * 2;
            bf16 h0, l0, h1, l1;
            bsplit(acc[mi][ni][0], h0, l0); bsplit(acc[mi][ni][1], h1, l1);
            *(__nv_bfloat162*)(Csp + (size_t)r0 * 5120 + col)        = __nv_bfloat162(h0, h1);
            *(__nv_bfloat162*)(Csp + (size_t)r0 * 5120 + 2560 + col) = __nv_bfloat162(l0, l1);
            bsplit(acc[mi][ni][2], h0, l0); bsplit(acc[mi][ni][3], h1, l1);
            *(__nv_bfloat162*)(Csp + (size_t)r1 * 5120 + col)        = __nv_bfloat162(h0, h1);
            *(__nv_bfloat162*)(Csp + (size_t)r1 * 5120 + 2560 + col) = __nv_bfloat162(l0, l1);
        }
    }
}

// ================= fused MLP: h = relu(LN2 W1 + b1) in smem; out = h W2 + b2 + x2 =================
#define HP 264
#define HPLANE (128 * HP * 2)            // 67584 B
#define W2S0 (2 * HPLANE)                // 135168
#define W2STG (2 * B_PL)                 // 40960
#define MLPSMEM (W2S0 + 2 * W2STG)       // 217088

__global__ __launch_bounds__(256, 1)
void mlp_fused_kernel(const bf16* __restrict__ ln2sp,
                      const bf16* __restrict__ w1sp,
                      const bf16* __restrict__ w2sp,
                      const float* __restrict__ b1,
                      const float* __restrict__ b2,
                      const float* __restrict__ x2,
                      float* __restrict__ out) {
    extern __shared__ bf16 smem[];
    uint32_t sb = (uint32_t)__cvta_generic_to_shared(smem);

    int tid = threadIdx.x;
    int lane = tid & 31, warp = tid >> 5;
    int wm = warp & 1, wn = warp >> 1;
    int g = lane >> 2, tig = lane & 3;
    int lrow8 = lane & 7, l8 = (lane >> 3) & 1, l16 = (lane >> 4) & 1;
    int rowBase = blockIdx.x * 128;

    uint32_t aoff = (uint32_t)(((wm * 64 + lrow8 + 8 * l8) * WGP + 8 * l16) * 2);
    uint32_t boff = (uint32_t)(((wn * 64 + lrow8) * WGP + 8 * l8) * 2);
    uint32_t hoff = (uint32_t)(((wm * 64 + lrow8 + 8 * l8) * HP + 8 * l16) * 2);

    float acc[4][8][4] = {};

    // ---- phase-1 loader (stages at smem offset 0) ----
    auto load1 = [&](int c, int st) {
        const bf16* Ag = ln2sp + (size_t)rowBase * 512 + c * 32;
        const bf16* Bg = w1sp + c * 32;
        uint32_t base = sb + (uint32_t)st * WSTAGE;
#pragma unroll
        for (int i = 0; i < 2; i++) {
            int f = tid + i * 256;
            int r = f >> 2, q = f & 3;
            uint32_t so = (uint32_t)(r * WGP + q * 8) * 2;
            const bf16* ga = Ag + (size_t)r * 512 + q * 8;
            cpasync16(base + so,        ga);
            cpasync16(base + A_PL + so, ga + 256);
        }
#pragma unroll
        for (int i = 0; i < 4; i++) {
            int f = tid + i * 256;
            int r = f >> 2, q = f & 3;
            uint32_t so = (uint32_t)(r * WGP + q * 8) * 2;
            const bf16* gb = Bg + (size_t)r * 512 + q * 8;
            cpasync16(base + 2 * A_PL + so,        gb);
            cpasync16(base + 2 * A_PL + B_PL + so, gb + 256);
        }
        asm volatile("cp.async.commit_group;\n");
    };
    // ---- phase-2 w2 loader ----
    auto load2 = [&](int c, int st) {
        const bf16* Bg = w2sp + c * 32;
        uint32_t base = sb + W2S0 + (uint32_t)st * W2STG;
#pragma unroll
        for (int i = 0; i < 4; i++) {
            int f = tid + i * 256;
            int r = f >> 2, q = f & 3;
            uint32_t so = (uint32_t)(r * WGP + q * 8) * 2;
            const bf16* gb = Bg + (size_t)r * 512 + q * 8;
            cpasync16(base + so,        gb);
            cpasync16(base + B_PL + so, gb + 256);
        }
        asm volatile("cp.async.commit_group;\n");
    };

    // ================= phase 1: h = relu(ln2 @ w1 + b1) =================
    load1(0, 0);
    for (int c = 0; c < 8; c++) {
        if (c + 1 < 8) {
            load1(c + 1, (c + 1) & 1);
            asm volatile("cp.async.wait_group 1;\n");
        } else {
            asm volatile("cp.async.wait_group 0;\n");
        }
        __syncthreads();
        uint32_t stb = sb + (uint32_t)(c & 1) * WSTAGE;
#pragma unroll
        for (int ks = 0; ks < 2; ks++) {
            uint32_t kb2 = ks * 32;
            uint32_t ahi[4][4], alo[4][4];
#pragma unroll
            for (int mi = 0; mi < 4; mi++) {
                uint32_t a = stb + aoff + mi * (16 * WGP * 2) + kb2;
                ldsm_x4(ahi[mi], a);
                ldsm_x4(alo[mi], a + A_PL);
            }
#pragma unroll
            for (int ni = 0; ni < 8; ni++) {
                uint32_t ba = stb + 2 * A_PL + boff + ni * (8 * WGP * 2) + kb2;
                uint32_t bh[2], bl[2];
                ldsm_x2(bh, ba);
                ldsm_x2(bl, ba + B_PL);
#pragma unroll
                for (int mi = 0; mi < 4; mi++) {
                    mma16816(acc[mi][ni], ahi[mi], bh);
                    mma16816(acc[mi][ni], alo[mi], bh);
                    mma16816(acc[mi][ni], ahi[mi], bl);
                }
            }
        }
        __syncthreads();
    }

    // start streaming w2 chunk 0 while we do the h epilogue
    load2(0, 0);

    // h epilogue: +b1, relu, split -> smem planes
    bf16* hhi = smem;
    bf16* hlo = smem + 128 * HP;
#pragma unroll
    for (int mi = 0; mi < 4; mi++) {
        int r0 = wm * 64 + mi * 16 + g;
        int r1 = r0 + 8;
#pragma unroll
        for (int ni = 0; ni < 8; ni++) {
            int col = wn * 64 + ni * 8 + tig * 2;
            float2 bv = *(const float2*)(b1 + col);
            float v0 = fmaxf(acc[mi][ni][0] + bv.x, 0.f);
            float v1 = fmaxf(acc[mi][ni][1] + bv.y, 0.f);
            float v2 = fmaxf(acc[mi][ni][2] + bv.x, 0.f);
            float v3 = fmaxf(acc[mi][ni][3] + bv.y, 0.f);
            bf16 h0, l0, h1, l1;
            bsplit(v0, h0, l0); bsplit(v1, h1, l1);
            *(__nv_bfloat162*)(hhi + r0 * HP + col) = __nv_bfloat162(h0, h1);
            *(__nv_bfloat162*)(hlo + r0 * HP + col) = __nv_bfloat162(l0, l1);
            bsplit(v2, h0, l0); bsplit(v3, h1, l1);
            *(__nv_bfloat162*)(hhi + r1 * HP + col) = __nv_bfloat162(h0, h1);
            *(__nv_bfloat162*)(hlo + r1 * HP + col) = __nv_bfloat162(l0, l1);
            acc[mi][ni][0] = 0.f; acc[mi][ni][1] = 0.f;
            acc[mi][ni][2] = 0.f; acc[mi][ni][3] = 0.f;
        }
    }
    __syncthreads();

    // ================= phase 2: out = h @ w2 + b2 + x2 =================
    for (int c = 0; c < 8; c++) {
        if (c + 1 < 8) {
            load2(c + 1, (c + 1) & 1);
            asm volatile("cp.async.wait_group 1;\n");
        } else {
            asm volatile("cp.async.wait_group 0;\n");
        }
        __syncthreads();
        uint32_t w2b = sb + W2S0 + (uint32_t)(c & 1) * W2STG;
#pragma unroll
        for (int ks = 0; ks < 2; ks++) {
            uint32_t kbyte = (uint32_t)((c * 32 + ks * 16) * 2);
            uint32_t kb2 = ks * 32;
            uint32_t ahi[4][4], alo[4][4];
#pragma unroll
            for (int mi = 0; mi < 4; mi++) {
                uint32_t a = sb + hoff + mi * (16 * HP * 2) + kbyte;
                ldsm_x4(ahi[mi], a);
                ldsm_x4(alo[mi], a + HPLANE);
            }
#pragma unroll
            for (int ni = 0; ni < 8; ni++) {
                uint32_t ba = w2b + boff + ni * (8 * WGP * 2) + kb2;
                uint32_t bh[2], bl[2];
                ldsm_x2(bh, ba);
                ldsm_x2(bl, ba + B_PL);
#pragma unroll
                for (int mi = 0; mi < 4; mi++) {
                    mma16816(acc[mi][ni], ahi[mi], bh);
                    mma16816(acc[mi][ni], alo[mi], bh);
                    mma16816(acc[mi][ni], ahi[mi], bl);
                }
            }
        }
        __syncthreads();
    }

#pragma unroll
    for (int mi = 0; mi < 4; mi++) {
        int r0 = rowBase + wm * 64 + mi * 16 + g;
        int r1 = r0 + 8;
#pragma unroll
        for (int ni = 0; ni < 8; ni++) {
            int col = wn * 64 + ni * 8 + tig * 2;
            float2 bv = *(const float2*)(b2 + col);
            float2 e0 = *(const float2*)(x2 + (size_t)r0 * DD + col);
            float2 e1 = *(const float2*)(x2 + (size_t)r1 * DD + col);
            float2 v0 = make_float2(acc[mi][ni][0] + bv.x + e0.x,
                                    acc[mi][ni][1] + bv.y + e0.y);
            float2 v1 = make_float2(acc[mi][ni][2] + bv.x + e1.x,
                                    acc[mi][ni][3] + bv.y + e1.y);
            *(float2*)(out + (size_t)r0 * DD + col) = v0;
            *(float2*)(out + (size_t)r1 * DD + col) = v1;
        }
    }
}

// ================= tensor-core attention + fused head-mix (R8) =================
#define TP 264
#define PP 72
#define TILE_E (64 * TP)
#define TEB (TILE_E * 2)
#define PPB (64 * PP * 2)
#define ATTN_SMEM_B (6 * TEB + 2 * PPB + 1024)

__global__ __launch_bounds__(256)
void attn_mma_kernel() {
    extern __shared__ bf16 asm_[];
    bf16* Ph = asm_ + 6 * TILE_E;
    bf16* Pl = Ph + 64 * PP;
    float* stmax = (float*)(Pl + 64 * PP);
    float* stsum = stmax + 128;
    uint32_t sbase = (uint32_t)__cvta_generic_to_shared(asm_);

    int tid = threadIdx.x;
    int lane = tid & 31, warp = tid >> 5;
    int g = lane >> 2, tig = lane & 3;
    int lrow8 = lane & 7, l8 = (lane >> 3) & 1, l16 = (lane >> 4) & 1;

    int u = blockIdx.x;
    bool gridmode = (u < 512);
    int b, fix;
    if (gridmode) { b = u >> 6; fix = u & 63; }
    else          { int u2 = u - 512; b = u2 >> 6; fix = u2 & 63; }
    size_t base; int stride;
    if (gridmode) { base = (size_t)b * 4096 + fix; stride = 64; }
    else          { base = (size_t)b * 4096 + (size_t)fix * 64; stride = 1; }
    int head0 = gridmode ? 0 : 4;

    auto load_piece = [&](int planeIdx, int colOff) {
        uint32_t sh = sbase + (uint32_t)planeIdx * TEB;
#pragma unroll
        for (int i = 0; i < 8; i++) {
            int f = i * 256 + tid;
            int r = f >> 5, q = f & 31;
            size_t token = base + (size_t)r * stride;
            const bf16* ga = g_qkvsp + token * 5120 + colOff + q * 8;
            uint32_t so = (uint32_t)(r * TP + q * 8) * 2;
            cpasync16(sh + so, ga);
            cpasync16(sh + TEB + so, ga + 2560);
        }
    };

    load_piece(2, 2048);
    load_piece(4, 2304);
    load_piece(0, head0 * 256);
    asm volatile("cp.async.commit_group;\n");
    asm volatile("cp.async.wait_group 0;\n");
    __syncthreads();

    int warpm = warp >> 1, warpn = warp & 1;
    int row0 = warpm * 16 + g, row1 = row0 + 8;

    uint32_t qoff = (uint32_t)(((warpm * 16 + lrow8 + 8 * l8) * TP + 8 * l16) * 2);
    uint32_t koff = (uint32_t)(((warpn * 32 + lrow8) * TP + 8 * l8) * 2);
    uint32_t poff = (uint32_t)(((warpm * 16 + lrow8 + 8 * l8) * PP + 8 * l16) * 2);
    uint32_t voff = (uint32_t)(((lrow8 + 8 * l8) * TP) * 2);
    uint32_t PB = sbase + 6 * TEB;
    uint32_t KB = sbase + 2 * TEB;
    uint32_t VB = sbase + 4 * TEB;

    float zacc[16][4] = {};

    for (int hl = 0; hl < 4; hl++) {
        int head = head0 + hl;

        float c[4][4] = {};
#pragma unroll 4
        for (int ks = 0; ks < 16; ks++) {
            uint32_t kb2 = ks * 32;
            uint32_t ahi[4], alo[4];
            ldsm_x4(ahi, sbase + qoff + kb2);
            ldsm_x4(alo, sbase + TEB + qoff + kb2);
#pragma unroll
            for (int ni = 0; ni < 4; ni++) {
                uint32_t ba = KB + koff + ni * (8 * TP * 2) + kb2;
                uint32_t bh[2], bl[2];
                ldsm_x2(bh, ba);
                ldsm_x2(bl, ba + TEB);
                mma16816(c[ni], ahi, bh);
                mma16816(c[ni], alo, bh);
                mma16816(c[ni], ahi, bl);
            }
        }

        float m0 = -1e30f, m1 = -1e30f;
#pragma unroll
        for (int ni = 0; ni < 4; ni++) {
            m0 = fmaxf(m0, fmaxf(c[ni][0], c[ni][1]));
            m1 = fmaxf(m1, fmaxf(c[ni][2], c[ni][3]));
        }
        m0 = fmaxf(m0, __shfl_xor_sync(0xffffffffu, m0, 1));
        m0 = fmaxf(m0, __shfl_xor_sync(0xffffffffu, m0, 2));
        m1 = fmaxf(m1, __shfl_xor_sync(0xffffffffu, m1, 1));
        m1 = fmaxf(m1, __shfl_xor_sync(0xffffffffu, m1, 2));
        if (tig == 0) {
            stmax[row0 * 2 + warpn] = m0;
            stmax[row1 * 2 + warpn] = m1;
        }
        __syncthreads();
        m0 = fmaxf(stmax[row0 * 2], stmax[row0 * 2 + 1]);
        m1 = fmaxf(stmax[row1 * 2], stmax[row1 * 2 + 1]);
        float s0 = 0.f, s1 = 0.f;
#pragma unroll
        for (int ni = 0; ni < 4; ni++) {
            c[ni][0] = __expf(c[ni][0] - m0);
            c[ni][1] = __expf(c[ni][1] - m0);
            c[ni][2] = __expf(c[ni][2] - m1);
            c[ni][3] = __expf(c[ni][3] - m1);
            s0 += c[ni][0] + c[ni][1];
            s1 += c[ni][2] + c[ni][3];
        }
        s0 += __shfl_xor_sync(0xffffffffu, s0, 1);
        s0 += __shfl_xor_sync(0xffffffffu, s0, 2);
        s1 += __shfl_xor_sync(0xffffffffu, s1, 1);
        s1 += __shfl_xor_sync(0xffffffffu, s1, 2);
        if (tig == 0) {
            stsum[row0 * 2 + warpn] = s0;
            stsum[row1 * 2 + warpn] = s1;
        }
        __syncthreads();
        float inv0 = 1.0f / (stsum[row0 * 2] + stsum[row0 * 2 + 1]);
        float inv1 = 1.0f / (stsum[row1 * 2] + stsum[row1 * 2 + 1]);
#pragma unroll
        for (int ni = 0; ni < 4; ni++) {
            int cn = warpn * 32 + ni * 8 + 2 * tig;
            bf16 h0, l0, h1, l1;
            bsplit(c[ni][0] * inv0, h0, l0); bsplit(c[ni][1] * inv0, h1, l1);
            *(__nv_bfloat162*)(Ph + row0 * PP + cn) = __nv_bfloat162(h0, h1);
            *(__nv_bfloat162*)(Pl + row0 * PP + cn) = __nv_bfloat162(l0, l1);
            bsplit(c[ni][2] * inv1, h0, l0); bsplit(c[ni][3] * inv1, h1, l1);
            *(__nv_bfloat162*)(Ph + row1 * PP + cn) = __nv_bfloat162(h0, h1);
            *(__nv_bfloat162*)(Pl + row1 * PP + cn) = __nv_bfloat162(l0, l1);
        }
        __syncthreads();

        if (hl < 3) {
            load_piece(0, (head + 1) * 256);
            asm volatile("cp.async.commit_group;\n");
        }

        const float* sop = g_so + head * 256;
#pragma unroll
        for (int ks = 0; ks < 4; ks++) {
            uint32_t kb2 = ks * 32;
            uint32_t ph[4], pl[4];
            ldsm_x4(ph, PB + poff + kb2);
            ldsm_x4(pl, PB + PPB + poff + kb2);
            uint32_t vrow = VB + voff + (uint32_t)ks * (16 * TP * 2);
#pragma unroll
            for (int ni = 0; ni < 16; ni++) {
                uint32_t va = vrow + (uint32_t)((warpn * 128 + ni * 8) * 2);
                uint32_t bh[2], bl[2];
                ldsm_x2t(bh, va);
                ldsm_x2t(bl, va + TEB);
                float ot[4] = {};
                mma16816(ot, ph, bh);
                mma16816(ot, pl, bh);
                mma16816(ot, ph, bl);
                float2 sv = *(const float2*)(sop + warpn * 128 + ni * 8 + 2 * tig);
                zacc[ni][0] += ot[0] * sv.x; zacc[ni][1] += ot[1] * sv.y;
                zacc[ni][2] += ot[2] * sv.x; zacc[ni][3] += ot[3] * sv.y;
            }
        }

        if (hl < 3) asm volatile("cp.async.wait_group 0;\n");
        __syncthreads();
    }

    float* gz = gridmode ? g_z1 : g_z2;
    size_t tok0 = base + (size_t)row0 * stride;
    size_t tok1 = base + (size_t)row1 * stride;
#pragma unroll
    for (int ni = 0; ni < 16; ni++) {
        int col = warpn * 128 + ni * 8 + 2 * tig;
        *(float2*)(gz + tok0 * DD + col) = make_float2(zacc[ni][0], zacc[ni][1]);
        *(float2*)(gz + tok1 * DD + col) = make_float2(zacc[ni][2], zacc[ni][3]);
    }
}

// ---------- z1+z2 + unpermute + residual + LN2 -> split bf16 ----------
__global__ void zred_ln2_kernel(const float* __restrict__ x,
                                const float* __restrict__ gamma,
                                const float* __restrict__ beta,
                                float* __restrict__ x2) {
    int gw   = (blockIdx.x * blockDim.x + threadIdx.x) >> 5;
    int lane = threadIdx.x & 31;

    int b = gw >> 12, m = (gw >> 6) & 63, n = gw & 63;
    int hh = ((n >> 3) << 3) | (m >> 3);
    int ww = ((n & 7) << 3) | (m & 7);
    size_t orow = ((size_t)b << 12) | (unsigned)((hh << 6) | ww);

    const float* z1 = g_z1 + (size_t)gw * DD;
    const float* z2 = g_z2 + (size_t)gw * DD;
    float4 a0 = ((const float4*)z1)[lane];
    float4 a1 = ((const float4*)z1)[lane + 32];
    float4 b0v = ((const float4*)z2)[lane];
    float4 b1v = ((const float4*)z2)[lane + 32];
    const float* xr = x + orow * DD;
    float4 x0 = ((const float4*)xr)[lane];
    float4 x1 = ((const float4*)xr)[lane + 32];
    float4 v0 = make_float4(x0.x + a0.x + b0v.x, x0.y + a0.y + b0v.y,
                            x0.z + a0.z + b0v.z, x0.w + a0.w + b0v.w);
    float4 v1 = make_float4(x1.x + a1.x + b1v.x, x1.y + a1.y + b1v.y,
                            x1.z + a1.z + b1v.z, x1.w + a1.w + b1v.w);

    ((float4*)(x2 + orow * DD))[lane]      = v0;
    ((float4*)(x2 + orow * DD))[lane + 32] = v1;

    float s  = v0.x + v0.y + v0.z + v0.w + v1.x + v1.y + v1.z + v1.w;
    float sq = v0.x*v0.x + v0.y*v0.y + v0.z*v0.z + v0.w*v0.w
             + v1.x*v1.x + v1.y*v1.y + v1.z*v1.z + v1.w*v1.w;
#pragma unroll
    for (int o = 16; o > 0; o >>= 1) {
        s  += __shfl_xor_sync(0xffffffffu, s,  o);
        sq += __shfl_xor_sync(0xffffffffu, sq, o);
    }
    float mean = s * (1.0f / 256.0f);
    float var  = sq * (1.0f / 256.0f) - mean * mean;
    float rstd = rsqrtf(var + 1e-5f);

    float4 g0 = ((const float4*)gamma)[lane];
    float4 g1 = ((const float4*)gamma)[lane + 32];
    float4 bb0 = ((const float4*)beta)[lane];
    float4 bb1 = ((const float4*)beta)[lane + 32];
    float4 o0, o1;
    o0.x = (v0.x - mean) * rstd * g0.x + bb0.x;
    o0.y = (v0.y - mean) * rstd * g0.y + bb0.y;
    o0.z = (v0.z - mean) * rstd * g0.z + bb0.z;
    o0.w = (v0.w - mean) * rstd * g0.w + bb0.w;
    o1.x = (v1.x - mean) * rstd * g1.x + bb1.x;
    o1.y = (v1.y - mean) * rstd * g1.y + bb1.y;
    o1.z = (v1.z - mean) * rstd * g1.z + bb1.z;
    o1.w = (v1.w - mean) * rstd * g1.w + bb1.w;
    store_split8(g_ln2sp + orow * 512, lane * 4, o0, o1);
}

// ---------------- launch ----------------
extern "C" void kernel_launch(void* const* d_in, const int* in_sizes, int n_in,
                              void* d_out, int out_size) {
    const float* x    = (const float*)d_in[0];
    const float* ln1w = (const float*)d_in[1];
    const float* ln1b = (const float*)d_in[2];
    const float* qw   = (const float*)d_in[3];
    const float* kw   = (const float*)d_in[4];
    const float* vw   = (const float*)d_in[5];
    const float* ow   = (const float*)d_in[6];
    const float* ln2w = (const float*)d_in[7];
    const float* ln2b = (const float*)d_in[8];
    const float* w1   = (const float*)d_in[9];
    const float* b1   = (const float*)d_in[10];
    const float* w2   = (const float*)d_in[11];
    const float* b2   = (const float*)d_in[12];
    float* out = (float*)d_out;

    bf16 *p_asp, *p_wsp, *p_w1sp, *p_w2sp, *p_ln2sp, *p_qkvsp;
    float *p_x2;
    cudaGetSymbolAddress((void**)&p_asp,   g_asp);
    cudaGetSymbolAddress((void**)&p_wsp,   g_wsp);
    cudaGetSymbolAddress((void**)&p_w1sp,  g_w1sp);
    cudaGetSymbolAddress((void**)&p_w2sp,  g_w2sp);
    cudaGetSymbolAddress((void**)&p_ln2sp, g_ln2sp);
    cudaGetSymbolAddress((void**)&p_qkvsp, g_qkvsp);
    cudaGetSymbolAddress((void**)&p_x2,    g_x2);

    cudaFuncSetAttribute(attn_mma_kernel, cudaFuncAttributeMaxDynamicSharedMemorySize,
                         ATTN_SMEM_B);
    cudaFuncSetAttribute(qkv_gemm_kernel, cudaFuncAttributeMaxDynamicSharedMemorySize, WGSMEM);
    cudaFuncSetAttribute(mlp_fused_kernel, cudaFuncAttributeMaxDynamicSharedMemorySize, MLPSMEM);

    // order chosen so launch #4 (profiled by ncu -s 5 -c 1) is the QKV GEMM
    prep_wqkv_kernel<<<QKVC, 256>>>(qw, kw, vw);                       // 1
    ln1_kernel<<<NTOK / 8, 256>>>(x, ln1w, ln1b);                      // 2
    prep_wt_kernel<<<256, 256>>>(w1, p_w1sp);                          // 3
    qkv_gemm_kernel<<<dim3(QKVC / 256, NTOK / 128), 256, WGSMEM>>>(    // 4
        p_asp, p_wsp, p_qkvsp);
    prep_so_kernel<<<256, 256>>>(ow);                                  // 5
    prep_wt_kernel<<<256, 256>>>(w2, p_w2sp);                          // 6
    attn_mma_kernel<<<1024, 256, ATTN_SMEM_B>>>();                     // 7
    zred_ln2_kernel<<<NTOK / 8, 256>>>(x, ln2w, ln2b, p_x2);           // 8
    mlp_fused_kernel<<<NTOK / 128, 256, MLPSMEM>>>(                    // 9
        p_ln2sp, p_w1sp, p_w2sp, b1, b2, p_x2, out);
}

// round 10
// speedup vs baseline: 2.3653x; 1.0047x over previous
#include <cuda_runtime.h>
#include <cuda_bf16.h>
#include <cstdint>
#include <cstddef>

typedef __nv_bfloat16 bf16;

// ---------------- problem constants ----------------
#define NTOK     32768
#define DD       256
#define QKVC     2560

// ---------------- static scratch ----------------
__device__ bf16 g_asp  [(size_t)NTOK * 512];
__device__ bf16 g_wsp  [(size_t)QKVC * 512];
__device__ bf16 g_w1sp [(size_t)DD * 512];
__device__ bf16 g_w2sp [(size_t)DD * 512];
__device__ bf16 g_ln2sp[(size_t)NTOK * 512];
__device__ bf16 g_qkvsp[(size_t)NTOK * 5120];
__device__ float g_z1  [(size_t)NTOK * DD];
__device__ float g_z2  [(size_t)NTOK * DD];
__device__ float g_so  [2048];
__device__ float g_x2  [(size_t)NTOK * DD];

// ---------------- helpers ----------------
__device__ __forceinline__ void bsplit(float v, bf16& h, bf16& l) {
    h = __float2bfloat16_rn(v);
    l = __float2bfloat16_rn(v - __bfloat162float(h));
}
__device__ __forceinline__ void cpasync16(uint32_t s, const void* g) {
    asm volatile("cp.async.cg.shared.global [%0], [%1], 16;\n" :: "r"(s), "l"(g));
}
__device__ __forceinline__ void mma16816(float* c, const uint32_t* a, const uint32_t* b) {
    asm volatile(
        "mma.sync.aligned.m16n8k16.row.col.f32.bf16.bf16.f32 "
        "{%0,%1,%2,%3},{%4,%5,%6,%7},{%8,%9},{%0,%1,%2,%3};\n"
        : "+f"(c[0]), "+f"(c[1]), "+f"(c[2]), "+f"(c[3])
        : "r"(a[0]), "r"(a[1]), "r"(a[2]), "r"(a[3]), "r"(b[0]), "r"(b[1]));
}
__device__ __forceinline__ void ldsm_x4(uint32_t* r, uint32_t a) {
    asm volatile("ldmatrix.sync.aligned.m8n8.x4.shared.b16 {%0,%1,%2,%3}, [%4];"
        : "=r"(r[0]), "=r"(r[1]), "=r"(r[2]), "=r"(r[3]) : "r"(a));
}
__device__ __forceinline__ void ldsm_x2(uint32_t* r, uint32_t a) {
    asm volatile("ldmatrix.sync.aligned.m8n8.x2.shared.b16 {%0,%1}, [%2];"
        : "=r"(r[0]), "=r"(r[1]) : "r"(a));
}
__device__ __forceinline__ void ldsm_x2t(uint32_t* r, uint32_t a) {
    asm volatile("ldmatrix.sync.aligned.m8n8.x2.trans.shared.b16 {%0,%1}, [%2];"
        : "=r"(r[0]), "=r"(r[1]) : "r"(a));
}

// ---------------- weight prep ----------------
__global__ void prep_wqkv_kernel(const float* __restrict__ q,
                                 const float* __restrict__ k,
                                 const float* __restrict__ v) {
    int idx = blockIdx.x * 256 + threadIdx.x;
    int d = idx & 255, j = idx >> 8;
    float val;
    if (j < 2048) { int h = j >> 8, kk = j & 255; val = q[((size_t)(h * 256 + d)) * 256 + kk]; }
    else if (j < 2304) val = k[(size_t)d * 256 + (j - 2048)];
    else               val = v[(size_t)d * 256 + (j - 2304)];
    bf16 h16, l16; bsplit(val, h16, l16);
    g_wsp[(size_t)j * 512 + d]       = h16;
    g_wsp[(size_t)j * 512 + 256 + d] = l16;
}

__global__ void prep_wt_kernel(const float* __restrict__ src, bf16* __restrict__ dst) {
    int idx = blockIdx.x * 256 + threadIdx.x;
    int d = idx & 255, j = idx >> 8;
    float val = src[(size_t)d * 256 + j];
    bf16 h16, l16; bsplit(val, h16, l16);
    dst[(size_t)j * 512 + d]       = h16;
    dst[(size_t)j * 512 + 256 + d] = l16;
}

__global__ void prep_so_kernel(const float* __restrict__ o) {
    int row  = (blockIdx.x * blockDim.x + threadIdx.x) >> 5;
    int lane = threadIdx.x & 31;
    const float* rp = o + (size_t)row * 256;
    float4 a = ((const float4*)rp)[lane];
    float4 b = ((const float4*)rp)[lane + 32];
    float s = a.x + a.y + a.z + a.w + b.x + b.y + b.z + b.w;
#pragma unroll
    for (int off = 16; off > 0; off >>= 1) s += __shfl_xor_sync(0xffffffffu, s, off);
    if (lane == 0) g_so[row] = s;
}

// ---------------- LN1 + block permute -> split bf16 ----------------
__device__ __forceinline__ void store_split8(bf16* rowp, int col, float4 v0, float4 v1) {
    bf16 h[8], l[8];
    bsplit(v0.x, h[0], l[0]); bsplit(v0.y, h[1], l[1]);
    bsplit(v0.z, h[2], l[2]); bsplit(v0.w, h[3], l[3]);
    bsplit(v1.x, h[4], l[4]); bsplit(v1.y, h[5], l[5]);
    bsplit(v1.z, h[6], l[6]); bsplit(v1.w, h[7], l[7]);
#pragma unroll
    for (int i = 0; i < 4; i++) {
        rowp[col + i]             = h[i];
        rowp[col + 128 + i]       = h[4 + i];
        rowp[256 + col + i]       = l[i];
        rowp[256 + col + 128 + i] = l[4 + i];
    }
}

__global__ void ln1_kernel(const float* __restrict__ in,
                           const float* __restrict__ gamma,
                           const float* __restrict__ beta) {
    int gwarp = (blockIdx.x * blockDim.x + threadIdx.x) >> 5;
    int lane  = threadIdx.x & 31;
    const float* row = in + (size_t)gwarp * DD;
    float4 v0 = ((const float4*)row)[lane];
    float4 v1 = ((const float4*)row)[lane + 32];
    float s  = v0.x + v0.y + v0.z + v0.w + v1.x + v1.y + v1.z + v1.w;
    float sq = v0.x*v0.x + v0.y*v0.y + v0.z*v0.z + v0.w*v0.w
             + v1.x*v1.x + v1.y*v1.y + v1.z*v1.z + v1.w*v1.w;
#pragma unroll
    for (int o = 16; o > 0; o >>= 1) {
        s  += __shfl_xor_sync(0xffffffffu, s,  o);
        sq += __shfl_xor_sync(0xffffffffu, sq, o);
    }
    float mean = s * (1.0f / 256.0f);
    float var  = sq * (1.0f / 256.0f) - mean * mean;
    float rstd = rsqrtf(var + 1e-5f);

    int b = gwarp >> 12, pos = gwarp & 4095;
    int h = pos >> 6, w = pos & 63;
    int m = ((h & 7) << 3) | (w & 7);
    int n = ((h >> 3) << 3) | (w >> 3);
    size_t orow = ((size_t)b << 12) | (unsigned)((m << 6) | n);

    float4 g0 = ((const float4*)gamma)[lane];
    float4 g1 = ((const float4*)gamma)[lane + 32];
    float4 b0 = ((const float4*)beta)[lane];
    float4 b1 = ((const float4*)beta)[lane + 32];
    float4 o0, o1;
    o0.x = (v0.x - mean) * rstd * g0.x + b0.x;
    o0.y = (v0.y - mean) * rstd * g0.y + b0.y;
    o0.z = (v0.z - mean) * rstd * g0.z + b0.z;
    o0.w = (v0.w - mean) * rstd * g0.w + b0.w;
    o1.x = (v1.x - mean) * rstd * g1.x + b1.x;
    o1.y = (v1.y - mean) * rstd * g1.y + b1.y;
    o1.z = (v1.z - mean) * rstd * g1.z + b1.z;
    o1.w = (v1.w - mean) * rstd * g1.w + b1.w;
    store_split8(g_asp + orow * 512, lane * 4, o0, o1);
}

// ================= QKV GEMM: R8-proven 128x128 tile, 3-term split, ldmatrix =================
#define GP 40
#define MATB (128 * GP * 2)            // 10240 B
#define STAGEB (4 * MATB)              // 40960 B
#define GSMEM (2 * STAGEB)             // 81920 B

__global__ __launch_bounds__(256, 2)
void qkv_gemm_kernel(const bf16* __restrict__ Asp,
                     const bf16* __restrict__ Bsp,
                     bf16* __restrict__ Csp) {
    extern __shared__ bf16 smem[];
    uint32_t sb = (uint32_t)__cvta_generic_to_shared(smem);

    int tid = threadIdx.x;
    int lane = tid & 31, warp = tid >> 5;
    int wm = warp & 1, wn = warp >> 1;
    int g = lane >> 2, tig = lane & 3;
    int lrow8 = lane & 7, l8 = (lane >> 3) & 1, l16 = (lane >> 4) & 1;
    int rowBase = blockIdx.y * 128;
    int colBase = blockIdx.x * 128;

    uint32_t aoff = (uint32_t)(((wm * 64 + lrow8 + 8 * l8) * GP + 8 * l16) * 2);
    uint32_t boff = (uint32_t)(((wn * 32 + lrow8) * GP + 8 * l8) * 2);

    float acc[4][4][4] = {};

    auto load_chunk = [&](int c, int st) {
        const bf16* Ag = Asp + (size_t)rowBase * 512 + c * 32;
        const bf16* Bg = Bsp + (size_t)colBase * 512 + c * 32;
        uint32_t base = sb + (uint32_t)st * STAGEB;
#pragma unroll
        for (int i = 0; i < 2; i++) {
            int f = tid + i * 256;
            int r = f >> 2, q = f & 3;
            uint32_t so = (uint32_t)(r * GP + q * 8) * 2;
            const bf16* ga = Ag + (size_t)r * 512 + q * 8;
            const bf16* gb = Bg + (size_t)r * 512 + q * 8;
            cpasync16(base + so,            ga);
            cpasync16(base + MATB + so,     ga + 256);
            cpasync16(base + 2 * MATB + so, gb);
            cpasync16(base + 3 * MATB + so, gb + 256);
        }
        asm volatile("cp.async.commit_group;\n");
    };

    load_chunk(0, 0);
    const int NCH = 8;
    for (int c = 0; c < NCH; c++) {
        if (c + 1 < NCH) {
            load_chunk(c + 1, (c + 1) & 1);
            asm volatile("cp.async.wait_group 1;\n");
        } else {
            asm volatile("cp.async.wait_group 0;\n");
        }
        __syncthreads();

        uint32_t stb = sb + (uint32_t)(c & 1) * STAGEB;
#pragma unroll
        for (int ks = 0; ks < 2; ks++) {
            uint32_t kb2 = ks * 32;
            uint32_t ahi[4][4], alo[4][4];
#pragma unroll
            for (int mi = 0; mi < 4; mi++) {
                uint32_t a = stb + aoff + mi * (16 * GP * 2) + kb2;
                ldsm_x4(ahi[mi], a);
                ldsm_x4(alo[mi], a + MATB);
            }
#pragma unroll
            for (int ni = 0; ni < 4; ni++) {
                uint32_t ba = stb + 2 * MATB + boff + ni * (8 * GP * 2) + kb2;
                uint32_t bh[2], bl[2];
                ldsm_x2(bh, ba);
                ldsm_x2(bl, ba + MATB);
#pragma unroll
                for (int mi = 0; mi < 4; mi++) {
                    mma16816(acc[mi][ni], ahi[mi], bh);
                    mma16816(acc[mi][ni], alo[mi], bh);
                    mma16816(acc[mi][ni], ahi[mi], bl);
                }
            }
        }
        __syncthreads();
    }

#pragma unroll
    for (int mi = 0; mi < 4; mi++) {
        int r0 = rowBase + wm * 64 + mi * 16 + g;
        int r1 = r0 + 8;
#pragma unroll
        for (int ni = 0; ni < 4; ni++) {
            int col = colBase + wn * 32 + ni * 8 + tig * 2;
            bf16 h0, l0, h1, l1;
            bsplit(acc[mi][ni][0], h0, l0); bsplit(acc[mi][ni][1], h1, l1);
            *(__nv_bfloat162*)(Csp + (size_t)r0 * 5120 + col)        = __nv_bfloat162(h0, h1);
            *(__nv_bfloat162*)(Csp + (size_t)r0 * 5120 + 2560 + col) = __nv_bfloat162(l0, l1);
            bsplit(acc[mi][ni][2], h0, l0); bsplit(acc[mi][ni][3], h1, l1);
            *(__nv_bfloat162*)(Csp + (size_t)r1 * 5120 + col)        = __nv_bfloat162(h0, h1);
            *(__nv_bfloat162*)(Csp + (size_t)r1 * 5120 + 2560 + col) = __nv_bfloat162(l0, l1);
        }
    }
}

// ================= fused MLP (R9-proven): h = relu(LN2 W1+b1) smem; out = h W2+b2+x2 =================
#define WGP 40
#define A_PL (128 * WGP * 2)            // 10240 B
#define B_PL (256 * WGP * 2)            // 20480 B
#define WSTAGE (2 * A_PL + 2 * B_PL)    // 61440 B
#define HP 264
#define HPLANE (128 * HP * 2)            // 67584 B
#define W2S0 (2 * HPLANE)                // 135168
#define W2STG (2 * B_PL)                 // 40960
#define MLPSMEM (W2S0 + 2 * W2STG)       // 217088

__global__ __launch_bounds__(256, 1)
void mlp_fused_kernel(const bf16* __restrict__ ln2sp,
                      const bf16* __restrict__ w1sp,
                      const bf16* __restrict__ w2sp,
                      const float* __restrict__ b1,
                      const float* __restrict__ b2,
                      const float* __restrict__ x2,
                      float* __restrict__ out) {
    extern __shared__ bf16 smem[];
    uint32_t sb = (uint32_t)__cvta_generic_to_shared(smem);

    int tid = threadIdx.x;
    int lane = tid & 31, warp = tid >> 5;
    int wm = warp & 1, wn = warp >> 1;
    int g = lane >> 2, tig = lane & 3;
    int lrow8 = lane & 7, l8 = (lane >> 3) & 1, l16 = (lane >> 4) & 1;
    int rowBase = blockIdx.x * 128;

    uint32_t aoff = (uint32_t)(((wm * 64 + lrow8 + 8 * l8) * WGP + 8 * l16) * 2);
    uint32_t boff = (uint32_t)(((wn * 64 + lrow8) * WGP + 8 * l8) * 2);
    uint32_t hoff = (uint32_t)(((wm * 64 + lrow8 + 8 * l8) * HP + 8 * l16) * 2);

    float acc[4][8][4] = {};

    auto load1 = [&](int c, int st) {
        const bf16* Ag = ln2sp + (size_t)rowBase * 512 + c * 32;
        const bf16* Bg = w1sp + c * 32;
        uint32_t base = sb + (uint32_t)st * WSTAGE;
#pragma unroll
        for (int i = 0; i < 2; i++) {
            int f = tid + i * 256;
            int r = f >> 2, q = f & 3;
            uint32_t so = (uint32_t)(r * WGP + q * 8) * 2;
            const bf16* ga = Ag + (size_t)r * 512 + q * 8;
            cpasync16(base + so,        ga);
            cpasync16(base + A_PL + so, ga + 256);
        }
#pragma unroll
        for (int i = 0; i < 4; i++) {
            int f = tid + i * 256;
            int r = f >> 2, q = f & 3;
            uint32_t so = (uint32_t)(r * WGP + q * 8) * 2;
            const bf16* gb = Bg + (size_t)r * 512 + q * 8;
            cpasync16(base + 2 * A_PL + so,        gb);
            cpasync16(base + 2 * A_PL + B_PL + so, gb + 256);
        }
        asm volatile("cp.async.commit_group;\n");
    };
    auto load2 = [&](int c, int st) {
        const bf16* Bg = w2sp + c * 32;
        uint32_t base = sb + W2S0 + (uint32_t)st * W2STG;
#pragma unroll
        for (int i = 0; i < 4; i++) {
            int f = tid + i * 256;
            int r = f >> 2, q = f & 3;
            uint32_t so = (uint32_t)(r * WGP + q * 8) * 2;
            const bf16* gb = Bg + (size_t)r * 512 + q * 8;
            cpasync16(base + so,        gb);
            cpasync16(base + B_PL + so, gb + 256);
        }
        asm volatile("cp.async.commit_group;\n");
    };

    // phase 1
    load1(0, 0);
    for (int c = 0; c < 8; c++) {
        if (c + 1 < 8) {
            load1(c + 1, (c + 1) & 1);
            asm volatile("cp.async.wait_group 1;\n");
        } else {
            asm volatile("cp.async.wait_group 0;\n");
        }
        __syncthreads();
        uint32_t stb = sb + (uint32_t)(c & 1) * WSTAGE;
#pragma unroll
        for (int ks = 0; ks < 2; ks++) {
            uint32_t kb2 = ks * 32;
            uint32_t ahi[4][4], alo[4][4];
#pragma unroll
            for (int mi = 0; mi < 4; mi++) {
                uint32_t a = stb + aoff + mi * (16 * WGP * 2) + kb2;
                ldsm_x4(ahi[mi], a);
                ldsm_x4(alo[mi], a + A_PL);
            }
#pragma unroll
            for (int ni = 0; ni < 8; ni++) {
                uint32_t ba = stb + 2 * A_PL + boff + ni * (8 * WGP * 2) + kb2;
                uint32_t bh[2], bl[2];
                ldsm_x2(bh, ba);
                ldsm_x2(bl, ba + B_PL);
#pragma unroll
                for (int mi = 0; mi < 4; mi++) {
                    mma16816(acc[mi][ni], ahi[mi], bh);
                    mma16816(acc[mi][ni], alo[mi], bh);
                    mma16816(acc[mi][ni], ahi[mi], bl);
                }
            }
        }
        __syncthreads();
    }

    load2(0, 0);

    bf16* hhi = smem;
    bf16* hlo = smem + 128 * HP;
#pragma unroll
    for (int mi = 0; mi < 4; mi++) {
        int r0 = wm * 64 + mi * 16 + g;
        int r1 = r0 + 8;
#pragma unroll
        for (int ni = 0; ni < 8; ni++) {
            int col = wn * 64 + ni * 8 + tig * 2;
            float2 bv = *(const float2*)(b1 + col);
            float v0 = fmaxf(acc[mi][ni][0] + bv.x, 0.f);
            float v1 = fmaxf(acc[mi][ni][1] + bv.y, 0.f);
            float v2 = fmaxf(acc[mi][ni][2] + bv.x, 0.f);
            float v3 = fmaxf(acc[mi][ni][3] + bv.y, 0.f);
            bf16 h0, l0, h1, l1;
            bsplit(v0, h0, l0); bsplit(v1, h1, l1);
            *(__nv_bfloat162*)(hhi + r0 * HP + col) = __nv_bfloat162(h0, h1);
            *(__nv_bfloat162*)(hlo + r0 * HP + col) = __nv_bfloat162(l0, l1);
            bsplit(v2, h0, l0); bsplit(v3, h1, l1);
            *(__nv_bfloat162*)(hhi + r1 * HP + col) = __nv_bfloat162(h0, h1);
            *(__nv_bfloat162*)(hlo + r1 * HP + col) = __nv_bfloat162(l0, l1);
            acc[mi][ni][0] = 0.f; acc[mi][ni][1] = 0.f;
            acc[mi][ni][2] = 0.f; acc[mi][ni][3] = 0.f;
        }
    }
    __syncthreads();

    // phase 2
    for (int c = 0; c < 8; c++) {
        if (c + 1 < 8) {
            load2(c + 1, (c + 1) & 1);
            asm volatile("cp.async.wait_group 1;\n");
        } else {
            asm volatile("cp.async.wait_group 0;\n");
        }
        __syncthreads();
        uint32_t w2b = sb + W2S0 + (uint32_t)(c & 1) * W2STG;
#pragma unroll
        for (int ks = 0; ks < 2; ks++) {
            uint32_t kbyte = (uint32_t)((c * 32 + ks * 16) * 2);
            uint32_t kb2 = ks * 32;
            uint32_t ahi[4][4], alo[4][4];
#pragma unroll
            for (int mi = 0; mi < 4; mi++) {
                uint32_t a = sb + hoff + mi * (16 * HP * 2) + kbyte;
                ldsm_x4(ahi[mi], a);
                ldsm_x4(alo[mi], a + HPLANE);
            }
#pragma unroll
            for (int ni = 0; ni < 8; ni++) {
                uint32_t ba = w2b + boff + ni * (8 * WGP * 2) + kb2;
                uint32_t bh[2], bl[2];
                ldsm_x2(bh, ba);
                ldsm_x2(bl, ba + B_PL);
#pragma unroll
                for (int mi = 0; mi < 4; mi++) {
                    mma16816(acc[mi][ni], ahi[mi], bh);
                    mma16816(acc[mi][ni], alo[mi], bh);
                    mma16816(acc[mi][ni], ahi[mi], bl);
                }
            }
        }
        __syncthreads();
    }

#pragma unroll
    for (int mi = 0; mi < 4; mi++) {
        int r0 = rowBase + wm * 64 + mi * 16 + g;
        int r1 = r0 + 8;
#pragma unroll
        for (int ni = 0; ni < 8; ni++) {
            int col = wn * 64 + ni * 8 + tig * 2;
            float2 bv = *(const float2*)(b2 + col);
            float2 e0 = *(const float2*)(x2 + (size_t)r0 * DD + col);
            float2 e1 = *(const float2*)(x2 + (size_t)r1 * DD + col);
            float2 v0 = make_float2(acc[mi][ni][0] + bv.x + e0.x,
                                    acc[mi][ni][1] + bv.y + e0.y);
            float2 v1 = make_float2(acc[mi][ni][2] + bv.x + e1.x,
                                    acc[mi][ni][3] + bv.y + e1.y);
            *(float2*)(out + (size_t)r0 * DD + col) = v0;
            *(float2*)(out + (size_t)r1 * DD + col) = v1;
        }
    }
}

// ================= tensor-core attention + fused head-mix (R8) =================
#define TP 264
#define PP 72
#define TILE_E (64 * TP)
#define TEB (TILE_E * 2)
#define PPB (64 * PP * 2)
#define ATTN_SMEM_B (6 * TEB + 2 * PPB + 1024)

__global__ __launch_bounds__(256)
void attn_mma_kernel() {
    extern __shared__ bf16 asm_[];
    bf16* Ph = asm_ + 6 * TILE_E;
    bf16* Pl = Ph + 64 * PP;
    float* stmax = (float*)(Pl + 64 * PP);
    float* stsum = stmax + 128;
    uint32_t sbase = (uint32_t)__cvta_generic_to_shared(asm_);

    int tid = threadIdx.x;
    int lane = tid & 31, warp = tid >> 5;
    int g = lane >> 2, tig = lane & 3;
    int lrow8 = lane & 7, l8 = (lane >> 3) & 1, l16 = (lane >> 4) & 1;

    int u = blockIdx.x;
    bool gridmode = (u < 512);
    int b, fix;
    if (gridmode) { b = u >> 6; fix = u & 63; }
    else          { int u2 = u - 512; b = u2 >> 6; fix = u2 & 63; }
    size_t base; int stride;
    if (gridmode) { base = (size_t)b * 4096 + fix; stride = 64; }
    else          { base = (size_t)b * 4096 + (size_t)fix * 64; stride = 1; }
    int head0 = gridmode ? 0 : 4;

    auto load_piece = [&](int planeIdx, int colOff) {
        uint32_t sh = sbase + (uint32_t)planeIdx * TEB;
#pragma unroll
        for (int i = 0; i < 8; i++) {
            int f = i * 256 + tid;
            int r = f >> 5, q = f & 31;
            size_t token = base + (size_t)r * stride;
            const bf16* ga = g_qkvsp + token * 5120 + colOff + q * 8;
            uint32_t so = (uint32_t)(r * TP + q * 8) * 2;
            cpasync16(sh + so, ga);
            cpasync16(sh + TEB + so, ga + 2560);
        }
    };

    load_piece(2, 2048);
    load_piece(4, 2304);
    load_piece(0, head0 * 256);
    asm volatile("cp.async.commit_group;\n");
    asm volatile("cp.async.wait_group 0;\n");
    __syncthreads();

    int warpm = warp >> 1, warpn = warp & 1;
    int row0 = warpm * 16 + g, row1 = row0 + 8;

    uint32_t qoff = (uint32_t)(((warpm * 16 + lrow8 + 8 * l8) * TP + 8 * l16) * 2);
    uint32_t koff = (uint32_t)(((warpn * 32 + lrow8) * TP + 8 * l8) * 2);
    uint32_t poff = (uint32_t)(((warpm * 16 + lrow8 + 8 * l8) * PP + 8 * l16) * 2);
    uint32_t voff = (uint32_t)(((lrow8 + 8 * l8) * TP) * 2);
    uint32_t PB = sbase + 6 * TEB;
    uint32_t KB = sbase + 2 * TEB;
    uint32_t VB = sbase + 4 * TEB;

    float zacc[16][4] = {};

    for (int hl = 0; hl < 4; hl++) {
        int head = head0 + hl;

        float c[4][4] = {};
#pragma unroll 4
        for (int ks = 0; ks < 16; ks++) {
            uint32_t kb2 = ks * 32;
            uint32_t ahi[4], alo[4];
            ldsm_x4(ahi, sbase + qoff + kb2);
            ldsm_x4(alo, sbase + TEB + qoff + kb2);
#pragma unroll
            for (int ni = 0; ni < 4; ni++) {
                uint32_t ba = KB + koff + ni * (8 * TP * 2) + kb2;
                uint32_t bh[2], bl[2];
                ldsm_x2(bh, ba);
                ldsm_x2(bl, ba + TEB);
                mma16816(c[ni], ahi, bh);
                mma16816(c[ni], alo, bh);
                mma16816(c[ni], ahi, bl);
            }
        }

        float m0 = -1e30f, m1 = -1e30f;
#pragma unroll
        for (int ni = 0; ni < 4; ni++) {
            m0 = fmaxf(m0, fmaxf(c[ni][0], c[ni][1]));
            m1 = fmaxf(m1, fmaxf(c[ni][2], c[ni][3]));
        }
        m0 = fmaxf(m0, __shfl_xor_sync(0xffffffffu, m0, 1));
        m0 = fmaxf(m0, __shfl_xor_sync(0xffffffffu, m0, 2));
        m1 = fmaxf(m1, __shfl_xor_sync(0xffffffffu, m1, 1));
        m1 = fmaxf(m1, __shfl_xor_sync(0xffffffffu, m1, 2));
        if (tig == 0) {
            stmax[row0 * 2 + warpn] = m0;
            stmax[row1 * 2 + warpn] = m1;
        }
        __syncthreads();
        m0 = fmaxf(stmax[row0 * 2], stmax[row0 * 2 + 1]);
        m1 = fmaxf(stmax[row1 * 2], stmax[row1 * 2 + 1]);
        float s0 = 0.f, s1 = 0.f;
#pragma unroll
        for (int ni = 0; ni < 4; ni++) {
            c[ni][0] = __expf(c[ni][0] - m0);
            c[ni][1] = __expf(c[ni][1] - m0);
            c[ni][2] = __expf(c[ni][2] - m1);
            c[ni][3] = __expf(c[ni][3] - m1);
            s0 += c[ni][0] + c[ni][1];
            s1 += c[ni][2] + c[ni][3];
        }
        s0 += __shfl_xor_sync(0xffffffffu, s0, 1);
        s0 += __shfl_xor_sync(0xffffffffu, s0, 2);
        s1 += __shfl_xor_sync(0xffffffffu, s1, 1);
        s1 += __shfl_xor_sync(0xffffffffu, s1, 2);
        if (tig == 0) {
            stsum[row0 * 2 + warpn] = s0;
            stsum[row1 * 2 + warpn] = s1;
        }
        __syncthreads();
        float inv0 = 1.0f / (stsum[row0 * 2] + stsum[row0 * 2 + 1]);
        float inv1 = 1.0f / (stsum[row1 * 2] + stsum[row1 * 2 + 1]);
#pragma unroll
        for (int ni = 0; ni < 4; ni++) {
            int cn = warpn * 32 + ni * 8 + 2 * tig;
            bf16 h0, l0, h1, l1;
            bsplit(c[ni][0] * inv0, h0, l0); bsplit(c[ni][1] * inv0, h1, l1);
            *(__nv_bfloat162*)(Ph + row0 * PP + cn) = __nv_bfloat162(h0, h1);
            *(__nv_bfloat162*)(Pl + row0 * PP + cn) = __nv_bfloat162(l0, l1);
            bsplit(c[ni][2] * inv1, h0, l0); bsplit(c[ni][3] * inv1, h1, l1);
            *(__nv_bfloat162*)(Ph + row1 * PP + cn) = __nv_bfloat162(h0, h1);
            *(__nv_bfloat162*)(Pl + row1 * PP + cn) = __nv_bfloat162(l0, l1);
        }
        __syncthreads();

        if (hl < 3) {
            load_piece(0, (head + 1) * 256);
            asm volatile("cp.async.commit_group;\n");
        }

        const float* sop = g_so + head * 256;
#pragma unroll
        for (int ks = 0; ks < 4; ks++) {
            uint32_t kb2 = ks * 32;
            uint32_t ph[4], pl[4];
            ldsm_x4(ph, PB + poff + kb2);
            ldsm_x4(pl, PB + PPB + poff + kb2);
            uint32_t vrow = VB + voff + (uint32_t)ks * (16 * TP * 2);
#pragma unroll
            for (int ni = 0; ni < 16; ni++) {
                uint32_t va = vrow + (uint32_t)((warpn * 128 + ni * 8) * 2);
                uint32_t bh[2], bl[2];
                ldsm_x2t(bh, va);
                ldsm_x2t(bl, va + TEB);
                float ot[4] = {};
                mma16816(ot, ph, bh);
                mma16816(ot, pl, bh);
                mma16816(ot, ph, bl);
                float2 sv = *(const float2*)(sop + warpn * 128 + ni * 8 + 2 * tig);
                zacc[ni][0] += ot[0] * sv.x; zacc[ni][1] += ot[1] * sv.y;
                zacc[ni][2] += ot[2] * sv.x; zacc[ni][3] += ot[3] * sv.y;
            }
        }

        if (hl < 3) asm volatile("cp.async.wait_group 0;\n");
        __syncthreads();
    }

    float* gz = gridmode ? g_z1 : g_z2;
    size_t tok0 = base + (size_t)row0 * stride;
    size_t tok1 = base + (size_t)row1 * stride;
#pragma unroll
    for (int ni = 0; ni < 16; ni++) {
        int col = warpn * 128 + ni * 8 + 2 * tig;
        *(float2*)(gz + tok0 * DD + col) = make_float2(zacc[ni][0], zacc[ni][1]);
        *(float2*)(gz + tok1 * DD + col) = make_float2(zacc[ni][2], zacc[ni][3]);
    }
}

// ---------- z1+z2 + unpermute + residual + LN2 -> split bf16 ----------
__global__ void zred_ln2_kernel(const float* __restrict__ x,
                                const float* __restrict__ gamma,
                                const float* __restrict__ beta,
                                float* __restrict__ x2) {
    int gw   = (blockIdx.x * blockDim.x + threadIdx.x) >> 5;
    int lane = threadIdx.x & 31;

    int b = gw >> 12, m = (gw >> 6) & 63, n = gw & 63;
    int hh = ((n >> 3) << 3) | (m >> 3);
    int ww = ((n & 7) << 3) | (m & 7);
    size_t orow = ((size_t)b << 12) | (unsigned)((hh << 6) | ww);

    const float* z1 = g_z1 + (size_t)gw * DD;
    const float* z2 = g_z2 + (size_t)gw * DD;
    float4 a0 = ((const float4*)z1)[lane];
    float4 a1 = ((const float4*)z1)[lane + 32];
    float4 b0v = ((const float4*)z2)[lane];
    float4 b1v = ((const float4*)z2)[lane + 32];
    const float* xr = x + orow * DD;
    float4 x0 = ((const float4*)xr)[lane];
    float4 x1 = ((const float4*)xr)[lane + 32];
    float4 v0 = make_float4(x0.x + a0.x + b0v.x, x0.y + a0.y + b0v.y,
                            x0.z + a0.z + b0v.z, x0.w + a0.w + b0v.w);
    float4 v1 = make_float4(x1.x + a1.x + b1v.x, x1.y + a1.y + b1v.y,
                            x1.z + a1.z + b1v.z, x1.w + a1.w + b1v.w);

    ((float4*)(x2 + orow * DD))[lane]      = v0;
    ((float4*)(x2 + orow * DD))[lane + 32] = v1;

    float s  = v0.x + v0.y + v0.z + v0.w + v1.x + v1.y + v1.z + v1.w;
    float sq = v0.x*v0.x + v0.y*v0.y + v0.z*v0.z + v0.w*v0.w
             + v1.x*v1.x + v1.y*v1.y + v1.z*v1.z + v1.w*v1.w;
#pragma unroll
    for (int o = 16; o > 0; o >>= 1) {
        s  += __shfl_xor_sync(0xffffffffu, s,  o);
        sq += __shfl_xor_sync(0xffffffffu, sq, o);
    }
    float mean = s * (1.0f / 256.0f);
    float var  = sq * (1.0f / 256.0f) - mean * mean;
    float rstd = rsqrtf(var + 1e-5f);

    float4 g0 = ((const float4*)gamma)[lane];
    float4 g1 = ((const float4*)gamma)[lane + 32];
    float4 bb0 = ((const float4*)beta)[lane];
    float4 bb1 = ((const float4*)beta)[lane + 32];
    float4 o0, o1;
    o0.x = (v0.x - mean) * rstd * g0.x + bb0.x;
    o0.y = (v0.y - mean) * rstd * g0.y + bb0.y;
    o0.z = (v0.z - mean) * rstd * g0.z + bb0.z;
    o0.w = (v0.w - mean) * rstd * g0.w + bb0.w;
    o1.x = (v1.x - mean) * rstd * g1.x + bb1.x;
    o1.y = (v1.y - mean) * rstd * g1.y + bb1.y;
    o1.z = (v1.z - mean) * rstd * g1.z + bb1.z;
    o1.w = (v1.w - mean) * rstd * g1.w + bb1.w;
    store_split8(g_ln2sp + orow * 512, lane * 4, o0, o1);
}

// ---------------- launch ----------------
extern "C" void kernel_launch(void* const* d_in, const int* in_sizes, int n_in,
                              void* d_out, int out_size) {
    const float* x    = (const float*)d_in[0];
    const float* ln1w = (const float*)d_in[1];
    const float* ln1b = (const float*)d_in[2];
    const float* qw   = (const float*)d_in[3];
    const float* kw   = (const float*)d_in[4];
    const float* vw   = (const float*)d_in[5];
    const float* ow   = (const float*)d_in[6];
    const float* ln2w = (const float*)d_in[7];
    const float* ln2b = (const float*)d_in[8];
    const float* w1   = (const float*)d_in[9];
    const float* b1   = (const float*)d_in[10];
    const float* w2   = (const float*)d_in[11];
    const float* b2   = (const float*)d_in[12];
    float* out = (float*)d_out;

    bf16 *p_asp, *p_wsp, *p_w1sp, *p_w2sp, *p_ln2sp, *p_qkvsp;
    float *p_x2;
    cudaGetSymbolAddress((void**)&p_asp,   g_asp);
    cudaGetSymbolAddress((void**)&p_wsp,   g_wsp);
    cudaGetSymbolAddress((void**)&p_w1sp,  g_w1sp);
    cudaGetSymbolAddress((void**)&p_w2sp,  g_w2sp);
    cudaGetSymbolAddress((void**)&p_ln2sp, g_ln2sp);
    cudaGetSymbolAddress((void**)&p_qkvsp, g_qkvsp);
    cudaGetSymbolAddress((void**)&p_x2,    g_x2);

    cudaFuncSetAttribute(attn_mma_kernel, cudaFuncAttributeMaxDynamicSharedMemorySize,
                         ATTN_SMEM_B);
    cudaFuncSetAttribute(qkv_gemm_kernel, cudaFuncAttributeMaxDynamicSharedMemorySize, GSMEM);
    cudaFuncSetAttribute(mlp_fused_kernel, cudaFuncAttributeMaxDynamicSharedMemorySize, MLPSMEM);

    // launch #4 = QKV GEMM (profiled by ncu -s 5 -c 1)
    prep_wqkv_kernel<<<QKVC, 256>>>(qw, kw, vw);                       // 1
    ln1_kernel<<<NTOK / 8, 256>>>(x, ln1w, ln1b);                      // 2
    prep_wt_kernel<<<256, 256>>>(w1, p_w1sp);                          // 3
    qkv_gemm_kernel<<<dim3(QKVC / 128, NTOK / 128), 256, GSMEM>>>(     // 4
        p_asp, p_wsp, p_qkvsp);
    prep_so_kernel<<<256, 256>>>(ow);                                  // 5
    prep_wt_kernel<<<256, 256>>>(w2, p_w2sp);                          // 6
    attn_mma_kernel<<<1024, 256, ATTN_SMEM_B>>>();                     // 7
    zred_ln2_kernel<<<NTOK / 8, 256>>>(x, ln2w, ln2b, p_x2);           // 8
    mlp_fused_kernel<<<NTOK / 128, 256, MLPSMEM>>>(                    // 9
        p_ln2sp, p_w1sp, p_w2sp, b1, b2, p_x2, out);
}

// round 11
// speedup vs baseline: 2.4017x; 1.0154x over previous
#include <cuda_runtime.h>
#include <cuda_bf16.h>
#include <cstdint>
#include <cstddef>

typedef __nv_bfloat16 bf16;

// ---------------- problem constants ----------------
#define NTOK     32768
#define DD       256
#define QKVC     2560

// ---------------- static scratch ----------------
__device__ bf16 g_asp  [(size_t)NTOK * 512];
__device__ bf16 g_wsp  [(size_t)QKVC * 512];
__device__ bf16 g_w1sp [(size_t)DD * 512];
__device__ bf16 g_w2sp [(size_t)DD * 512];
__device__ bf16 g_ln2sp[(size_t)NTOK * 512];
__device__ bf16 g_qkvsp[(size_t)NTOK * 5120];
__device__ float g_z1  [(size_t)NTOK * DD];
__device__ float g_z2  [(size_t)NTOK * DD];
__device__ float g_so  [2048];
__device__ float g_x2  [(size_t)NTOK * DD];

// ---------------- helpers ----------------
__device__ __forceinline__ void bsplit(float v, bf16& h, bf16& l) {
    h = __float2bfloat16_rn(v);
    l = __float2bfloat16_rn(v - __bfloat162float(h));
}
__device__ __forceinline__ void cpasync16(uint32_t s, const void* g) {
    asm volatile("cp.async.cg.shared.global [%0], [%1], 16;\n" :: "r"(s), "l"(g));
}
__device__ __forceinline__ void mma16816(float* c, const uint32_t* a, const uint32_t* b) {
    asm volatile(
        "mma.sync.aligned.m16n8k16.row.col.f32.bf16.bf16.f32 "
        "{%0,%1,%2,%3},{%4,%5,%6,%7},{%8,%9},{%0,%1,%2,%3};\n"
        : "+f"(c[0]), "+f"(c[1]), "+f"(c[2]), "+f"(c[3])
        : "r"(a[0]), "r"(a[1]), "r"(a[2]), "r"(a[3]), "r"(b[0]), "r"(b[1]));
}
__device__ __forceinline__ void ldsm_x4(uint32_t* r, uint32_t a) {
    asm volatile("ldmatrix.sync.aligned.m8n8.x4.shared.b16 {%0,%1,%2,%3}, [%4];"
        : "=r"(r[0]), "=r"(r[1]), "=r"(r[2]), "=r"(r[3]) : "r"(a));
}
__device__ __forceinline__ void ldsm_x2(uint32_t* r, uint32_t a) {
    asm volatile("ldmatrix.sync.aligned.m8n8.x2.shared.b16 {%0,%1}, [%2];"
        : "=r"(r[0]), "=r"(r[1]) : "r"(a));
}
__device__ __forceinline__ void ldsm_x2t(uint32_t* r, uint32_t a) {
    asm volatile("ldmatrix.sync.aligned.m8n8.x2.trans.shared.b16 {%0,%1}, [%2];"
        : "=r"(r[0]), "=r"(r[1]) : "r"(a));
}

// ---------------- weight prep ----------------
__global__ void prep_wqkv_kernel(const float* __restrict__ q,
                                 const float* __restrict__ k,
                                 const float* __restrict__ v) {
    int idx = blockIdx.x * 256 + threadIdx.x;
    int d = idx & 255, j = idx >> 8;
    float val;
    if (j < 2048) { int h = j >> 8, kk = j & 255; val = q[((size_t)(h * 256 + d)) * 256 + kk]; }
    else if (j < 2304) val = k[(size_t)d * 256 + (j - 2048)];
    else               val = v[(size_t)d * 256 + (j - 2304)];
    bf16 h16, l16; bsplit(val, h16, l16);
    g_wsp[(size_t)j * 512 + d]       = h16;
    g_wsp[(size_t)j * 512 + 256 + d] = l16;
}

__global__ void prep_wt_kernel(const float* __restrict__ src, bf16* __restrict__ dst) {
    int idx = blockIdx.x * 256 + threadIdx.x;
    int d = idx & 255, j = idx >> 8;
    float val = src[(size_t)d * 256 + j];
    bf16 h16, l16; bsplit(val, h16, l16);
    dst[(size_t)j * 512 + d]       = h16;
    dst[(size_t)j * 512 + 256 + d] = l16;
}

__global__ void prep_so_kernel(const float* __restrict__ o) {
    int row  = (blockIdx.x * blockDim.x + threadIdx.x) >> 5;
    int lane = threadIdx.x & 31;
    const float* rp = o + (size_t)row * 256;
    float4 a = ((const float4*)rp)[lane];
    float4 b = ((const float4*)rp)[lane + 32];
    float s = a.x + a.y + a.z + a.w + b.x + b.y + b.z + b.w;
#pragma unroll
    for (int off = 16; off > 0; off >>= 1) s += __shfl_xor_sync(0xffffffffu, s, off);
    if (lane == 0) g_so[row] = s;
}

// ---------------- LN1 + block permute -> split bf16 ----------------
__device__ __forceinline__ void store_split8(bf16* rowp, int col, float4 v0, float4 v1) {
    bf16 h[8], l[8];
    bsplit(v0.x, h[0], l[0]); bsplit(v0.y, h[1], l[1]);
    bsplit(v0.z, h[2], l[2]); bsplit(v0.w, h[3], l[3]);
    bsplit(v1.x, h[4], l[4]); bsplit(v1.y, h[5], l[5]);
    bsplit(v1.z, h[6], l[6]); bsplit(v1.w, h[7], l[7]);
#pragma unroll
    for (int i = 0; i < 4; i++) {
        rowp[col + i]             = h[i];
        rowp[col + 128 + i]       = h[4 + i];
        rowp[256 + col + i]       = l[i];
        rowp[256 + col + 128 + i] = l[4 + i];
    }
}

__global__ void ln1_kernel(const float* __restrict__ in,
                           const float* __restrict__ gamma,
                           const float* __restrict__ beta) {
    int gwarp = (blockIdx.x * blockDim.x + threadIdx.x) >> 5;
    int lane  = threadIdx.x & 31;
    const float* row = in + (size_t)gwarp * DD;
    float4 v0 = ((const float4*)row)[lane];
    float4 v1 = ((const float4*)row)[lane + 32];
    float s  = v0.x + v0.y + v0.z + v0.w + v1.x + v1.y + v1.z + v1.w;
    float sq = v0.x*v0.x + v0.y*v0.y + v0.z*v0.z + v0.w*v0.w
             + v1.x*v1.x + v1.y*v1.y + v1.z*v1.z + v1.w*v1.w;
#pragma unroll
    for (int o = 16; o > 0; o >>= 1) {
        s  += __shfl_xor_sync(0xffffffffu, s,  o);
        sq += __shfl_xor_sync(0xffffffffu, sq, o);
    }
    float mean = s * (1.0f / 256.0f);
    float var  = sq * (1.0f / 256.0f) - mean * mean;
    float rstd = rsqrtf(var + 1e-5f);

    int b = gwarp >> 12, pos = gwarp & 4095;
    int h = pos >> 6, w = pos & 63;
    int m = ((h & 7) << 3) | (w & 7);
    int n = ((h >> 3) << 3) | (w >> 3);
    size_t orow = ((size_t)b << 12) | (unsigned)((m << 6) | n);

    float4 g0 = ((const float4*)gamma)[lane];
    float4 g1 = ((const float4*)gamma)[lane + 32];
    float4 b0 = ((const float4*)beta)[lane];
    float4 b1 = ((const float4*)beta)[lane + 32];
    float4 o0, o1;
    o0.x = (v0.x - mean) * rstd * g0.x + b0.x;
    o0.y = (v0.y - mean) * rstd * g0.y + b0.y;
    o0.z = (v0.z - mean) * rstd * g0.z + b0.z;
    o0.w = (v0.w - mean) * rstd * g0.w + b0.w;
    o1.x = (v1.x - mean) * rstd * g1.x + b1.x;
    o1.y = (v1.y - mean) * rstd * g1.y + b1.y;
    o1.z = (v1.z - mean) * rstd * g1.z + b1.z;
    o1.w = (v1.w - mean) * rstd * g1.w + b1.w;
    store_split8(g_asp + orow * 512, lane * 4, o0, o1);
}

// ================= QKV GEMM: 128x128 tile, term-major 3-split =================
#define GP 40
#define MATB (128 * GP * 2)            // 10240 B
#define STAGEB (4 * MATB)              // 40960 B
#define GSMEM (2 * STAGEB)             // 81920 B

__global__ __launch_bounds__(256, 2)
void qkv_gemm_kernel(const bf16* __restrict__ Asp,
                     const bf16* __restrict__ Bsp,
                     bf16* __restrict__ Csp) {
    extern __shared__ bf16 smem[];
    uint32_t sb = (uint32_t)__cvta_generic_to_shared(smem);

    int tid = threadIdx.x;
    int lane = tid & 31, warp = tid >> 5;
    int wm = warp & 1, wn = warp >> 1;
    int g = lane >> 2, tig = lane & 3;
    int lrow8 = lane & 7, l8 = (lane >> 3) & 1, l16 = (lane >> 4) & 1;
    int rowBase = blockIdx.y * 128;
    int colBase = blockIdx.x * 128;

    uint32_t aoff = (uint32_t)(((wm * 64 + lrow8 + 8 * l8) * GP + 8 * l16) * 2);
    uint32_t boff = (uint32_t)(((wn * 32 + lrow8) * GP + 8 * l8) * 2);

    float acc[4][4][4] = {};

    auto load_chunk = [&](int c, int st) {
        const bf16* Ag = Asp + (size_t)rowBase * 512 + c * 32;
        const bf16* Bg = Bsp + (size_t)colBase * 512 + c * 32;
        uint32_t base = sb + (uint32_t)st * STAGEB;
#pragma unroll
        for (int i = 0; i < 2; i++) {
            int f = tid + i * 256;
            int r = f >> 2, q = f & 3;
            uint32_t so = (uint32_t)(r * GP + q * 8) * 2;
            const bf16* ga = Ag + (size_t)r * 512 + q * 8;
            const bf16* gb = Bg + (size_t)r * 512 + q * 8;
            cpasync16(base + so,            ga);
            cpasync16(base + MATB + so,     ga + 256);
            cpasync16(base + 2 * MATB + so, gb);
            cpasync16(base + 3 * MATB + so, gb + 256);
        }
        asm volatile("cp.async.commit_group;\n");
    };

    load_chunk(0, 0);
    const int NCH = 8;
    for (int c = 0; c < NCH; c++) {
        if (c + 1 < NCH) {
            load_chunk(c + 1, (c + 1) & 1);
            asm volatile("cp.async.wait_group 1;\n");
        } else {
            asm volatile("cp.async.wait_group 0;\n");
        }
        __syncthreads();

        uint32_t stb = sb + (uint32_t)(c & 1) * STAGEB;
#pragma unroll
        for (int ks = 0; ks < 2; ks++) {
            uint32_t kb2 = ks * 32;
            uint32_t ahi[4][4], alo[4][4];
#pragma unroll
            for (int mi = 0; mi < 4; mi++) {
                uint32_t a = stb + aoff + mi * (16 * GP * 2) + kb2;
                ldsm_x4(ahi[mi], a);
                ldsm_x4(alo[mi], a + MATB);
            }
#pragma unroll
            for (int ni = 0; ni < 4; ni++) {
                uint32_t ba = stb + 2 * MATB + boff + ni * (8 * GP * 2) + kb2;
                uint32_t bh[2], bl[2];
                ldsm_x2(bh, ba);
                ldsm_x2(bl, ba + MATB);
                // term-major: dependency distance 4 (independent mi chains)
#pragma unroll
                for (int mi = 0; mi < 4; mi++) mma16816(acc[mi][ni], ahi[mi], bh);
#pragma unroll
                for (int mi = 0; mi < 4; mi++) mma16816(acc[mi][ni], alo[mi], bh);
#pragma unroll
                for (int mi = 0; mi < 4; mi++) mma16816(acc[mi][ni], ahi[mi], bl);
            }
        }
        __syncthreads();
    }

#pragma unroll
    for (int mi = 0; mi < 4; mi++) {
        int r0 = rowBase + wm * 64 + mi * 16 + g;
        int r1 = r0 + 8;
#pragma unroll
        for (int ni = 0; ni < 4; ni++) {
            int col = colBase + wn * 32 + ni * 8 + tig * 2;
            bf16 h0, l0, h1, l1;
            bsplit(acc[mi][ni][0], h0, l0); bsplit(acc[mi][ni][1], h1, l1);
            *(__nv_bfloat162*)(Csp + (size_t)r0 * 5120 + col)        = __nv_bfloat162(h0, h1);
            *(__nv_bfloat162*)(Csp + (size_t)r0 * 5120 + 2560 + col) = __nv_bfloat162(l0, l1);
            bsplit(acc[mi][ni][2], h0, l0); bsplit(acc[mi][ni][3], h1, l1);
            *(__nv_bfloat162*)(Csp + (size_t)r1 * 5120 + col)        = __nv_bfloat162(h0, h1);
            *(__nv_bfloat162*)(Csp + (size_t)r1 * 5120 + 2560 + col) = __nv_bfloat162(l0, l1);
        }
    }
}

// ================= fused MLP, term-major inner loops =================
#define WGP 40
#define A_PL (128 * WGP * 2)
#define B_PL (256 * WGP * 2)
#define WSTAGE (2 * A_PL + 2 * B_PL)
#define HP 264
#define HPLANE (128 * HP * 2)
#define W2S0 (2 * HPLANE)
#define W2STG (2 * B_PL)
#define MLPSMEM (W2S0 + 2 * W2STG)

__global__ __launch_bounds__(256, 1)
void mlp_fused_kernel(const bf16* __restrict__ ln2sp,
                      const bf16* __restrict__ w1sp,
                      const bf16* __restrict__ w2sp,
                      const float* __restrict__ b1,
                      const float* __restrict__ b2,
                      const float* __restrict__ x2,
                      float* __restrict__ out) {
    extern __shared__ bf16 smem[];
    uint32_t sb = (uint32_t)__cvta_generic_to_shared(smem);

    int tid = threadIdx.x;
    int lane = tid & 31, warp = tid >> 5;
    int wm = warp & 1, wn = warp >> 1;
    int g = lane >> 2, tig = lane & 3;
    int lrow8 = lane & 7, l8 = (lane >> 3) & 1, l16 = (lane >> 4) & 1;
    int rowBase = blockIdx.x * 128;

    uint32_t aoff = (uint32_t)(((wm * 64 + lrow8 + 8 * l8) * WGP + 8 * l16) * 2);
    uint32_t boff = (uint32_t)(((wn * 64 + lrow8) * WGP + 8 * l8) * 2);
    uint32_t hoff = (uint32_t)(((wm * 64 + lrow8 + 8 * l8) * HP + 8 * l16) * 2);

    float acc[4][8][4] = {};

    auto load1 = [&](int c, int st) {
        const bf16* Ag = ln2sp + (size_t)rowBase * 512 + c * 32;
        const bf16* Bg = w1sp + c * 32;
        uint32_t base = sb + (uint32_t)st * WSTAGE;
#pragma unroll
        for (int i = 0; i < 2; i++) {
            int f = tid + i * 256;
            int r = f >> 2, q = f & 3;
            uint32_t so = (uint32_t)(r * WGP + q * 8) * 2;
            const bf16* ga = Ag + (size_t)r * 512 + q * 8;
            cpasync16(base + so,        ga);
            cpasync16(base + A_PL + so, ga + 256);
        }
#pragma unroll
        for (int i = 0; i < 4; i++) {
            int f = tid + i * 256;
            int r = f >> 2, q = f & 3;
            uint32_t so = (uint32_t)(r * WGP + q * 8) * 2;
            const bf16* gb = Bg + (size_t)r * 512 + q * 8;
            cpasync16(base + 2 * A_PL + so,        gb);
            cpasync16(base + 2 * A_PL + B_PL + so, gb + 256);
        }
        asm volatile("cp.async.commit_group;\n");
    };
    auto load2 = [&](int c, int st) {
        const bf16* Bg = w2sp + c * 32;
        uint32_t base = sb + W2S0 + (uint32_t)st * W2STG;
#pragma unroll
        for (int i = 0; i < 4; i++) {
            int f = tid + i * 256;
            int r = f >> 2, q = f & 3;
            uint32_t so = (uint32_t)(r * WGP + q * 8) * 2;
            const bf16* gb = Bg + (size_t)r * 512 + q * 8;
            cpasync16(base + so,        gb);
            cpasync16(base + B_PL + so, gb + 256);
        }
        asm volatile("cp.async.commit_group;\n");
    };

    // phase 1
    load1(0, 0);
    for (int c = 0; c < 8; c++) {
        if (c + 1 < 8) {
            load1(c + 1, (c + 1) & 1);
            asm volatile("cp.async.wait_group 1;\n");
        } else {
            asm volatile("cp.async.wait_group 0;\n");
        }
        __syncthreads();
        uint32_t stb = sb + (uint32_t)(c & 1) * WSTAGE;
#pragma unroll
        for (int ks = 0; ks < 2; ks++) {
            uint32_t kb2 = ks * 32;
            uint32_t ahi[4][4], alo[4][4];
#pragma unroll
            for (int mi = 0; mi < 4; mi++) {
                uint32_t a = stb + aoff + mi * (16 * WGP * 2) + kb2;
                ldsm_x4(ahi[mi], a);
                ldsm_x4(alo[mi], a + A_PL);
            }
#pragma unroll
            for (int ni = 0; ni < 8; ni++) {
                uint32_t ba = stb + 2 * A_PL + boff + ni * (8 * WGP * 2) + kb2;
                uint32_t bh[2], bl[2];
                ldsm_x2(bh, ba);
                ldsm_x2(bl, ba + B_PL);
#pragma unroll
                for (int mi = 0; mi < 4; mi++) mma16816(acc[mi][ni], ahi[mi], bh);
#pragma unroll
                for (int mi = 0; mi < 4; mi++) mma16816(acc[mi][ni], alo[mi], bh);
#pragma unroll
                for (int mi = 0; mi < 4; mi++) mma16816(acc[mi][ni], ahi[mi], bl);
            }
        }
        __syncthreads();
    }

    load2(0, 0);

    bf16* hhi = smem;
    bf16* hlo = smem + 128 * HP;
#pragma unroll
    for (int mi = 0; mi < 4; mi++) {
        int r0 = wm * 64 + mi * 16 + g;
        int r1 = r0 + 8;
#pragma unroll
        for (int ni = 0; ni < 8; ni++) {
            int col = wn * 64 + ni * 8 + tig * 2;
            float2 bv = *(const float2*)(b1 + col);
            float v0 = fmaxf(acc[mi][ni][0] + bv.x, 0.f);
            float v1 = fmaxf(acc[mi][ni][1] + bv.y, 0.f);
            float v2 = fmaxf(acc[mi][ni][2] + bv.x, 0.f);
            float v3 = fmaxf(acc[mi][ni][3] + bv.y, 0.f);
            bf16 h0, l0, h1, l1;
            bsplit(v0, h0, l0); bsplit(v1, h1, l1);
            *(__nv_bfloat162*)(hhi + r0 * HP + col) = __nv_bfloat162(h0, h1);
            *(__nv_bfloat162*)(hlo + r0 * HP + col) = __nv_bfloat162(l0, l1);
            bsplit(v2, h0, l0); bsplit(v3, h1, l1);
            *(__nv_bfloat162*)(hhi + r1 * HP + col) = __nv_bfloat162(h0, h1);
            *(__nv_bfloat162*)(hlo + r1 * HP + col) = __nv_bfloat162(l0, l1);
            acc[mi][ni][0] = 0.f; acc[mi][ni][1] = 0.f;
            acc[mi][ni][2] = 0.f; acc[mi][ni][3] = 0.f;
        }
    }
    __syncthreads();

    // phase 2
    for (int c = 0; c < 8; c++) {
        if (c + 1 < 8) {
            load2(c + 1, (c + 1) & 1);
            asm volatile("cp.async.wait_group 1;\n");
        } else {
            asm volatile("cp.async.wait_group 0;\n");
        }
        __syncthreads();
        uint32_t w2b = sb + W2S0 + (uint32_t)(c & 1) * W2STG;
#pragma unroll
        for (int ks = 0; ks < 2; ks++) {
            uint32_t kbyte = (uint32_t)((c * 32 + ks * 16) * 2);
            uint32_t kb2 = ks * 32;
            uint32_t ahi[4][4], alo[4][4];
#pragma unroll
            for (int mi = 0; mi < 4; mi++) {
                uint32_t a = sb + hoff + mi * (16 * HP * 2) + kbyte;
                ldsm_x4(ahi[mi], a);
                ldsm_x4(alo[mi], a + HPLANE);
            }
#pragma unroll
            for (int ni = 0; ni < 8; ni++) {
                uint32_t ba = w2b + boff + ni * (8 * WGP * 2) + kb2;
                uint32_t bh[2], bl[2];
                ldsm_x2(bh, ba);
                ldsm_x2(bl, ba + B_PL);
#pragma unroll
                for (int mi = 0; mi < 4; mi++) mma16816(acc[mi][ni], ahi[mi], bh);
#pragma unroll
                for (int mi = 0; mi < 4; mi++) mma16816(acc[mi][ni], alo[mi], bh);
#pragma unroll
                for (int mi = 0; mi < 4; mi++) mma16816(acc[mi][ni], ahi[mi], bl);
            }
        }
        __syncthreads();
    }

#pragma unroll
    for (int mi = 0; mi < 4; mi++) {
        int r0 = rowBase + wm * 64 + mi * 16 + g;
        int r1 = r0 + 8;
#pragma unroll
        for (int ni = 0; ni < 8; ni++) {
            int col = wn * 64 + ni * 8 + tig * 2;
            float2 bv = *(const float2*)(b2 + col);
            float2 e0 = *(const float2*)(x2 + (size_t)r0 * DD + col);
            float2 e1 = *(const float2*)(x2 + (size_t)r1 * DD + col);
            float2 v0 = make_float2(acc[mi][ni][0] + bv.x + e0.x,
                                    acc[mi][ni][1] + bv.y + e0.y);
            float2 v1 = make_float2(acc[mi][ni][2] + bv.x + e1.x,
                                    acc[mi][ni][3] + bv.y + e1.y);
            *(float2*)(out + (size_t)r0 * DD + col) = v0;
            *(float2*)(out + (size_t)r1 * DD + col) = v1;
        }
    }
}

// ================= tensor-core attention + fused head-mix =================
#define TP 264
#define PP 72
#define TILE_E (64 * TP)
#define TEB (TILE_E * 2)
#define PPB (64 * PP * 2)
#define ATTN_SMEM_B (6 * TEB + 2 * PPB + 1024)

__global__ __launch_bounds__(256)
void attn_mma_kernel() {
    extern __shared__ bf16 asm_[];
    bf16* Ph = asm_ + 6 * TILE_E;
    bf16* Pl = Ph + 64 * PP;
    float* stmax = (float*)(Pl + 64 * PP);
    float* stsum = stmax + 128;
    uint32_t sbase = (uint32_t)__cvta_generic_to_shared(asm_);

    int tid = threadIdx.x;
    int lane = tid & 31, warp = tid >> 5;
    int g = lane >> 2, tig = lane & 3;
    int lrow8 = lane & 7, l8 = (lane >> 3) & 1, l16 = (lane >> 4) & 1;

    int u = blockIdx.x;
    bool gridmode = (u < 512);
    int b, fix;
    if (gridmode) { b = u >> 6; fix = u & 63; }
    else          { int u2 = u - 512; b = u2 >> 6; fix = u2 & 63; }
    size_t base; int stride;
    if (gridmode) { base = (size_t)b * 4096 + fix; stride = 64; }
    else          { base = (size_t)b * 4096 + (size_t)fix * 64; stride = 1; }
    int head0 = gridmode ? 0 : 4;

    auto load_piece = [&](int planeIdx, int colOff) {
        uint32_t sh = sbase + (uint32_t)planeIdx * TEB;
#pragma unroll
        for (int i = 0; i < 8; i++) {
            int f = i * 256 + tid;
            int r = f >> 5, q = f & 31;
            size_t token = base + (size_t)r * stride;
            const bf16* ga = g_qkvsp + token * 5120 + colOff + q * 8;
            uint32_t so = (uint32_t)(r * TP + q * 8) * 2;
            cpasync16(sh + so, ga);
            cpasync16(sh + TEB + so, ga + 2560);
        }
    };

    load_piece(2, 2048);
    load_piece(4, 2304);
    load_piece(0, head0 * 256);
    asm volatile("cp.async.commit_group;\n");
    asm volatile("cp.async.wait_group 0;\n");
    __syncthreads();

    int warpm = warp >> 1, warpn = warp & 1;
    int row0 = warpm * 16 + g, row1 = row0 + 8;

    uint32_t qoff = (uint32_t)(((warpm * 16 + lrow8 + 8 * l8) * TP + 8 * l16) * 2);
    uint32_t koff = (uint32_t)(((warpn * 32 + lrow8) * TP + 8 * l8) * 2);
    uint32_t poff = (uint32_t)(((warpm * 16 + lrow8 + 8 * l8) * PP + 8 * l16) * 2);
    uint32_t voff = (uint32_t)(((lrow8 + 8 * l8) * TP) * 2);
    uint32_t PB = sbase + 6 * TEB;
    uint32_t KB = sbase + 2 * TEB;
    uint32_t VB = sbase + 4 * TEB;

    float zacc[16][4] = {};

    for (int hl = 0; hl < 4; hl++) {
        int head = head0 + hl;

        // ---------- S = Q K^T (term-major passes) ----------
        float c[4][4] = {};
#pragma unroll 4
        for (int ks = 0; ks < 16; ks++) {
            uint32_t kb2 = ks * 32;
            uint32_t ahi[4], alo[4];
            ldsm_x4(ahi, sbase + qoff + kb2);
            ldsm_x4(alo, sbase + TEB + qoff + kb2);
            uint32_t bh[4][2], bl[4][2];
#pragma unroll
            for (int ni = 0; ni < 4; ni++) {
                uint32_t ba = KB + koff + ni * (8 * TP * 2) + kb2;
                ldsm_x2(bh[ni], ba);
                ldsm_x2(bl[ni], ba + TEB);
            }
#pragma unroll
            for (int ni = 0; ni < 4; ni++) mma16816(c[ni], ahi, bh[ni]);
#pragma unroll
            for (int ni = 0; ni < 4; ni++) mma16816(c[ni], alo, bh[ni]);
#pragma unroll
            for (int ni = 0; ni < 4; ni++) mma16816(c[ni], ahi, bl[ni]);
        }

        // ---------- softmax ----------
        float m0 = -1e30f, m1 = -1e30f;
#pragma unroll
        for (int ni = 0; ni < 4; ni++) {
            m0 = fmaxf(m0, fmaxf(c[ni][0], c[ni][1]));
            m1 = fmaxf(m1, fmaxf(c[ni][2], c[ni][3]));
        }
        m0 = fmaxf(m0, __shfl_xor_sync(0xffffffffu, m0, 1));
        m0 = fmaxf(m0, __shfl_xor_sync(0xffffffffu, m0, 2));
        m1 = fmaxf(m1, __shfl_xor_sync(0xffffffffu, m1, 1));
        m1 = fmaxf(m1, __shfl_xor_sync(0xffffffffu, m1, 2));
        if (tig == 0) {
            stmax[row0 * 2 + warpn] = m0;
            stmax[row1 * 2 + warpn] = m1;
        }
        __syncthreads();
        m0 = fmaxf(stmax[row0 * 2], stmax[row0 * 2 + 1]);
        m1 = fmaxf(stmax[row1 * 2], stmax[row1 * 2 + 1]);
        float s0 = 0.f, s1 = 0.f;
#pragma unroll
        for (int ni = 0; ni < 4; ni++) {
            c[ni][0] = __expf(c[ni][0] - m0);
            c[ni][1] = __expf(c[ni][1] - m0);
            c[ni][2] = __expf(c[ni][2] - m1);
            c[ni][3] = __expf(c[ni][3] - m1);
            s0 += c[ni][0] + c[ni][1];
            s1 += c[ni][2] + c[ni][3];
        }
        s0 += __shfl_xor_sync(0xffffffffu, s0, 1);
        s0 += __shfl_xor_sync(0xffffffffu, s0, 2);
        s1 += __shfl_xor_sync(0xffffffffu, s1, 1);
        s1 += __shfl_xor_sync(0xffffffffu, s1, 2);
        if (tig == 0) {
            stsum[row0 * 2 + warpn] = s0;
            stsum[row1 * 2 + warpn] = s1;
        }
        __syncthreads();
        float inv0 = 1.0f / (stsum[row0 * 2] + stsum[row0 * 2 + 1]);
        float inv1 = 1.0f / (stsum[row1 * 2] + stsum[row1 * 2 + 1]);
#pragma unroll
        for (int ni = 0; ni < 4; ni++) {
            int cn = warpn * 32 + ni * 8 + 2 * tig;
            bf16 h0, l0, h1, l1;
            bsplit(c[ni][0] * inv0, h0, l0); bsplit(c[ni][1] * inv0, h1, l1);
            *(__nv_bfloat162*)(Ph + row0 * PP + cn) = __nv_bfloat162(h0, h1);
            *(__nv_bfloat162*)(Pl + row0 * PP + cn) = __nv_bfloat162(l0, l1);
            bsplit(c[ni][2] * inv1, h0, l0); bsplit(c[ni][3] * inv1, h1, l1);
            *(__nv_bfloat162*)(Ph + row1 * PP + cn) = __nv_bfloat162(h0, h1);
            *(__nv_bfloat162*)(Pl + row1 * PP + cn) = __nv_bfloat162(l0, l1);
        }
        __syncthreads();

        if (hl < 3) {
            load_piece(0, (head + 1) * 256);
            asm volatile("cp.async.commit_group;\n");
        }

        // ---------- O = P V, so-scaled ----------
        const float* sop = g_so + head * 256;
#pragma unroll
        for (int ks = 0; ks < 4; ks++) {
            uint32_t kb2 = ks * 32;
            uint32_t ph[4], pl[4];
            ldsm_x4(ph, PB + poff + kb2);
            ldsm_x4(pl, PB + PPB + poff + kb2);
            uint32_t vrow = VB + voff + (uint32_t)ks * (16 * TP * 2);
#pragma unroll
            for (int ni = 0; ni < 16; ni++) {
                uint32_t va = vrow + (uint32_t)((warpn * 128 + ni * 8) * 2);
                uint32_t bh[2], bl[2];
                ldsm_x2t(bh, va);
                ldsm_x2t(bl, va + TEB);
                float ot[4] = {};
                mma16816(ot, ph, bh);
                mma16816(ot, pl, bh);
                mma16816(ot, ph, bl);
                float2 sv = *(const float2*)(sop + warpn * 128 + ni * 8 + 2 * tig);
                zacc[ni][0] += ot[0] * sv.x; zacc[ni][1] += ot[1] * sv.y;
                zacc[ni][2] += ot[2] * sv.x; zacc[ni][3] += ot[3] * sv.y;
            }
        }

        if (hl < 3) asm volatile("cp.async.wait_group 0;\n");
        __syncthreads();
    }

    float* gz = gridmode ? g_z1 : g_z2;
    size_t tok0 = base + (size_t)row0 * stride;
    size_t tok1 = base + (size_t)row1 * stride;
#pragma unroll
    for (int ni = 0; ni < 16; ni++) {
        int col = warpn * 128 + ni * 8 + 2 * tig;
        *(float2*)(gz + tok0 * DD + col) = make_float2(zacc[ni][0], zacc[ni][1]);
        *(float2*)(gz + tok1 * DD + col) = make_float2(zacc[ni][2], zacc[ni][3]);
    }
}

// ---------- z1+z2 + unpermute + residual + LN2 -> split bf16 ----------
__global__ void zred_ln2_kernel(const float* __restrict__ x,
                                const float* __restrict__ gamma,
                                const float* __restrict__ beta,
                                float* __restrict__ x2) {
    int gw   = (blockIdx.x * blockDim.x + threadIdx.x) >> 5;
    int lane = threadIdx.x & 31;

    int b = gw >> 12, m = (gw >> 6) & 63, n = gw & 63;
    int hh = ((n >> 3) << 3) | (m >> 3);
    int ww = ((n & 7) << 3) | (m & 7);
    size_t orow = ((size_t)b << 12) | (unsigned)((hh << 6) | ww);

    const float* z1 = g_z1 + (size_t)gw * DD;
    const float* z2 = g_z2 + (size_t)gw * DD;
    float4 a0 = ((const float4*)z1)[lane];
    float4 a1 = ((const float4*)z1)[lane + 32];
    float4 b0v = ((const float4*)z2)[lane];
    float4 b1v = ((const float4*)z2)[lane + 32];
    const float* xr = x + orow * DD;
    float4 x0 = ((const float4*)xr)[lane];
    float4 x1 = ((const float4*)xr)[lane + 32];
    float4 v0 = make_float4(x0.x + a0.x + b0v.x, x0.y + a0.y + b0v.y,
                            x0.z + a0.z + b0v.z, x0.w + a0.w + b0v.w);
    float4 v1 = make_float4(x1.x + a1.x + b1v.x, x1.y + a1.y + b1v.y,
                            x1.z + a1.z + b1v.z, x1.w + a1.w + b1v.w);

    ((float4*)(x2 + orow * DD))[lane]      = v0;
    ((float4*)(x2 + orow * DD))[lane + 32] = v1;

    float s  = v0.x + v0.y + v0.z + v0.w + v1.x + v1.y + v1.z + v1.w;
    float sq = v0.x*v0.x + v0.y*v0.y + v0.z*v0.z + v0.w*v0.w
             + v1.x*v1.x + v1.y*v1.y + v1.z*v1.z + v1.w*v1.w;
#pragma unroll
    for (int o = 16; o > 0; o >>= 1) {
        s  += __shfl_xor_sync(0xffffffffu, s,  o);
        sq += __shfl_xor_sync(0xffffffffu, sq, o);
    }
    float mean = s * (1.0f / 256.0f);
    float var  = sq * (1.0f / 256.0f) - mean * mean;
    float rstd = rsqrtf(var + 1e-5f);

    float4 g0 = ((const float4*)gamma)[lane];
    float4 g1 = ((const float4*)gamma)[lane + 32];
    float4 bb0 = ((const float4*)beta)[lane];
    float4 bb1 = ((const float4*)beta)[lane + 32];
    float4 o0, o1;
    o0.x = (v0.x - mean) * rstd * g0.x + bb0.x;
    o0.y = (v0.y - mean) * rstd * g0.y + bb0.y;
    o0.z = (v0.z - mean) * rstd * g0.z + bb0.z;
    o0.w = (v0.w - mean) * rstd * g0.w + bb0.w;
    o1.x = (v1.x - mean) * rstd * g1.x + bb1.x;
    o1.y = (v1.y - mean) * rstd * g1.y + bb1.y;
    o1.z = (v1.z - mean) * rstd * g1.z + bb1.z;
    o1.w = (v1.w - mean) * rstd * g1.w + bb1.w;
    store_split8(g_ln2sp + orow * 512, lane * 4, o0, o1);
}

// ---------------- launch ----------------
extern "C" void kernel_launch(void* const* d_in, const int* in_sizes, int n_in,
                              void* d_out, int out_size) {
    const float* x    = (const float*)d_in[0];
    const float* ln1w = (const float*)d_in[1];
    const float* ln1b = (const float*)d_in[2];
    const float* qw   = (const float*)d_in[3];
    const float* kw   = (const float*)d_in[4];
    const float* vw   = (const float*)d_in[5];
    const float* ow   = (const float*)d_in[6];
    const float* ln2w = (const float*)d_in[7];
    const float* ln2b = (const float*)d_in[8];
    const float* w1   = (const float*)d_in[9];
    const float* b1   = (const float*)d_in[10];
    const float* w2   = (const float*)d_in[11];
    const float* b2   = (const float*)d_in[12];
    float* out = (float*)d_out;

    bf16 *p_asp, *p_wsp, *p_w1sp, *p_w2sp, *p_ln2sp, *p_qkvsp;
    float *p_x2;
    cudaGetSymbolAddress((void**)&p_asp,   g_asp);
    cudaGetSymbolAddress((void**)&p_wsp,   g_wsp);
    cudaGetSymbolAddress((void**)&p_w1sp,  g_w1sp);
    cudaGetSymbolAddress((void**)&p_w2sp,  g_w2sp);
    cudaGetSymbolAddress((void**)&p_ln2sp, g_ln2sp);
    cudaGetSymbolAddress((void**)&p_qkvsp, g_qkvsp);
    cudaGetSymbolAddress((void**)&p_x2,    g_x2);

    cudaFuncSetAttribute(attn_mma_kernel, cudaFuncAttributeMaxDynamicSharedMemorySize,
                         ATTN_SMEM_B);
    cudaFuncSetAttribute(qkv_gemm_kernel, cudaFuncAttributeMaxDynamicSharedMemorySize, GSMEM);
    cudaFuncSetAttribute(mlp_fused_kernel, cudaFuncAttributeMaxDynamicSharedMemorySize, MLPSMEM);

    // launch #4 = QKV GEMM (profiled by ncu -s 5 -c 1)
    prep_wqkv_kernel<<<QKVC, 256>>>(qw, kw, vw);                       // 1
    ln1_kernel<<<NTOK / 8, 256>>>(x, ln1w, ln1b);                      // 2
    prep_wt_kernel<<<256, 256>>>(w1, p_w1sp);                          // 3
    qkv_gemm_kernel<<<dim3(QKVC / 128, NTOK / 128), 256, GSMEM>>>(     // 4
        p_asp, p_wsp, p_qkvsp);
    prep_so_kernel<<<256, 256>>>(ow);                                  // 5
    prep_wt_kernel<<<256, 256>>>(w2, p_w2sp);                          // 6
    attn_mma_kernel<<<1024, 256, ATTN_SMEM_B>>>();                     // 7
    zred_ln2_kernel<<<NTOK / 8, 256>>>(x, ln2w, ln2b, p_x2);           // 8
    mlp_fused_kernel<<<NTOK / 128, 256, MLPSMEM>>>(                    // 9
        p_ln2sp, p_w1sp, p_w2sp, b1, b2, p_x2, out);
}